// round 10
// baseline (speedup 1.0000x reference)
#include <cuda_runtime.h>
#include <cuda_fp16.h>
#include <math.h>
#include <stdint.h>

// Problem constants
#define BQ 8
#define TQ 4096
#define NTOK (BQ*TQ)          // 32768 tokens
#define EMB 512
#define HEADS 8
#define ES 64
#define MF 32                 // random features
#define HID (4*EMB)           // 2048
#define LN_EPS 1e-5f

__device__ __forceinline__ uint32_t smem_to_u32(const void* smem_ptr) {
    uint32_t addr;
    asm("{ .reg .u64 tmp; cvta.to.shared.u64 tmp, %1; cvt.u32.u64 %0, tmp; }"
        : "=r"(addr) : "l"(smem_ptr));
    return addr;
}

__device__ __forceinline__ void cp_async16(uint32_t saddr, const void* gaddr) {
    asm volatile("cp.async.cg.shared.global [%0], [%1], 16;" :: "r"(saddr), "l"(gaddr));
}
#define CP_COMMIT() asm volatile("cp.async.commit_group;" ::: "memory")
#define CP_WAIT0()  asm volatile("cp.async.wait_group 0;" ::: "memory")
#define CP_WAIT1()  asm volatile("cp.async.wait_group 1;" ::: "memory")

__device__ __forceinline__ void ldsm_x4(uint32_t& r0, uint32_t& r1, uint32_t& r2, uint32_t& r3,
                                        uint32_t addr) {
    asm volatile("ldmatrix.sync.aligned.m8n8.x4.shared.b16 {%0,%1,%2,%3}, [%4];"
        : "=r"(r0), "=r"(r1), "=r"(r2), "=r"(r3) : "r"(addr));
}

__device__ __forceinline__ void mma_f16(float* c, const uint32_t* a, const uint32_t* b) {
    asm volatile(
        "mma.sync.aligned.m16n8k16.row.col.f32.f16.f16.f32 "
        "{%0,%1,%2,%3}, {%4,%5,%6,%7}, {%8,%9}, {%0,%1,%2,%3};"
        : "+f"(c[0]), "+f"(c[1]), "+f"(c[2]), "+f"(c[3])
        : "r"(a[0]), "r"(a[1]), "r"(a[2]), "r"(a[3]), "r"(b[0]), "r"(b[1]));
}

// ---- packed fp32x2 FMA (sm_100+ baseline PTX; doubles fp32 FMA rate) ----
__device__ __forceinline__ void ffma2(uint64_t& d, uint64_t a, uint64_t b) {
    asm("fma.rn.f32x2 %0, %1, %2, %0;" : "+l"(d) : "l"(a), "l"(b));
}
__device__ __forceinline__ float2 unpk2(uint64_t v) {
    float2 r;
    asm("mov.b64 {%0, %1}, %2;" : "=f"(r.x), "=f"(r.y) : "l"(v));
    return r;
}

// -------- scratch (device globals; no runtime allocation) --------
__device__ float g_v[(size_t)NTOK*HEADS*ES];
__device__ float g_qp[(size_t)NTOK*HEADS*MF];
__device__ float g_kp[(size_t)NTOK*HEADS*MF];
__device__ float g_kptv_part[16*64*ES*MF];
__device__ float g_ksum_part[16*64*MF];
__device__ float g_kptv[64*ES*MF];
__device__ float g_ksum[64*MF];
__device__ float g_x1[(size_t)NTOK*EMB];
__device__ __align__(16) __half g_h2h[(size_t)NTOK*EMB];
__device__ __align__(16) __half g_yh[(size_t)NTOK*EMB];
__device__ __align__(16) __half g_hidh[(size_t)NTOK*HID];
__device__ __align__(16) __half g_pwh[EMB*EMB];
__device__ __align__(16) __half g_w1h[HID*EMB];
__device__ __align__(16) __half g_w2h[EMB*HID];

// ---------------- fused weight fp16 conversion (all 3 weights) ----------------
#define CVT_N4 (65536 + 262144 + 262144)
__global__ void cvt_all_kernel(const float* __restrict__ pw, const float* __restrict__ w1,
                               const float* __restrict__ w2, __half* __restrict__ pwh,
                               __half* __restrict__ w1h, __half* __restrict__ w2h) {
    int i = blockIdx.x * 256 + threadIdx.x;
    if (i >= CVT_N4) return;
    const float* src;
    __half* dst;
    int j;
    if (i < 65536)       { src = pw; dst = pwh; j = i; }
    else if (i < 327680) { src = w1; dst = w1h; j = i - 65536; }
    else                 { src = w2; dst = w2h; j = i - 327680; }
    float4 v = ((const float4*)src)[j];
    __half h[4];
    h[0] = __float2half(v.x); h[1] = __float2half(v.y);
    h[2] = __float2half(v.z); h[3] = __float2half(v.w);
    *(uint2*)(dst + (size_t)j*4) = *(uint2*)h;
}

// ---------------- LayerNorm (LN2): warp per token, fp16 out ----------------
__global__ void ln2_kernel(const float* __restrict__ x, const float* __restrict__ g,
                           const float* __restrict__ b, __half* __restrict__ ohi) {
    int tok  = blockIdx.x * 8 + (threadIdx.x >> 5);
    int lane = threadIdx.x & 31;
    const float4* xr = (const float4*)(x + (size_t)tok * EMB);
    float4 v[4];
    float s = 0.f, sq = 0.f;
    #pragma unroll
    for (int i = 0; i < 4; i++) {
        v[i] = xr[lane + 32*i];
        s  += v[i].x + v[i].y + v[i].z + v[i].w;
        sq += v[i].x*v[i].x + v[i].y*v[i].y + v[i].z*v[i].z + v[i].w*v[i].w;
    }
    #pragma unroll
    for (int o = 16; o; o >>= 1) {
        s  += __shfl_xor_sync(0xffffffffu, s,  o);
        sq += __shfl_xor_sync(0xffffffffu, sq, o);
    }
    float mean = s * (1.0f/EMB);
    float var  = sq * (1.0f/EMB) - mean*mean;
    float rstd = rsqrtf(var + LN_EPS);
    const float4* g4 = (const float4*)g;
    const float4* b4 = (const float4*)b;
    #pragma unroll
    for (int i = 0; i < 4; i++) {
        float4 gg = g4[lane + 32*i], bb = b4[lane + 32*i];
        size_t idx = (size_t)tok * EMB + (size_t)(lane + 32*i) * 4;
        __half h[4];
        h[0] = __float2half((v[i].x - mean) * rstd * gg.x + bb.x);
        h[1] = __float2half((v[i].y - mean) * rstd * gg.y + bb.y);
        h[2] = __float2half((v[i].z - mean) * rstd * gg.z + bb.z);
        h[3] = __float2half((v[i].w - mean) * rstd * gg.w + bb.w);
        *(uint2*)(ohi + idx) = *(uint2*)h;
    }
}

// ---------------- fused LN1 + kqv + prm_exp, f32x2-packed (8 tok/block, 4 heads/pass) ----------------
#define SKQ_STRIDE 200
#define WKF_STRIDE 66
#define WRM_STRIDE 66
// sh_h 4096 | wk_f 192*66=12672 | wr_m 32*66=2112 | sbias 192 | skqv4 6400 | sxd4 64
#define K1_SMEM_FLOATS (4096 + 12672 + 2112 + 192 + 6400 + 64)
__global__ void kqv_prm_kernel(const float* __restrict__ xg, const float* __restrict__ ln1_g,
                               const float* __restrict__ ln1_b,
                               const float* __restrict__ kqv_w,
                               const float* __restrict__ kqv_b, const float* __restrict__ wrf,
                               float* __restrict__ gv, float* __restrict__ gkp,
                               float* __restrict__ gqp) {
    extern __shared__ float sm[];
    float* sh_h  = sm;                    // [8 tok][512] normalized
    float* wk_f  = sm + 4096;             // [192 f][66] (e minor, padded)
    float* wr_m  = wk_f + 192*WKF_STRIDE; // [32 m][66]
    float* sbias = wr_m + 32*WRM_STRIDE;  // [192]
    float* skqv4 = sbias + 192;           // [4 hd][8 tok][SKQ_STRIDE]
    float* sxd4  = skqv4 + 6400;          // [4 hd][16]
    int tid = threadIdx.x;
    size_t t0 = (size_t)blockIdx.x * 8;

    // ---- fused LN1: warp per token ----
    {
        int tok = tid >> 5, lane = tid & 31;
        const float4* xr = (const float4*)(xg + (t0 + tok) * EMB);
        float4 v[4];
        float s = 0.f, sq = 0.f;
        #pragma unroll
        for (int i = 0; i < 4; i++) {
            v[i] = xr[lane + 32*i];
            s  += v[i].x + v[i].y + v[i].z + v[i].w;
            sq += v[i].x*v[i].x + v[i].y*v[i].y + v[i].z*v[i].z + v[i].w*v[i].w;
        }
        #pragma unroll
        for (int o = 16; o; o >>= 1) {
            s  += __shfl_xor_sync(0xffffffffu, s,  o);
            sq += __shfl_xor_sync(0xffffffffu, sq, o);
        }
        float mean = s * (1.0f/EMB);
        float var  = sq * (1.0f/EMB) - mean*mean;
        float rstd = rsqrtf(var + LN_EPS);
        const float4* g4 = (const float4*)ln1_g;
        const float4* b4 = (const float4*)ln1_b;
        float4* hrow = (float4*)(sh_h + tok * 512);
        #pragma unroll
        for (int i = 0; i < 4; i++) {
            float4 gg = g4[lane + 32*i], bb = b4[lane + 32*i];
            float4 o;
            o.x = (v[i].x - mean) * rstd * gg.x + bb.x;
            o.y = (v[i].y - mean) * rstd * gg.y + bb.y;
            o.z = (v[i].z - mean) * rstd * gg.z + bb.z;
            o.w = (v[i].w - mean) * rstd * gg.w + bb.w;
            hrow[lane + 32*i] = o;
        }
    }
    // ---- weights to smem (f-major / m-major, padded) ----
    #pragma unroll
    for (int i = 0; i < 12; i++) {
        int j = tid + 256*i;                  // 3072 float4 of kqv_w
        int f = j >> 4, e0 = (j & 15) << 2;
        float4 w4 = ((const float4*)kqv_w)[j];
        float* row = wk_f + f * WKF_STRIDE + e0;
        row[0] = w4.x; row[1] = w4.y; row[2] = w4.z; row[3] = w4.w;
    }
    #pragma unroll
    for (int i = 0; i < 2; i++) {
        int j = tid + 256*i;                  // 512 float4 of wrf [32 m][64 e]
        int m = j >> 4, e0 = (j & 15) << 2;
        float4 w4 = ((const float4*)wrf)[j];
        float* row = wr_m + m * WRM_STRIDE + e0;
        row[0] = w4.x; row[1] = w4.y; row[2] = w4.z; row[3] = w4.w;
    }
    if (tid < 192) sbias[tid] = kqv_b[tid];
    __syncthreads();

    int fg = tid & 63, tg = tid >> 6;
    int f0 = fg * 3, tokA = tg * 2;

    for (int hg = 0; hg < 2; hg++) {
        // ---- kqv: packed f32x2 over e-pairs; 3f x 2tok x 4heads tile ----
        uint64_t accp[3][2][4];
        #pragma unroll
        for (int a = 0; a < 3; a++)
            #pragma unroll
            for (int t = 0; t < 2; t++)
                #pragma unroll
                for (int d = 0; d < 4; d++) accp[a][t][d] = 0ull;
        const float* hbase = sh_h + hg * 4 * 64 + tokA * 512;
        const float* w0r = wk_f + (f0+0) * WKF_STRIDE;
        const float* w1r = wk_f + (f0+1) * WKF_STRIDE;
        const float* w2r = wk_f + (f0+2) * WKF_STRIDE;
        #pragma unroll 4
        for (int e = 0; e < 64; e += 2) {
            uint64_t w0 = *(const uint64_t*)(w0r + e);
            uint64_t w1 = *(const uint64_t*)(w1r + e);
            uint64_t w2 = *(const uint64_t*)(w2r + e);
            #pragma unroll
            for (int d = 0; d < 4; d++) {
                uint64_t h0 = *(const uint64_t*)(hbase + d*64 + e);
                uint64_t h1 = *(const uint64_t*)(hbase + 512 + d*64 + e);
                ffma2(accp[0][0][d], w0, h0); ffma2(accp[0][1][d], w0, h1);
                ffma2(accp[1][0][d], w1, h0); ffma2(accp[1][1][d], w1, h1);
                ffma2(accp[2][0][d], w2, h0); ffma2(accp[2][1][d], w2, h1);
            }
        }
        #pragma unroll
        for (int d = 0; d < 4; d++)
            #pragma unroll
            for (int t = 0; t < 2; t++) {
                float* row = skqv4 + d*8*SKQ_STRIDE + (tokA+t)*SKQ_STRIDE;
                float2 p0 = unpk2(accp[0][t][d]);
                float2 p1 = unpk2(accp[1][t][d]);
                float2 p2 = unpk2(accp[2][t][d]);
                row[f0+0] = p0.x + p0.y + sbias[f0+0];
                row[f0+1] = p1.x + p1.y + sbias[f0+1];
                row[f0+2] = p2.x + p2.y + sbias[f0+2];
            }
        __syncthreads();

        // ---- v write: 4*8*64 = 2048 values ----
        #pragma unroll
        for (int i = 0; i < 8; i++) {
            int idx = tid + 256*i;
            int hd4 = idx >> 9, tok = (idx >> 6) & 7, e = idx & 63;
            gv[(((t0 + tok) * HEADS) + hg*4 + hd4) * ES + e] =
                skqv4[hd4*8*SKQ_STRIDE + tok*SKQ_STRIDE + 128 + e];
        }
        // ---- xd ----
        if (tid < 64) {
            int hd4 = tid >> 4, r = tid & 15, tok = r >> 1, which = r & 1;
            const float* z = skqv4 + hd4*8*SKQ_STRIDE + tok*SKQ_STRIDE + which*64;
            float s = 0.f;
            #pragma unroll 8
            for (int e = 0; e < 64; e++) { float zz = z[e]; s += zz*zz; }
            sxd4[hd4*16 + r] = 0.5f * s;
        }
        __syncthreads();

        // ---- wtx + exp: 512 slots x 4m, packed over e-pairs ----
        #pragma unroll
        for (int i = 0; i < 2; i++) {
            int sidx = tid + 256*i;
            int mg = sidx & 7, which = (sidx >> 3) & 1, tok = (sidx >> 4) & 7, hd4 = sidx >> 7;
            int m0 = mg * 4;
            const float* z = skqv4 + hd4*8*SKQ_STRIDE + tok*SKQ_STRIDE + which*64;
            uint64_t a0p = 0ull, a1p = 0ull, a2p = 0ull, a3p = 0ull;
            const float* wm0 = wr_m + (m0+0) * WRM_STRIDE;
            const float* wm1 = wr_m + (m0+1) * WRM_STRIDE;
            const float* wm2 = wr_m + (m0+2) * WRM_STRIDE;
            const float* wm3 = wr_m + (m0+3) * WRM_STRIDE;
            #pragma unroll 4
            for (int e = 0; e < 64; e += 2) {
                uint64_t zp = *(const uint64_t*)(z + e);
                ffma2(a0p, zp, *(const uint64_t*)(wm0 + e));
                ffma2(a1p, zp, *(const uint64_t*)(wm1 + e));
                ffma2(a2p, zp, *(const uint64_t*)(wm2 + e));
                ffma2(a3p, zp, *(const uint64_t*)(wm3 + e));
            }
            float2 q0 = unpk2(a0p), q1 = unpk2(a1p), q2 = unpk2(a2p), q3 = unpk2(a3p);
            float xdv = sxd4[hd4*16 + tok*2 + which];
            float4 o;
            o.x = expf(q0.x + q0.y - xdv) * 0.17677669529663689f;
            o.y = expf(q1.x + q1.y - xdv) * 0.17677669529663689f;
            o.z = expf(q2.x + q2.y - xdv) * 0.17677669529663689f;
            o.w = expf(q3.x + q3.y - xdv) * 0.17677669529663689f;
            float* dst = which ? gqp : gkp;
            *(float4*)&dst[(((t0 + tok) * HEADS) + hg*4 + hd4) * MF + m0] = o;
        }
        __syncthreads();
    }
}

// ---------------- kptv / ksum partial reduction over T ----------------
__global__ void kpt_kernel(const float* __restrict__ gv, const float* __restrict__ gkp,
                           float* __restrict__ part_kptv, float* __restrict__ part_ksum) {
    int chunk = blockIdx.x;
    int bh = blockIdx.y;
    int b = bh >> 3, h = bh & 7;
    __shared__ float sv[16][64];
    __shared__ float skp[16][32];
    int tid = threadIdx.x, lane = tid & 31, wid = tid >> 5;
    float acc[8] = {0,0,0,0,0,0,0,0};
    float ks = 0.f;
    int t0 = chunk * 256;
    for (int st = 0; st < 16; st++) {
        int s0 = t0 + st * 16;
        __syncthreads();
        #pragma unroll
        for (int i = 0; i < 4; i++) {
            int idx = tid + 256*i;
            int s = idx >> 6, e = idx & 63;
            sv[s][e] = gv[((((size_t)b*TQ + s0 + s) * HEADS) + h) * ES + e];
        }
        #pragma unroll
        for (int i = 0; i < 2; i++) {
            int idx = tid + 256*i;
            int s = idx >> 5, m = idx & 31;
            skp[s][m] = gkp[((((size_t)b*TQ + s0 + s) * HEADS) + h) * MF + m];
        }
        __syncthreads();
        #pragma unroll
        for (int s = 0; s < 16; s++) {
            float kv = skp[s][lane];
            float4 va = *(const float4*)&sv[s][wid*8];
            float4 vb = *(const float4*)&sv[s][wid*8 + 4];
            acc[0] += va.x*kv; acc[1] += va.y*kv; acc[2] += va.z*kv; acc[3] += va.w*kv;
            acc[4] += vb.x*kv; acc[5] += vb.y*kv; acc[6] += vb.z*kv; acc[7] += vb.w*kv;
            if (wid == 0) ks += kv;
        }
    }
    size_t base = ((size_t)(chunk*64 + bh)) * (ES*MF);
    #pragma unroll
    for (int j = 0; j < 8; j++)
        part_kptv[base + (wid*8 + j)*MF + lane] = acc[j];
    if (wid == 0) part_ksum[(chunk*64 + bh)*MF + lane] = ks;
}

__global__ void reduce_kernel(const float* __restrict__ pk, const float* __restrict__ ps,
                              float* __restrict__ kptv, float* __restrict__ ksum) {
    int bid = blockIdx.x;
    if (bid < 512) {
        int idx = bid * 256 + threadIdx.x;
        int bh = idx >> 11;
        float s = 0.f;
        #pragma unroll
        for (int c = 0; c < 16; c++) s += pk[((size_t)(c*64 + bh)) * 2048 + (idx & 2047)];
        kptv[idx] = s;
    } else {
        #pragma unroll
        for (int j = 0; j < 8; j++) {
            int idx = threadIdx.x * 8 + j;
            int bh = idx >> 5, m = idx & 31;
            float s = 0.f;
            #pragma unroll
            for (int c = 0; c < 16; c++) s += ps[(c*64 + bh)*MF + m];
            ksum[idx] = s;
        }
    }
}

// ---------------- y = (qp . kptv) / D  -> fp16 ----------------
__global__ void y_kernel(const float* __restrict__ gqp, const float* __restrict__ kptv,
                         const float* __restrict__ ksum, __half* __restrict__ yh) {
    int bh = blockIdx.y, b = bh >> 3, h = bh & 7;
    __shared__ float sk[64*33];
    __shared__ float sks[32];
    int tid = threadIdx.x, lane = tid & 31, wid = tid >> 5;
    #pragma unroll
    for (int i = 0; i < 8; i++) {
        int idx = tid + 256*i;
        sk[(idx >> 5)*33 + (idx & 31)] = kptv[(size_t)bh*2048 + idx];
    }
    if (tid < 32) sks[tid] = ksum[bh*32 + tid];
    __syncthreads();
    float ksv = sks[lane];
    for (int it = 0; it < 32; it++) {
        int t = blockIdx.x * 256 + wid * 32 + it;
        float qpv = gqp[((((size_t)b*TQ + t) * HEADS) + h) * MF + lane];
        float d = qpv * ksv;
        #pragma unroll
        for (int o = 16; o; o >>= 1) d += __shfl_xor_sync(0xffffffffu, d, o);
        float a0 = 0.f, a1 = 0.f;
        #pragma unroll
        for (int m = 0; m < 32; m++) {
            float qm = __shfl_sync(0xffffffffu, qpv, m);
            a0 += qm * sk[lane*33 + m];
            a1 += qm * sk[(lane+32)*33 + m];
        }
        float inv = 1.0f / d;
        size_t off = ((size_t)b*TQ + t) * EMB + h * ES;
        yh[off + lane]      = __float2half(a0 * inv);
        yh[off + lane + 32] = __float2half(a1 * inv);
    }
}

// ============== mma.sync fp16 GEMM (fp32 accum), 3-stage, ONE sync per chunk ==============
#define PLANE_BYTES 16384
#define BUF_BYTES (2*PLANE_BYTES)
#define GEMM_SMEM (3*BUF_BYTES)

#define SWZ_ADDR(base, row, chunk) \
    ((base) + (uint32_t)(row)*128u + (uint32_t)(((chunk) ^ ((row)&7)) << 4))

template<int EPI>
__global__ __launch_bounds__(256, 2)
void gemm_mma(const __half* __restrict__ Ah, const __half* __restrict__ Bh,
              const float* __restrict__ bias, const float* __restrict__ res,
              float* __restrict__ Cf, __half* __restrict__ Chi, int N, int K) {
    extern __shared__ char gsm[];
    uint32_t sb = smem_to_u32(gsm);
    int tid = threadIdx.x, lane = tid & 31, wid = tid >> 5;
    int rowBase = blockIdx.y * 128, colBase = blockIdx.x * 128;

    int wm = wid & 3, wn = wid >> 2;
    int m0 = wm * 32, n0 = wn * 64;

    float acc[2][8][4];
    #pragma unroll
    for (int i = 0; i < 2; i++)
        #pragma unroll
        for (int j = 0; j < 8; j++)
            #pragma unroll
            for (int q = 0; q < 4; q++) acc[i][j][q] = 0.f;

    int arow_l = (lane & 15);
    int acb    = (lane >> 4);
    int brow_l = (lane & 7) + ((lane >> 4) << 3);
    int bcb    = (lane >> 3) & 1;

    auto load_chunk = [&](int buf, int k0) {
        uint32_t sbase = sb + buf * BUF_BYTES;
        int row = tid >> 1, c0 = (tid & 1) * 4;
        size_t goA = (size_t)(rowBase + row) * K + k0 + c0 * 8;
        size_t goB = (size_t)(colBase + row) * K + k0 + c0 * 8;
        #pragma unroll
        for (int j = 0; j < 4; j++) {
            uint32_t so = SWZ_ADDR(sbase, row, c0 + j);
            cp_async16(so,               Ah + goA + j * 8);
            cp_async16(PLANE_BYTES + so, Bh + goB + j * 8);
        }
    };

    int NC = K >> 6;
    load_chunk(0, 0);
    CP_COMMIT();
    load_chunk(1, 64);
    CP_COMMIT();

    int bufc = 0, bufn = 2;
    for (int c = 0; c < NC; c++) {
        if (c + 1 < NC) { CP_WAIT1(); } else { CP_WAIT0(); }
        __syncthreads();
        if (c + 2 < NC) {
            load_chunk(bufn, (c + 2) << 6);
            CP_COMMIT();
        }

        uint32_t pA = sb + bufc * BUF_BYTES;
        #pragma unroll
        for (int ks = 0; ks < 4; ks++) {
            uint32_t ah[2][4];
            #pragma unroll
            for (int mt = 0; mt < 2; mt++) {
                int ar = m0 + mt * 16 + arow_l;
                uint32_t ad = SWZ_ADDR(pA, ar, ks * 2 + acb);
                ldsm_x4(ah[mt][0], ah[mt][1], ah[mt][2], ah[mt][3], ad);
            }
            #pragma unroll
            for (int ng = 0; ng < 4; ng++) {
                int br = n0 + ng * 16 + brow_l;
                uint32_t bd = SWZ_ADDR(pA + PLANE_BYTES, br, ks * 2 + bcb);
                uint32_t bh2[2][2];
                ldsm_x4(bh2[0][0], bh2[0][1], bh2[1][0], bh2[1][1], bd);
                #pragma unroll
                for (int mt = 0; mt < 2; mt++)
                    #pragma unroll
                    for (int j = 0; j < 2; j++)
                        mma_f16(acc[mt][2*ng + j], ah[mt], bh2[j]);
            }
        }
        bufc = (bufc + 1 == 3) ? 0 : bufc + 1;
        bufn = (bufn + 1 == 3) ? 0 : bufn + 1;
    }

    int rbase = rowBase + m0 + (lane >> 2);
    int cbase = colBase + n0 + (lane & 3) * 2;
    #pragma unroll
    for (int mt = 0; mt < 2; mt++) {
        #pragma unroll
        for (int half = 0; half < 2; half++) {
            int row = rbase + mt * 16 + half * 8;
            if (EPI == 0) {
                float* crow = Cf + (size_t)row * N;
                const float* rrow = res + (size_t)row * N;
                #pragma unroll
                for (int nt = 0; nt < 8; nt++) {
                    int col = cbase + nt * 8;
                    float2 o;
                    o.x = acc[mt][nt][half*2+0] + bias[col]   + rrow[col];
                    o.y = acc[mt][nt][half*2+1] + bias[col+1] + rrow[col+1];
                    *(float2*)(crow + col) = o;
                }
            } else {
                __half* hrow = Chi + (size_t)row * N;
                #pragma unroll
                for (int nt = 0; nt < 8; nt++) {
                    int col = cbase + nt * 8;
                    float v0 = acc[mt][nt][half*2+0] + bias[col];
                    float v1 = acc[mt][nt][half*2+1] + bias[col+1];
                    v0 = 0.5f * v0 * (1.0f + erff(v0 * 0.70710678118654752f));
                    v1 = 0.5f * v1 * (1.0f + erff(v1 * 0.70710678118654752f));
                    __half hh[2] = {__float2half(v0), __float2half(v1)};
                    *(uint32_t*)(hrow + col) = *(uint32_t*)hh;
                }
            }
        }
    }
}

// ---------------- launch ----------------
extern "C" void kernel_launch(void* const* d_in, const int* in_sizes, int n_in,
                              void* d_out, int out_size) {
    const float* x      = (const float*)d_in[0];
    const float* wrf    = (const float*)d_in[1];
    const float* kqv_w  = (const float*)d_in[2];
    const float* kqv_b  = (const float*)d_in[3];
    const float* proj_w = (const float*)d_in[4];
    const float* proj_b = (const float*)d_in[5];
    const float* ln1_g  = (const float*)d_in[6];
    const float* ln1_b  = (const float*)d_in[7];
    const float* ln2_g  = (const float*)d_in[8];
    const float* ln2_b  = (const float*)d_in[9];
    const float* mlp_w1 = (const float*)d_in[10];
    const float* mlp_b1 = (const float*)d_in[11];
    const float* mlp_w2 = (const float*)d_in[12];
    const float* mlp_b2 = (const float*)d_in[13];
    float* out = (float*)d_out;

    float *p_v, *p_qp, *p_kp, *p_pk, *p_ps, *p_kptv, *p_ksum, *p_x1;
    __half *p_h2h, *p_yh, *p_hidh, *p_pwh, *p_w1h, *p_w2h;
    cudaGetSymbolAddress((void**)&p_v,    g_v);
    cudaGetSymbolAddress((void**)&p_qp,   g_qp);
    cudaGetSymbolAddress((void**)&p_kp,   g_kp);
    cudaGetSymbolAddress((void**)&p_pk,   g_kptv_part);
    cudaGetSymbolAddress((void**)&p_ps,   g_ksum_part);
    cudaGetSymbolAddress((void**)&p_kptv, g_kptv);
    cudaGetSymbolAddress((void**)&p_ksum, g_ksum);
    cudaGetSymbolAddress((void**)&p_x1,   g_x1);
    cudaGetSymbolAddress((void**)&p_h2h,  g_h2h);
    cudaGetSymbolAddress((void**)&p_yh,   g_yh);
    cudaGetSymbolAddress((void**)&p_hidh, g_hidh);
    cudaGetSymbolAddress((void**)&p_pwh,  g_pwh);
    cudaGetSymbolAddress((void**)&p_w1h,  g_w1h);
    cudaGetSymbolAddress((void**)&p_w2h,  g_w2h);

    const size_t k1_smem = (size_t)K1_SMEM_FLOATS * sizeof(float);   // ~102KB
    cudaFuncSetAttribute(kqv_prm_kernel, cudaFuncAttributeMaxDynamicSharedMemorySize,
                         (int)k1_smem);
    cudaFuncSetAttribute(gemm_mma<0>, cudaFuncAttributeMaxDynamicSharedMemorySize, GEMM_SMEM);
    cudaFuncSetAttribute(gemm_mma<1>, cudaFuncAttributeMaxDynamicSharedMemorySize, GEMM_SMEM);

    // 0. all weight fp16 rounds (one launch)
    cvt_all_kernel<<<(CVT_N4 + 255)/256, 256>>>(proj_w, mlp_w1, mlp_w2, p_pwh, p_w1h, p_w2h);
    // 1. fused LN1 + kqv + prm_exp (f32x2-packed)
    kqv_prm_kernel<<<NTOK/8, 256, k1_smem>>>(x, ln1_g, ln1_b, kqv_w, kqv_b, wrf,
                                             p_v, p_kp, p_qp);
    // 2-3. kptv/ksum reduction over T
    kpt_kernel<<<dim3(16, 64), 256>>>(p_v, p_kp, p_pk, p_ps);
    reduce_kernel<<<513, 256>>>(p_pk, p_ps, p_kptv, p_ksum);
    // 4. y (fp16)
    y_kernel<<<dim3(TQ/256, 64), 256>>>(p_qp, p_kptv, p_ksum, p_yh);
    // 5. attn proj + residual -> x1 (fp32)
    gemm_mma<0><<<dim3(EMB/128, NTOK/128), 256, GEMM_SMEM>>>(
        p_yh, p_pwh, proj_b, x, p_x1, nullptr, EMB, EMB);
    // 6. LN2 -> fp16
    ln2_kernel<<<NTOK/8, 256>>>(p_x1, ln2_g, ln2_b, p_h2h);
    // 7. mlp1 + gelu -> hid (fp16)
    gemm_mma<1><<<dim3(HID/128, NTOK/128), 256, GEMM_SMEM>>>(
        p_h2h, p_w1h, mlp_b1, nullptr, nullptr, p_hidh, HID, EMB);
    // 8. mlp2 + residual -> out (fp32)
    gemm_mma<0><<<dim3(EMB/128, NTOK/128), 256, GEMM_SMEM>>>(
        p_hidh, p_w2h, mlp_b2, p_x1, out, nullptr, EMB, HID);
}

// round 11
// speedup vs baseline: 1.2005x; 1.2005x over previous
#include <cuda_runtime.h>
#include <cuda_fp16.h>
#include <math.h>
#include <stdint.h>

// Problem constants
#define BQ 8
#define TQ 4096
#define NTOK (BQ*TQ)          // 32768 tokens
#define EMB 512
#define HEADS 8
#define ES 64
#define MF 32                 // random features
#define HID (4*EMB)           // 2048
#define LN_EPS 1e-5f

__device__ __forceinline__ uint32_t smem_to_u32(const void* smem_ptr) {
    uint32_t addr;
    asm("{ .reg .u64 tmp; cvta.to.shared.u64 tmp, %1; cvt.u32.u64 %0, tmp; }"
        : "=r"(addr) : "l"(smem_ptr));
    return addr;
}

__device__ __forceinline__ void cp_async16(uint32_t saddr, const void* gaddr) {
    asm volatile("cp.async.cg.shared.global [%0], [%1], 16;" :: "r"(saddr), "l"(gaddr));
}
#define CP_COMMIT() asm volatile("cp.async.commit_group;" ::: "memory")
#define CP_WAIT0()  asm volatile("cp.async.wait_group 0;" ::: "memory")
#define CP_WAIT1()  asm volatile("cp.async.wait_group 1;" ::: "memory")

__device__ __forceinline__ void ldsm_x4(uint32_t& r0, uint32_t& r1, uint32_t& r2, uint32_t& r3,
                                        uint32_t addr) {
    asm volatile("ldmatrix.sync.aligned.m8n8.x4.shared.b16 {%0,%1,%2,%3}, [%4];"
        : "=r"(r0), "=r"(r1), "=r"(r2), "=r"(r3) : "r"(addr));
}

__device__ __forceinline__ void mma_f16(float* c, const uint32_t* a, const uint32_t* b) {
    asm volatile(
        "mma.sync.aligned.m16n8k16.row.col.f32.f16.f16.f32 "
        "{%0,%1,%2,%3}, {%4,%5,%6,%7}, {%8,%9}, {%0,%1,%2,%3};"
        : "+f"(c[0]), "+f"(c[1]), "+f"(c[2]), "+f"(c[3])
        : "r"(a[0]), "r"(a[1]), "r"(a[2]), "r"(a[3]), "r"(b[0]), "r"(b[1]));
}

// -------- scratch (device globals; no runtime allocation) --------
__device__ float g_v[(size_t)NTOK*HEADS*ES];
__device__ float g_qp[(size_t)NTOK*HEADS*MF];
__device__ float g_kp[(size_t)NTOK*HEADS*MF];
__device__ float g_kptv_part[16*64*ES*MF];
__device__ float g_ksum_part[16*64*MF];
__device__ float g_kptv[64*ES*MF];
__device__ float g_ksum[64*MF];
__device__ float g_x1[(size_t)NTOK*EMB];
__device__ __align__(16) __half g_h2h[(size_t)NTOK*EMB];
__device__ __align__(16) __half g_yh[(size_t)NTOK*EMB];
__device__ __align__(16) __half g_hidh[(size_t)NTOK*HID];
__device__ __align__(16) __half g_pwh[EMB*EMB];
__device__ __align__(16) __half g_w1h[HID*EMB];
__device__ __align__(16) __half g_w2h[EMB*HID];
__device__ __align__(16) __half g_kwh[192*64];   // kqv_w fp16

// ---------------- fused weight fp16 conversion (all 4 weights) ----------------
// float4 ranges: [0,64K) proj | [64K,320K) w1 | [320K,576K) w2 | [576K,579K) kqv_w
#define CVT_N4 (65536 + 262144 + 262144 + 3072)
__global__ void cvt_all_kernel(const float* __restrict__ pw, const float* __restrict__ w1,
                               const float* __restrict__ w2, const float* __restrict__ kw,
                               __half* __restrict__ pwh, __half* __restrict__ w1h,
                               __half* __restrict__ w2h, __half* __restrict__ kwh) {
    int i = blockIdx.x * 256 + threadIdx.x;
    if (i >= CVT_N4) return;
    const float* src;
    __half* dst;
    int j;
    if (i < 65536)       { src = pw; dst = pwh; j = i; }
    else if (i < 327680) { src = w1; dst = w1h; j = i - 65536; }
    else if (i < 589824) { src = w2; dst = w2h; j = i - 327680; }
    else                 { src = kw; dst = kwh; j = i - 589824; }
    float4 v = ((const float4*)src)[j];
    __half h[4];
    h[0] = __float2half(v.x); h[1] = __float2half(v.y);
    h[2] = __float2half(v.z); h[3] = __float2half(v.w);
    *(uint2*)(dst + (size_t)j*4) = *(uint2*)h;
}

// ---------------- LayerNorm (LN2): warp per token, fp16 out ----------------
__global__ void ln2_kernel(const float* __restrict__ x, const float* __restrict__ g,
                           const float* __restrict__ b, __half* __restrict__ ohi) {
    int tok  = blockIdx.x * 8 + (threadIdx.x >> 5);
    int lane = threadIdx.x & 31;
    const float4* xr = (const float4*)(x + (size_t)tok * EMB);
    float4 v[4];
    float s = 0.f, sq = 0.f;
    #pragma unroll
    for (int i = 0; i < 4; i++) {
        v[i] = xr[lane + 32*i];
        s  += v[i].x + v[i].y + v[i].z + v[i].w;
        sq += v[i].x*v[i].x + v[i].y*v[i].y + v[i].z*v[i].z + v[i].w*v[i].w;
    }
    #pragma unroll
    for (int o = 16; o; o >>= 1) {
        s  += __shfl_xor_sync(0xffffffffu, s,  o);
        sq += __shfl_xor_sync(0xffffffffu, sq, o);
    }
    float mean = s * (1.0f/EMB);
    float var  = sq * (1.0f/EMB) - mean*mean;
    float rstd = rsqrtf(var + LN_EPS);
    const float4* g4 = (const float4*)g;
    const float4* b4 = (const float4*)b;
    #pragma unroll
    for (int i = 0; i < 4; i++) {
        float4 gg = g4[lane + 32*i], bb = b4[lane + 32*i];
        size_t idx = (size_t)tok * EMB + (size_t)(lane + 32*i) * 4;
        __half h[4];
        h[0] = __float2half((v[i].x - mean) * rstd * gg.x + bb.x);
        h[1] = __float2half((v[i].y - mean) * rstd * gg.y + bb.y);
        h[2] = __float2half((v[i].z - mean) * rstd * gg.z + bb.z);
        h[3] = __float2half((v[i].w - mean) * rstd * gg.w + bb.w);
        *(uint2*)(ohi + idx) = *(uint2*)h;
    }
}

// ======== fused LN1 + tensor-core kqv + prm_exp (8 tok/block, 4 heads/pass) ========
// Per pass: A = 32 rows (4 hd x 8 tok) x 64 e, split hi/lo fp16 (exact);
// W = kqv_w fp16 [192 f x 64 e] in smem. MMA m16n8k16, 2 terms, fp32 accum.
// smem bytes: sh_h 16384 | w16 24576 | a_hi 4096 | a_lo 4096 |
//             wr_t 8192 | sbias 768 | skqv4 25600 | sxd4 256  => 83968
#define SKQ_STRIDE 200
#define W16_OFF 16384
#define AHI_OFF 40960
#define ALO_OFF 45056
#define K1_SMEM_FLOATS 20992
__global__ void kqv_prm_kernel(const float* __restrict__ xg, const float* __restrict__ ln1_g,
                               const float* __restrict__ ln1_b,
                               const __half* __restrict__ kwh,
                               const float* __restrict__ kqv_b, const float* __restrict__ wrf,
                               float* __restrict__ gv, float* __restrict__ gkp,
                               float* __restrict__ gqp) {
    extern __shared__ float sm[];
    char* smc = (char*)sm;
    uint32_t sb = smem_to_u32(sm);
    float* sh_h  = sm;                    // [8 tok][512]
    float* wr_t  = sm + 12288;            // [64 e][32 m]
    float* sbias = wr_t + 2048;           // [192]
    float* skqv4 = sbias + 192;           // [4 hd][8 tok][SKQ_STRIDE]
    float* sxd4  = skqv4 + 6400;          // [4 hd][16]
    int tid = threadIdx.x, lane = tid & 31, wid = tid >> 5;
    size_t t0 = (size_t)blockIdx.x * 8;

    // ---- kqv_w fp16 -> smem via cp.async (192 rows x 128B, swizzled) ----
    #pragma unroll
    for (int i = 0; i < 6; i++) {
        int idx = tid + 256*i;            // 1536 x 16B
        int row = idx >> 3, c = idx & 7;
        cp_async16(sb + W16_OFF + (uint32_t)row*128 + (uint32_t)((c ^ (row & 7)) << 4),
                   kwh + row*64 + c*8);
    }
    CP_COMMIT();

    // ---- fused LN1: warp per token -> sh_h (fp32) ----
    {
        int tok = tid >> 5;
        const float4* xr = (const float4*)(xg + (t0 + tok) * EMB);
        float4 v[4];
        float s = 0.f, sq = 0.f;
        #pragma unroll
        for (int i = 0; i < 4; i++) {
            v[i] = xr[lane + 32*i];
            s  += v[i].x + v[i].y + v[i].z + v[i].w;
            sq += v[i].x*v[i].x + v[i].y*v[i].y + v[i].z*v[i].z + v[i].w*v[i].w;
        }
        #pragma unroll
        for (int o = 16; o; o >>= 1) {
            s  += __shfl_xor_sync(0xffffffffu, s,  o);
            sq += __shfl_xor_sync(0xffffffffu, sq, o);
        }
        float mean = s * (1.0f/EMB);
        float var  = sq * (1.0f/EMB) - mean*mean;
        float rstd = rsqrtf(var + LN_EPS);
        const float4* g4 = (const float4*)ln1_g;
        const float4* b4 = (const float4*)ln1_b;
        float4* hrow = (float4*)(sh_h + tok * 512);
        #pragma unroll
        for (int i = 0; i < 4; i++) {
            float4 gg = g4[lane + 32*i], bb = b4[lane + 32*i];
            float4 o;
            o.x = (v[i].x - mean) * rstd * gg.x + bb.x;
            o.y = (v[i].y - mean) * rstd * gg.y + bb.y;
            o.z = (v[i].z - mean) * rstd * gg.z + bb.z;
            o.w = (v[i].w - mean) * rstd * gg.w + bb.w;
            hrow[lane + 32*i] = o;
        }
    }
    // ---- wr_t [64 e][32 m] (R9 layout) + bias ----
    #pragma unroll
    for (int i = 0; i < 2; i++) {
        int j = tid + 256*i;              // 512 float4 of wrf [32 m][64 e]
        int m = j >> 4, e0 = (j & 15) << 2;
        float4 w4 = ((const float4*)wrf)[j];
        wr_t[(e0+0)*32 + m] = w4.x;
        wr_t[(e0+1)*32 + m] = w4.y;
        wr_t[(e0+2)*32 + m] = w4.z;
        wr_t[(e0+3)*32 + m] = w4.w;
    }
    if (tid < 192) sbias[tid] = kqv_b[tid];
    CP_WAIT0();
    __syncthreads();

    // warp layout: 2 m-warps x 4 n-warps; warp tile 16 x 48
    int wm = wid & 1, wn = wid >> 1;
    int m0 = wm * 16, n0 = wn * 48;
    int arow = m0 + (lane & 15), acb = lane >> 4;
    int brow_l = (lane & 7) + ((lane >> 4) << 3), bcb = (lane >> 3) & 1;

    for (int hg = 0; hg < 2; hg++) {
        // ---- convert A (32 rows x 64 e) to hi/lo fp16, swizzled ----
        {
            int r = tid >> 3, c = tid & 7;        // r = hd4*8 + tok
            int hd4 = r >> 3, tok = r & 7;
            const float* hp = sh_h + tok*512 + (hg*4 + hd4)*64 + c*8;
            float4 f0 = *(const float4*)hp;
            float4 f1 = *(const float4*)(hp + 4);
            float vv[8] = {f0.x,f0.y,f0.z,f0.w,f1.x,f1.y,f1.z,f1.w};
            __half hi[8], lo[8];
            #pragma unroll
            for (int q = 0; q < 8; q++) {
                hi[q] = __float2half(vv[q]);
                lo[q] = __float2half(vv[q] - __half2float(hi[q]));
            }
            uint32_t off = (uint32_t)r*128 + (uint32_t)((c ^ (r & 7)) << 4);
            *(uint4*)(smc + AHI_OFF + off) = *(uint4*)hi;
            *(uint4*)(smc + ALO_OFF + off) = *(uint4*)lo;
        }
        __syncthreads();

        // ---- MMA: 2-term (hi+lo) x W16 ----
        float acc[6][4];
        #pragma unroll
        for (int nf = 0; nf < 6; nf++)
            #pragma unroll
            for (int q = 0; q < 4; q++) acc[nf][q] = 0.f;
        #pragma unroll
        for (int ks = 0; ks < 4; ks++) {
            uint32_t aoff = (uint32_t)arow*128 +
                            (uint32_t)((((ks*2 + acb)) ^ (arow & 7)) << 4);
            uint32_t ah[4], al[4];
            ldsm_x4(ah[0], ah[1], ah[2], ah[3], sb + AHI_OFF + aoff);
            ldsm_x4(al[0], al[1], al[2], al[3], sb + ALO_OFF + aoff);
            #pragma unroll
            for (int ng = 0; ng < 3; ng++) {
                int br = n0 + ng*16 + brow_l;
                uint32_t boff = (uint32_t)br*128 +
                                (uint32_t)(((ks*2 + bcb) ^ (br & 7)) << 4);
                uint32_t b2[2][2];
                ldsm_x4(b2[0][0], b2[0][1], b2[1][0], b2[1][1], sb + W16_OFF + boff);
                #pragma unroll
                for (int j = 0; j < 2; j++) {
                    mma_f16(acc[2*ng + j], ah, b2[j]);
                    mma_f16(acc[2*ng + j], al, b2[j]);
                }
            }
        }
        // ---- epilogue: acc + bias -> skqv4 ----
        {
            int rb = m0 + (lane >> 2);
            int cb = n0 + (lane & 3) * 2;
            #pragma unroll
            for (int half = 0; half < 2; half++) {
                int r = rb + half*8;
                int hd4 = r >> 3, tok = r & 7;
                float* row = skqv4 + hd4*8*SKQ_STRIDE + tok*SKQ_STRIDE;
                #pragma unroll
                for (int nf = 0; nf < 6; nf++) {
                    int col = cb + nf*8;
                    row[col]   = acc[nf][half*2+0] + sbias[col];
                    row[col+1] = acc[nf][half*2+1] + sbias[col+1];
                }
            }
        }
        __syncthreads();

        // ---- v write: 4*8*64 = 2048 values ----
        #pragma unroll
        for (int i = 0; i < 8; i++) {
            int idx = tid + 256*i;
            int hd4 = idx >> 9, tok = (idx >> 6) & 7, e = idx & 63;
            gv[(((t0 + tok) * HEADS) + hg*4 + hd4) * ES + e] =
                skqv4[hd4*8*SKQ_STRIDE + tok*SKQ_STRIDE + 128 + e];
        }
        // ---- xd ----
        if (tid < 64) {
            int hd4 = tid >> 4, r = tid & 15, tok = r >> 1, which = r & 1;
            const float* z = skqv4 + hd4*8*SKQ_STRIDE + tok*SKQ_STRIDE + which*64;
            float s = 0.f;
            #pragma unroll 8
            for (int e = 0; e < 64; e++) { float zz = z[e]; s += zz*zz; }
            sxd4[hd4*16 + r] = 0.5f * s;
        }
        __syncthreads();

        // ---- wtx + exp: 512 slots x 4m (R9 verbatim) ----
        #pragma unroll
        for (int i = 0; i < 2; i++) {
            int sidx = tid + 256*i;
            int mg = sidx & 7, which = (sidx >> 3) & 1, tok = (sidx >> 4) & 7, hd4 = sidx >> 7;
            int mq = mg * 4;
            const float* z = skqv4 + hd4*8*SKQ_STRIDE + tok*SKQ_STRIDE + which*64;
            float a0 = 0.f, a1 = 0.f, a2 = 0.f, a3 = 0.f;
            #pragma unroll 8
            for (int e = 0; e < 64; e++) {
                float zv = z[e];
                float4 w4 = *(const float4*)&wr_t[e*32 + mq];
                a0 += zv*w4.x; a1 += zv*w4.y; a2 += zv*w4.z; a3 += zv*w4.w;
            }
            float xdv = sxd4[hd4*16 + tok*2 + which];
            float4 o;
            o.x = expf(a0 - xdv) * 0.17677669529663689f;
            o.y = expf(a1 - xdv) * 0.17677669529663689f;
            o.z = expf(a2 - xdv) * 0.17677669529663689f;
            o.w = expf(a3 - xdv) * 0.17677669529663689f;
            float* dst = which ? gqp : gkp;
            *(float4*)&dst[(((t0 + tok) * HEADS) + hg*4 + hd4) * MF + mq] = o;
        }
        __syncthreads();
    }
}

// ---------------- kptv / ksum partial reduction over T ----------------
__global__ void kpt_kernel(const float* __restrict__ gv, const float* __restrict__ gkp,
                           float* __restrict__ part_kptv, float* __restrict__ part_ksum) {
    int chunk = blockIdx.x;
    int bh = blockIdx.y;
    int b = bh >> 3, h = bh & 7;
    __shared__ float sv[16][64];
    __shared__ float skp[16][32];
    int tid = threadIdx.x, lane = tid & 31, wid = tid >> 5;
    float acc[8] = {0,0,0,0,0,0,0,0};
    float ks = 0.f;
    int t0 = chunk * 256;
    for (int st = 0; st < 16; st++) {
        int s0 = t0 + st * 16;
        __syncthreads();
        #pragma unroll
        for (int i = 0; i < 4; i++) {
            int idx = tid + 256*i;
            int s = idx >> 6, e = idx & 63;
            sv[s][e] = gv[((((size_t)b*TQ + s0 + s) * HEADS) + h) * ES + e];
        }
        #pragma unroll
        for (int i = 0; i < 2; i++) {
            int idx = tid + 256*i;
            int s = idx >> 5, m = idx & 31;
            skp[s][m] = gkp[((((size_t)b*TQ + s0 + s) * HEADS) + h) * MF + m];
        }
        __syncthreads();
        #pragma unroll
        for (int s = 0; s < 16; s++) {
            float kv = skp[s][lane];
            float4 va = *(const float4*)&sv[s][wid*8];
            float4 vb = *(const float4*)&sv[s][wid*8 + 4];
            acc[0] += va.x*kv; acc[1] += va.y*kv; acc[2] += va.z*kv; acc[3] += va.w*kv;
            acc[4] += vb.x*kv; acc[5] += vb.y*kv; acc[6] += vb.z*kv; acc[7] += vb.w*kv;
            if (wid == 0) ks += kv;
        }
    }
    size_t base = ((size_t)(chunk*64 + bh)) * (ES*MF);
    #pragma unroll
    for (int j = 0; j < 8; j++)
        part_kptv[base + (wid*8 + j)*MF + lane] = acc[j];
    if (wid == 0) part_ksum[(chunk*64 + bh)*MF + lane] = ks;
}

__global__ void reduce_kernel(const float* __restrict__ pk, const float* __restrict__ ps,
                              float* __restrict__ kptv, float* __restrict__ ksum) {
    int bid = blockIdx.x;
    if (bid < 512) {
        int idx = bid * 256 + threadIdx.x;
        int bh = idx >> 11;
        float s = 0.f;
        #pragma unroll
        for (int c = 0; c < 16; c++) s += pk[((size_t)(c*64 + bh)) * 2048 + (idx & 2047)];
        kptv[idx] = s;
    } else {
        #pragma unroll
        for (int j = 0; j < 8; j++) {
            int idx = threadIdx.x * 8 + j;
            int bh = idx >> 5, m = idx & 31;
            float s = 0.f;
            #pragma unroll
            for (int c = 0; c < 16; c++) s += ps[(c*64 + bh)*MF + m];
            ksum[idx] = s;
        }
    }
}

// ---------------- y = (qp . kptv) / D  -> fp16 ----------------
__global__ void y_kernel(const float* __restrict__ gqp, const float* __restrict__ kptv,
                         const float* __restrict__ ksum, __half* __restrict__ yh) {
    int bh = blockIdx.y, b = bh >> 3, h = bh & 7;
    __shared__ float sk[64*33];
    __shared__ float sks[32];
    int tid = threadIdx.x, lane = tid & 31, wid = tid >> 5;
    #pragma unroll
    for (int i = 0; i < 8; i++) {
        int idx = tid + 256*i;
        sk[(idx >> 5)*33 + (idx & 31)] = kptv[(size_t)bh*2048 + idx];
    }
    if (tid < 32) sks[tid] = ksum[bh*32 + tid];
    __syncthreads();
    float ksv = sks[lane];
    for (int it = 0; it < 32; it++) {
        int t = blockIdx.x * 256 + wid * 32 + it;
        float qpv = gqp[((((size_t)b*TQ + t) * HEADS) + h) * MF + lane];
        float d = qpv * ksv;
        #pragma unroll
        for (int o = 16; o; o >>= 1) d += __shfl_xor_sync(0xffffffffu, d, o);
        float a0 = 0.f, a1 = 0.f;
        #pragma unroll
        for (int m = 0; m < 32; m++) {
            float qm = __shfl_sync(0xffffffffu, qpv, m);
            a0 += qm * sk[lane*33 + m];
            a1 += qm * sk[(lane+32)*33 + m];
        }
        float inv = 1.0f / d;
        size_t off = ((size_t)b*TQ + t) * EMB + h * ES;
        yh[off + lane]      = __float2half(a0 * inv);
        yh[off + lane + 32] = __float2half(a1 * inv);
    }
}

// ============== mma.sync fp16 GEMM (fp32 accum), 3-stage, ONE sync per chunk ==============
#define PLANE_BYTES 16384
#define BUF_BYTES (2*PLANE_BYTES)
#define GEMM_SMEM (3*BUF_BYTES)

#define SWZ_ADDR(base, row, chunk) \
    ((base) + (uint32_t)(row)*128u + (uint32_t)(((chunk) ^ ((row)&7)) << 4))

template<int EPI>
__global__ __launch_bounds__(256, 2)
void gemm_mma(const __half* __restrict__ Ah, const __half* __restrict__ Bh,
              const float* __restrict__ bias, const float* __restrict__ res,
              float* __restrict__ Cf, __half* __restrict__ Chi, int N, int K) {
    extern __shared__ char gsm[];
    uint32_t sb = smem_to_u32(gsm);
    int tid = threadIdx.x, lane = tid & 31, wid = tid >> 5;
    int rowBase = blockIdx.y * 128, colBase = blockIdx.x * 128;

    int wm = wid & 3, wn = wid >> 2;
    int m0 = wm * 32, n0 = wn * 64;

    float acc[2][8][4];
    #pragma unroll
    for (int i = 0; i < 2; i++)
        #pragma unroll
        for (int j = 0; j < 8; j++)
            #pragma unroll
            for (int q = 0; q < 4; q++) acc[i][j][q] = 0.f;

    int arow_l = (lane & 15);
    int acb    = (lane >> 4);
    int brow_l = (lane & 7) + ((lane >> 4) << 3);
    int bcb    = (lane >> 3) & 1;

    auto load_chunk = [&](int buf, int k0) {
        uint32_t sbase = sb + buf * BUF_BYTES;
        int row = tid >> 1, c0 = (tid & 1) * 4;
        size_t goA = (size_t)(rowBase + row) * K + k0 + c0 * 8;
        size_t goB = (size_t)(colBase + row) * K + k0 + c0 * 8;
        #pragma unroll
        for (int j = 0; j < 4; j++) {
            uint32_t so = SWZ_ADDR(sbase, row, c0 + j);
            cp_async16(so,               Ah + goA + j * 8);
            cp_async16(PLANE_BYTES + so, Bh + goB + j * 8);
        }
    };

    int NC = K >> 6;
    load_chunk(0, 0);
    CP_COMMIT();
    load_chunk(1, 64);
    CP_COMMIT();

    int bufc = 0, bufn = 2;
    for (int c = 0; c < NC; c++) {
        if (c + 1 < NC) { CP_WAIT1(); } else { CP_WAIT0(); }
        __syncthreads();
        if (c + 2 < NC) {
            load_chunk(bufn, (c + 2) << 6);
            CP_COMMIT();
        }

        uint32_t pA = sb + bufc * BUF_BYTES;
        #pragma unroll
        for (int ks = 0; ks < 4; ks++) {
            uint32_t ah[2][4];
            #pragma unroll
            for (int mt = 0; mt < 2; mt++) {
                int ar = m0 + mt * 16 + arow_l;
                uint32_t ad = SWZ_ADDR(pA, ar, ks * 2 + acb);
                ldsm_x4(ah[mt][0], ah[mt][1], ah[mt][2], ah[mt][3], ad);
            }
            #pragma unroll
            for (int ng = 0; ng < 4; ng++) {
                int br = n0 + ng * 16 + brow_l;
                uint32_t bd = SWZ_ADDR(pA + PLANE_BYTES, br, ks * 2 + bcb);
                uint32_t bh2[2][2];
                ldsm_x4(bh2[0][0], bh2[0][1], bh2[1][0], bh2[1][1], bd);
                #pragma unroll
                for (int mt = 0; mt < 2; mt++)
                    #pragma unroll
                    for (int j = 0; j < 2; j++)
                        mma_f16(acc[mt][2*ng + j], ah[mt], bh2[j]);
            }
        }
        bufc = (bufc + 1 == 3) ? 0 : bufc + 1;
        bufn = (bufn + 1 == 3) ? 0 : bufn + 1;
    }

    int rbase = rowBase + m0 + (lane >> 2);
    int cbase = colBase + n0 + (lane & 3) * 2;
    #pragma unroll
    for (int mt = 0; mt < 2; mt++) {
        #pragma unroll
        for (int half = 0; half < 2; half++) {
            int row = rbase + mt * 16 + half * 8;
            if (EPI == 0) {
                float* crow = Cf + (size_t)row * N;
                const float* rrow = res + (size_t)row * N;
                #pragma unroll
                for (int nt = 0; nt < 8; nt++) {
                    int col = cbase + nt * 8;
                    float2 o;
                    o.x = acc[mt][nt][half*2+0] + bias[col]   + rrow[col];
                    o.y = acc[mt][nt][half*2+1] + bias[col+1] + rrow[col+1];
                    *(float2*)(crow + col) = o;
                }
            } else {
                __half* hrow = Chi + (size_t)row * N;
                #pragma unroll
                for (int nt = 0; nt < 8; nt++) {
                    int col = cbase + nt * 8;
                    float v0 = acc[mt][nt][half*2+0] + bias[col];
                    float v1 = acc[mt][nt][half*2+1] + bias[col+1];
                    v0 = 0.5f * v0 * (1.0f + erff(v0 * 0.70710678118654752f));
                    v1 = 0.5f * v1 * (1.0f + erff(v1 * 0.70710678118654752f));
                    __half hh[2] = {__float2half(v0), __float2half(v1)};
                    *(uint32_t*)(hrow + col) = *(uint32_t*)hh;
                }
            }
        }
    }
}

// ---------------- launch ----------------
extern "C" void kernel_launch(void* const* d_in, const int* in_sizes, int n_in,
                              void* d_out, int out_size) {
    const float* x      = (const float*)d_in[0];
    const float* wrf    = (const float*)d_in[1];
    const float* kqv_w  = (const float*)d_in[2];
    const float* kqv_b  = (const float*)d_in[3];
    const float* proj_w = (const float*)d_in[4];
    const float* proj_b = (const float*)d_in[5];
    const float* ln1_g  = (const float*)d_in[6];
    const float* ln1_b  = (const float*)d_in[7];
    const float* ln2_g  = (const float*)d_in[8];
    const float* ln2_b  = (const float*)d_in[9];
    const float* mlp_w1 = (const float*)d_in[10];
    const float* mlp_b1 = (const float*)d_in[11];
    const float* mlp_w2 = (const float*)d_in[12];
    const float* mlp_b2 = (const float*)d_in[13];
    float* out = (float*)d_out;

    float *p_v, *p_qp, *p_kp, *p_pk, *p_ps, *p_kptv, *p_ksum, *p_x1;
    __half *p_h2h, *p_yh, *p_hidh, *p_pwh, *p_w1h, *p_w2h, *p_kwh;
    cudaGetSymbolAddress((void**)&p_v,    g_v);
    cudaGetSymbolAddress((void**)&p_qp,   g_qp);
    cudaGetSymbolAddress((void**)&p_kp,   g_kp);
    cudaGetSymbolAddress((void**)&p_pk,   g_kptv_part);
    cudaGetSymbolAddress((void**)&p_ps,   g_ksum_part);
    cudaGetSymbolAddress((void**)&p_kptv, g_kptv);
    cudaGetSymbolAddress((void**)&p_ksum, g_ksum);
    cudaGetSymbolAddress((void**)&p_x1,   g_x1);
    cudaGetSymbolAddress((void**)&p_h2h,  g_h2h);
    cudaGetSymbolAddress((void**)&p_yh,   g_yh);
    cudaGetSymbolAddress((void**)&p_hidh, g_hidh);
    cudaGetSymbolAddress((void**)&p_pwh,  g_pwh);
    cudaGetSymbolAddress((void**)&p_w1h,  g_w1h);
    cudaGetSymbolAddress((void**)&p_w2h,  g_w2h);
    cudaGetSymbolAddress((void**)&p_kwh,  g_kwh);

    const size_t k1_smem = (size_t)K1_SMEM_FLOATS * sizeof(float);   // 83968B
    cudaFuncSetAttribute(kqv_prm_kernel, cudaFuncAttributeMaxDynamicSharedMemorySize,
                         (int)k1_smem);
    cudaFuncSetAttribute(gemm_mma<0>, cudaFuncAttributeMaxDynamicSharedMemorySize, GEMM_SMEM);
    cudaFuncSetAttribute(gemm_mma<1>, cudaFuncAttributeMaxDynamicSharedMemorySize, GEMM_SMEM);

    // 0. all weight fp16 rounds (one launch)
    cvt_all_kernel<<<(CVT_N4 + 255)/256, 256>>>(proj_w, mlp_w1, mlp_w2, kqv_w,
                                                p_pwh, p_w1h, p_w2h, p_kwh);
    // 1. fused LN1 + tensor kqv + prm_exp
    kqv_prm_kernel<<<NTOK/8, 256, k1_smem>>>(x, ln1_g, ln1_b, p_kwh, kqv_b, wrf,
                                             p_v, p_kp, p_qp);
    // 2-3. kptv/ksum reduction over T
    kpt_kernel<<<dim3(16, 64), 256>>>(p_v, p_kp, p_pk, p_ps);
    reduce_kernel<<<513, 256>>>(p_pk, p_ps, p_kptv, p_ksum);
    // 4. y (fp16)
    y_kernel<<<dim3(TQ/256, 64), 256>>>(p_qp, p_kptv, p_ksum, p_yh);
    // 5. attn proj + residual -> x1 (fp32)
    gemm_mma<0><<<dim3(EMB/128, NTOK/128), 256, GEMM_SMEM>>>(
        p_yh, p_pwh, proj_b, x, p_x1, nullptr, EMB, EMB);
    // 6. LN2 -> fp16
    ln2_kernel<<<NTOK/8, 256>>>(p_x1, ln2_g, ln2_b, p_h2h);
    // 7. mlp1 + gelu -> hid (fp16)
    gemm_mma<1><<<dim3(HID/128, NTOK/128), 256, GEMM_SMEM>>>(
        p_h2h, p_w1h, mlp_b1, nullptr, nullptr, p_hidh, HID, EMB);
    // 8. mlp2 + residual -> out (fp32)
    gemm_mma<0><<<dim3(EMB/128, NTOK/128), 256, GEMM_SMEM>>>(
        p_hidh, p_w2h, mlp_b2, p_x1, out, nullptr, EMB, HID);
}

// round 12
// speedup vs baseline: 1.2173x; 1.0140x over previous
#include <cuda_runtime.h>
#include <cuda_fp16.h>
#include <math.h>
#include <stdint.h>

// Problem constants
#define BQ 8
#define TQ 4096
#define NTOK (BQ*TQ)          // 32768 tokens
#define EMB 512
#define HEADS 8
#define ES 64
#define MF 32                 // random features
#define HID (4*EMB)           // 2048
#define LN_EPS 1e-5f

__device__ __forceinline__ uint32_t smem_to_u32(const void* smem_ptr) {
    uint32_t addr;
    asm("{ .reg .u64 tmp; cvta.to.shared.u64 tmp, %1; cvt.u32.u64 %0, tmp; }"
        : "=r"(addr) : "l"(smem_ptr));
    return addr;
}

__device__ __forceinline__ void cp_async16(uint32_t saddr, const void* gaddr) {
    asm volatile("cp.async.cg.shared.global [%0], [%1], 16;" :: "r"(saddr), "l"(gaddr));
}
#define CP_COMMIT() asm volatile("cp.async.commit_group;" ::: "memory")
#define CP_WAIT0()  asm volatile("cp.async.wait_group 0;" ::: "memory")
#define CP_WAIT1()  asm volatile("cp.async.wait_group 1;" ::: "memory")

__device__ __forceinline__ void ldsm_x4(uint32_t& r0, uint32_t& r1, uint32_t& r2, uint32_t& r3,
                                        uint32_t addr) {
    asm volatile("ldmatrix.sync.aligned.m8n8.x4.shared.b16 {%0,%1,%2,%3}, [%4];"
        : "=r"(r0), "=r"(r1), "=r"(r2), "=r"(r3) : "r"(addr));
}

__device__ __forceinline__ void mma_f16(float* c, const uint32_t* a, const uint32_t* b) {
    asm volatile(
        "mma.sync.aligned.m16n8k16.row.col.f32.f16.f16.f32 "
        "{%0,%1,%2,%3}, {%4,%5,%6,%7}, {%8,%9}, {%0,%1,%2,%3};"
        : "+f"(c[0]), "+f"(c[1]), "+f"(c[2]), "+f"(c[3])
        : "r"(a[0]), "r"(a[1]), "r"(a[2]), "r"(a[3]), "r"(b[0]), "r"(b[1]));
}

// -------- scratch (device globals; no runtime allocation) --------
__device__ __align__(16) __half g_vh[(size_t)NTOK*HEADS*ES];   // v fp16
__device__ float g_qp[(size_t)NTOK*HEADS*MF];
__device__ float g_kp[(size_t)NTOK*HEADS*MF];
__device__ float g_kptv_part[16*64*ES*MF];
__device__ float g_ksum_part[16*64*MF];
__device__ float g_kptv[64*ES*MF];
__device__ float g_ksum[64*MF];
__device__ float g_x1[(size_t)NTOK*EMB];
__device__ __align__(16) __half g_h2h[(size_t)NTOK*EMB];
__device__ __align__(16) __half g_yh[(size_t)NTOK*EMB];
__device__ __align__(16) __half g_hidh[(size_t)NTOK*HID];
__device__ __align__(16) __half g_pwh[EMB*EMB];
__device__ __align__(16) __half g_w1h[HID*EMB];
__device__ __align__(16) __half g_w2h[EMB*HID];
__device__ __align__(16) __half g_kwh[192*64];   // kqv_w fp16

// ---------------- fused weight fp16 conversion (all 4 weights) ----------------
#define CVT_N4 (65536 + 262144 + 262144 + 3072)
__global__ void cvt_all_kernel(const float* __restrict__ pw, const float* __restrict__ w1,
                               const float* __restrict__ w2, const float* __restrict__ kw,
                               __half* __restrict__ pwh, __half* __restrict__ w1h,
                               __half* __restrict__ w2h, __half* __restrict__ kwh) {
    int i = blockIdx.x * 256 + threadIdx.x;
    if (i >= CVT_N4) return;
    const float* src;
    __half* dst;
    int j;
    if (i < 65536)       { src = pw; dst = pwh; j = i; }
    else if (i < 327680) { src = w1; dst = w1h; j = i - 65536; }
    else if (i < 589824) { src = w2; dst = w2h; j = i - 327680; }
    else                 { src = kw; dst = kwh; j = i - 589824; }
    float4 v = ((const float4*)src)[j];
    __half h[4];
    h[0] = __float2half(v.x); h[1] = __float2half(v.y);
    h[2] = __float2half(v.z); h[3] = __float2half(v.w);
    *(uint2*)(dst + (size_t)j*4) = *(uint2*)h;
}

// ---------------- LayerNorm (LN2): warp per token, fp16 out ----------------
__global__ void ln2_kernel(const float* __restrict__ x, const float* __restrict__ g,
                           const float* __restrict__ b, __half* __restrict__ ohi) {
    int tok  = blockIdx.x * 8 + (threadIdx.x >> 5);
    int lane = threadIdx.x & 31;
    const float4* xr = (const float4*)(x + (size_t)tok * EMB);
    float4 v[4];
    float s = 0.f, sq = 0.f;
    #pragma unroll
    for (int i = 0; i < 4; i++) {
        v[i] = xr[lane + 32*i];
        s  += v[i].x + v[i].y + v[i].z + v[i].w;
        sq += v[i].x*v[i].x + v[i].y*v[i].y + v[i].z*v[i].z + v[i].w*v[i].w;
    }
    #pragma unroll
    for (int o = 16; o; o >>= 1) {
        s  += __shfl_xor_sync(0xffffffffu, s,  o);
        sq += __shfl_xor_sync(0xffffffffu, sq, o);
    }
    float mean = s * (1.0f/EMB);
    float var  = sq * (1.0f/EMB) - mean*mean;
    float rstd = rsqrtf(var + LN_EPS);
    const float4* g4 = (const float4*)g;
    const float4* b4 = (const float4*)b;
    #pragma unroll
    for (int i = 0; i < 4; i++) {
        float4 gg = g4[lane + 32*i], bb = b4[lane + 32*i];
        size_t idx = (size_t)tok * EMB + (size_t)(lane + 32*i) * 4;
        __half h[4];
        h[0] = __float2half((v[i].x - mean) * rstd * gg.x + bb.x);
        h[1] = __float2half((v[i].y - mean) * rstd * gg.y + bb.y);
        h[2] = __float2half((v[i].z - mean) * rstd * gg.z + bb.z);
        h[3] = __float2half((v[i].w - mean) * rstd * gg.w + bb.w);
        *(uint2*)(ohi + idx) = *(uint2*)h;
    }
}

// ======== fused LN1 + tensor-core kqv + prm_exp (8 tok/block, 4 heads/pass) ========
#define SKQ_STRIDE 200
#define W16_OFF 16384
#define AHI_OFF 40960
#define ALO_OFF 45056
#define K1_SMEM_FLOATS 20992
__global__ void kqv_prm_kernel(const float* __restrict__ xg, const float* __restrict__ ln1_g,
                               const float* __restrict__ ln1_b,
                               const __half* __restrict__ kwh,
                               const float* __restrict__ kqv_b, const float* __restrict__ wrf,
                               __half* __restrict__ gvh, float* __restrict__ gkp,
                               float* __restrict__ gqp) {
    extern __shared__ float sm[];
    char* smc = (char*)sm;
    uint32_t sb = smem_to_u32(sm);
    float* sh_h  = sm;                    // [8 tok][512]
    float* wr_t  = sm + 12288;            // [64 e][32 m]
    float* sbias = wr_t + 2048;           // [192]
    float* skqv4 = sbias + 192;           // [4 hd][8 tok][SKQ_STRIDE]
    float* sxd4  = skqv4 + 6400;          // [4 hd][16]
    int tid = threadIdx.x, lane = tid & 31, wid = tid >> 5;
    size_t t0 = (size_t)blockIdx.x * 8;

    // ---- kqv_w fp16 -> smem via cp.async (192 rows x 128B, swizzled) ----
    #pragma unroll
    for (int i = 0; i < 6; i++) {
        int idx = tid + 256*i;
        int row = idx >> 3, c = idx & 7;
        cp_async16(sb + W16_OFF + (uint32_t)row*128 + (uint32_t)((c ^ (row & 7)) << 4),
                   kwh + row*64 + c*8);
    }
    CP_COMMIT();

    // ---- fused LN1: warp per token -> sh_h (fp32) ----
    {
        int tok = tid >> 5;
        const float4* xr = (const float4*)(xg + (t0 + tok) * EMB);
        float4 v[4];
        float s = 0.f, sq = 0.f;
        #pragma unroll
        for (int i = 0; i < 4; i++) {
            v[i] = xr[lane + 32*i];
            s  += v[i].x + v[i].y + v[i].z + v[i].w;
            sq += v[i].x*v[i].x + v[i].y*v[i].y + v[i].z*v[i].z + v[i].w*v[i].w;
        }
        #pragma unroll
        for (int o = 16; o; o >>= 1) {
            s  += __shfl_xor_sync(0xffffffffu, s,  o);
            sq += __shfl_xor_sync(0xffffffffu, sq, o);
        }
        float mean = s * (1.0f/EMB);
        float var  = sq * (1.0f/EMB) - mean*mean;
        float rstd = rsqrtf(var + LN_EPS);
        const float4* g4 = (const float4*)ln1_g;
        const float4* b4 = (const float4*)ln1_b;
        float4* hrow = (float4*)(sh_h + tok * 512);
        #pragma unroll
        for (int i = 0; i < 4; i++) {
            float4 gg = g4[lane + 32*i], bb = b4[lane + 32*i];
            float4 o;
            o.x = (v[i].x - mean) * rstd * gg.x + bb.x;
            o.y = (v[i].y - mean) * rstd * gg.y + bb.y;
            o.z = (v[i].z - mean) * rstd * gg.z + bb.z;
            o.w = (v[i].w - mean) * rstd * gg.w + bb.w;
            hrow[lane + 32*i] = o;
        }
    }
    // ---- wr_t [64 e][32 m] + bias ----
    #pragma unroll
    for (int i = 0; i < 2; i++) {
        int j = tid + 256*i;
        int m = j >> 4, e0 = (j & 15) << 2;
        float4 w4 = ((const float4*)wrf)[j];
        wr_t[(e0+0)*32 + m] = w4.x;
        wr_t[(e0+1)*32 + m] = w4.y;
        wr_t[(e0+2)*32 + m] = w4.z;
        wr_t[(e0+3)*32 + m] = w4.w;
    }
    if (tid < 192) sbias[tid] = kqv_b[tid];
    CP_WAIT0();
    __syncthreads();

    int wm = wid & 1, wn = wid >> 1;
    int m0 = wm * 16, n0 = wn * 48;
    int arow = m0 + (lane & 15), acb = lane >> 4;
    int brow_l = (lane & 7) + ((lane >> 4) << 3), bcb = (lane >> 3) & 1;

    for (int hg = 0; hg < 2; hg++) {
        // ---- convert A (32 rows x 64 e) to hi/lo fp16, swizzled ----
        {
            int r = tid >> 3, c = tid & 7;
            int hd4 = r >> 3, tok = r & 7;
            const float* hp = sh_h + tok*512 + (hg*4 + hd4)*64 + c*8;
            float4 f0 = *(const float4*)hp;
            float4 f1 = *(const float4*)(hp + 4);
            float vv[8] = {f0.x,f0.y,f0.z,f0.w,f1.x,f1.y,f1.z,f1.w};
            __half hi[8], lo[8];
            #pragma unroll
            for (int q = 0; q < 8; q++) {
                hi[q] = __float2half(vv[q]);
                lo[q] = __float2half(vv[q] - __half2float(hi[q]));
            }
            uint32_t off = (uint32_t)r*128 + (uint32_t)((c ^ (r & 7)) << 4);
            *(uint4*)(smc + AHI_OFF + off) = *(uint4*)hi;
            *(uint4*)(smc + ALO_OFF + off) = *(uint4*)lo;
        }
        __syncthreads();

        // ---- MMA: 2-term (hi+lo) x W16 ----
        float acc[6][4];
        #pragma unroll
        for (int nf = 0; nf < 6; nf++)
            #pragma unroll
            for (int q = 0; q < 4; q++) acc[nf][q] = 0.f;
        #pragma unroll
        for (int ks = 0; ks < 4; ks++) {
            uint32_t aoff = (uint32_t)arow*128 +
                            (uint32_t)((((ks*2 + acb)) ^ (arow & 7)) << 4);
            uint32_t ah[4], al[4];
            ldsm_x4(ah[0], ah[1], ah[2], ah[3], sb + AHI_OFF + aoff);
            ldsm_x4(al[0], al[1], al[2], al[3], sb + ALO_OFF + aoff);
            #pragma unroll
            for (int ng = 0; ng < 3; ng++) {
                int br = n0 + ng*16 + brow_l;
                uint32_t boff = (uint32_t)br*128 +
                                (uint32_t)(((ks*2 + bcb) ^ (br & 7)) << 4);
                uint32_t b2[2][2];
                ldsm_x4(b2[0][0], b2[0][1], b2[1][0], b2[1][1], sb + W16_OFF + boff);
                #pragma unroll
                for (int j = 0; j < 2; j++) {
                    mma_f16(acc[2*ng + j], ah, b2[j]);
                    mma_f16(acc[2*ng + j], al, b2[j]);
                }
            }
        }
        // ---- epilogue: acc + bias -> skqv4 ----
        {
            int rb = m0 + (lane >> 2);
            int cb = n0 + (lane & 3) * 2;
            #pragma unroll
            for (int half = 0; half < 2; half++) {
                int r = rb + half*8;
                int hd4 = r >> 3, tok = r & 7;
                float* row = skqv4 + hd4*8*SKQ_STRIDE + tok*SKQ_STRIDE;
                #pragma unroll
                for (int nf = 0; nf < 6; nf++) {
                    int col = cb + nf*8;
                    row[col]   = acc[nf][half*2+0] + sbias[col];
                    row[col+1] = acc[nf][half*2+1] + sbias[col+1];
                }
            }
        }
        __syncthreads();

        // ---- v write: 1024 half2 pairs ----
        #pragma unroll
        for (int i = 0; i < 4; i++) {
            int idx = tid + 256*i;
            int hd4 = idx >> 8, tok = (idx >> 5) & 7, e2 = idx & 31;
            const float* src = &skqv4[hd4*8*SKQ_STRIDE + tok*SKQ_STRIDE + 128 + e2*2];
            __half2 hv = __floats2half2_rn(src[0], src[1]);
            *(__half2*)&gvh[(((t0 + tok) * HEADS) + hg*4 + hd4) * ES + e2*2] = hv;
        }
        // ---- xd ----
        if (tid < 64) {
            int hd4 = tid >> 4, r = tid & 15, tok = r >> 1, which = r & 1;
            const float* z = skqv4 + hd4*8*SKQ_STRIDE + tok*SKQ_STRIDE + which*64;
            float s = 0.f;
            #pragma unroll 8
            for (int e = 0; e < 64; e++) { float zz = z[e]; s += zz*zz; }
            sxd4[hd4*16 + r] = 0.5f * s;
        }
        __syncthreads();

        // ---- wtx + exp ----
        #pragma unroll
        for (int i = 0; i < 2; i++) {
            int sidx = tid + 256*i;
            int mg = sidx & 7, which = (sidx >> 3) & 1, tok = (sidx >> 4) & 7, hd4 = sidx >> 7;
            int mq = mg * 4;
            const float* z = skqv4 + hd4*8*SKQ_STRIDE + tok*SKQ_STRIDE + which*64;
            float a0 = 0.f, a1 = 0.f, a2 = 0.f, a3 = 0.f;
            #pragma unroll 8
            for (int e = 0; e < 64; e++) {
                float zv = z[e];
                float4 w4 = *(const float4*)&wr_t[e*32 + mq];
                a0 += zv*w4.x; a1 += zv*w4.y; a2 += zv*w4.z; a3 += zv*w4.w;
            }
            float xdv = sxd4[hd4*16 + tok*2 + which];
            float4 o;
            o.x = expf(a0 - xdv) * 0.17677669529663689f;
            o.y = expf(a1 - xdv) * 0.17677669529663689f;
            o.z = expf(a2 - xdv) * 0.17677669529663689f;
            o.w = expf(a3 - xdv) * 0.17677669529663689f;
            float* dst = which ? gqp : gkp;
            *(float4*)&dst[(((t0 + tok) * HEADS) + hg*4 + hd4) * MF + mq] = o;
        }
        __syncthreads();
    }
}

// ------- kptv / ksum partial reduction over T: cp.async double-buffered -------
__global__ void kpt_kernel(const __half* __restrict__ gvh, const float* __restrict__ gkp,
                           float* __restrict__ part_kptv, float* __restrict__ part_ksum) {
    int chunk = blockIdx.x;
    int bh = blockIdx.y;
    int b = bh >> 3, h = bh & 7;
    __shared__ __half sv[2][16][64];      // 2 x 2048 B
    __shared__ float skp[2][16][32];      // 2 x 2048 B
    uint32_t sv_b = smem_to_u32(sv), skp_b = smem_to_u32(skp);
    int tid = threadIdx.x, lane = tid & 31, wid = tid >> 5;
    float acc[8] = {0,0,0,0,0,0,0,0};
    float ks = 0.f;
    int t0 = chunk * 256;

    auto load_stage = [&](int buf, int s0) {
        if (tid < 128) {
            int s = tid >> 3, c = tid & 7;
            cp_async16(sv_b + buf*2048 + s*128 + c*16,
                       gvh + (((size_t)b*TQ + s0 + s) * HEADS + h) * ES + c*8);
        } else {
            int r = tid - 128;
            int s = r >> 3, c = r & 7;
            cp_async16(skp_b + buf*2048 + s*128 + c*16,
                       gkp + (((size_t)b*TQ + s0 + s) * HEADS + h) * MF + c*4);
        }
    };

    load_stage(0, t0);
    CP_COMMIT();
    for (int st = 0; st < 16; st++) {
        CP_WAIT0();
        __syncthreads();
        if (st + 1 < 16) {
            load_stage((st + 1) & 1, t0 + (st + 1) * 16);
            CP_COMMIT();
        }
        int buf = st & 1;
        #pragma unroll
        for (int s = 0; s < 16; s++) {
            float kv = skp[buf][s][lane];
            uint4 vr = *(const uint4*)&sv[buf][s][wid*8];
            __half2* hp = (__half2*)&vr;
            float2 c0 = __half22float2(hp[0]);
            float2 c1 = __half22float2(hp[1]);
            float2 c2 = __half22float2(hp[2]);
            float2 c3 = __half22float2(hp[3]);
            acc[0] += c0.x*kv; acc[1] += c0.y*kv; acc[2] += c1.x*kv; acc[3] += c1.y*kv;
            acc[4] += c2.x*kv; acc[5] += c2.y*kv; acc[6] += c3.x*kv; acc[7] += c3.y*kv;
            if (wid == 0) ks += kv;
        }
    }
    size_t base = ((size_t)(chunk*64 + bh)) * (ES*MF);
    #pragma unroll
    for (int j = 0; j < 8; j++)
        part_kptv[base + (wid*8 + j)*MF + lane] = acc[j];
    if (wid == 0) part_ksum[(chunk*64 + bh)*MF + lane] = ks;
}

__global__ void reduce_kernel(const float* __restrict__ pk, const float* __restrict__ ps,
                              float* __restrict__ kptv, float* __restrict__ ksum) {
    int bid = blockIdx.x;
    if (bid < 512) {
        int idx = bid * 256 + threadIdx.x;
        int bh = idx >> 11;
        float s = 0.f;
        #pragma unroll
        for (int c = 0; c < 16; c++) s += pk[((size_t)(c*64 + bh)) * 2048 + (idx & 2047)];
        kptv[idx] = s;
    } else {
        #pragma unroll
        for (int j = 0; j < 8; j++) {
            int idx = threadIdx.x * 8 + j;
            int bh = idx >> 5, m = idx & 31;
            float s = 0.f;
            #pragma unroll
            for (int c = 0; c < 16; c++) s += ps[(c*64 + bh)*MF + m];
            ksum[idx] = s;
        }
    }
}

// ------- y = (qp . kptv) / D -> fp16: smem qp tile + precomputed 1/D, no shfl -------
__global__ void y_kernel(const float* __restrict__ gqp, const float* __restrict__ kptv,
                         const float* __restrict__ ksum, __half* __restrict__ yh) {
    int bh = blockIdx.y, b = bh >> 3, h = bh & 7;
    __shared__ float sk[64*33];
    __shared__ float sks[32];
    __shared__ float sqp[256*33];
    __shared__ float sdinv[256];
    int tid = threadIdx.x, lane = tid & 31, wid = tid >> 5;
    int tbase = blockIdx.x * 256;
    #pragma unroll
    for (int i = 0; i < 8; i++) {
        int idx = tid + 256*i;
        sk[(idx >> 5)*33 + (idx & 31)] = kptv[(size_t)bh*2048 + idx];
    }
    if (tid < 32) sks[tid] = ksum[bh*32 + tid];
    // qp tile: 256 tokens x 32 m, coalesced float4
    #pragma unroll
    for (int i = 0; i < 8; i++) {
        int idx = tid + 256*i;              // 2048 float4
        int t = idx >> 3, mq = (idx & 7) * 4;
        float4 q4 = *(const float4*)&gqp[(((size_t)b*TQ + tbase + t) * HEADS + h) * MF + mq];
        float* row = sqp + t*33 + mq;
        row[0] = q4.x; row[1] = q4.y; row[2] = q4.z; row[3] = q4.w;
    }
    __syncthreads();
    // per-token 1/D (conflict-free: (t*33+m)%32 distinct per lane)
    {
        float d = 0.f;
        const float* qrow = sqp + tid*33;
        #pragma unroll 8
        for (int m = 0; m < 32; m++) d += qrow[m] * sks[m];
        sdinv[tid] = 1.0f / d;
    }
    __syncthreads();
    for (int it = 0; it < 32; it++) {
        int tl = wid * 32 + it;
        const float* qrow = sqp + tl*33;    // broadcast reads
        float a0 = 0.f, a1 = 0.f;
        #pragma unroll 8
        for (int m = 0; m < 32; m++) {
            float qm = qrow[m];
            a0 += qm * sk[lane*33 + m];
            a1 += qm * sk[(lane+32)*33 + m];
        }
        float inv = sdinv[tl];
        size_t off = ((size_t)b*TQ + tbase + tl) * EMB + h * ES;
        yh[off + lane]      = __float2half(a0 * inv);
        yh[off + lane + 32] = __float2half(a1 * inv);
    }
}

// ============== mma.sync fp16 GEMM (fp32 accum), 3-stage, ONE sync per chunk ==============
#define PLANE_BYTES 16384
#define BUF_BYTES (2*PLANE_BYTES)
#define GEMM_SMEM (3*BUF_BYTES)

#define SWZ_ADDR(base, row, chunk) \
    ((base) + (uint32_t)(row)*128u + (uint32_t)(((chunk) ^ ((row)&7)) << 4))

template<int EPI>
__global__ __launch_bounds__(256, 2)
void gemm_mma(const __half* __restrict__ Ah, const __half* __restrict__ Bh,
              const float* __restrict__ bias, const float* __restrict__ res,
              float* __restrict__ Cf, __half* __restrict__ Chi, int N, int K) {
    extern __shared__ char gsm[];
    uint32_t sb = smem_to_u32(gsm);
    int tid = threadIdx.x, lane = tid & 31, wid = tid >> 5;
    int rowBase = blockIdx.y * 128, colBase = blockIdx.x * 128;

    int wm = wid & 3, wn = wid >> 2;
    int m0 = wm * 32, n0 = wn * 64;

    float acc[2][8][4];
    #pragma unroll
    for (int i = 0; i < 2; i++)
        #pragma unroll
        for (int j = 0; j < 8; j++)
            #pragma unroll
            for (int q = 0; q < 4; q++) acc[i][j][q] = 0.f;

    int arow_l = (lane & 15);
    int acb    = (lane >> 4);
    int brow_l = (lane & 7) + ((lane >> 4) << 3);
    int bcb    = (lane >> 3) & 1;

    auto load_chunk = [&](int buf, int k0) {
        uint32_t sbase = sb + buf * BUF_BYTES;
        int row = tid >> 1, c0 = (tid & 1) * 4;
        size_t goA = (size_t)(rowBase + row) * K + k0 + c0 * 8;
        size_t goB = (size_t)(colBase + row) * K + k0 + c0 * 8;
        #pragma unroll
        for (int j = 0; j < 4; j++) {
            uint32_t so = SWZ_ADDR(sbase, row, c0 + j);
            cp_async16(so,               Ah + goA + j * 8);
            cp_async16(PLANE_BYTES + so, Bh + goB + j * 8);
        }
    };

    int NC = K >> 6;
    load_chunk(0, 0);
    CP_COMMIT();
    load_chunk(1, 64);
    CP_COMMIT();

    int bufc = 0, bufn = 2;
    for (int c = 0; c < NC; c++) {
        if (c + 1 < NC) { CP_WAIT1(); } else { CP_WAIT0(); }
        __syncthreads();
        if (c + 2 < NC) {
            load_chunk(bufn, (c + 2) << 6);
            CP_COMMIT();
        }

        uint32_t pA = sb + bufc * BUF_BYTES;
        #pragma unroll
        for (int ks = 0; ks < 4; ks++) {
            uint32_t ah[2][4];
            #pragma unroll
            for (int mt = 0; mt < 2; mt++) {
                int ar = m0 + mt * 16 + arow_l;
                uint32_t ad = SWZ_ADDR(pA, ar, ks * 2 + acb);
                ldsm_x4(ah[mt][0], ah[mt][1], ah[mt][2], ah[mt][3], ad);
            }
            #pragma unroll
            for (int ng = 0; ng < 4; ng++) {
                int br = n0 + ng * 16 + brow_l;
                uint32_t bd = SWZ_ADDR(pA + PLANE_BYTES, br, ks * 2 + bcb);
                uint32_t bh2[2][2];
                ldsm_x4(bh2[0][0], bh2[0][1], bh2[1][0], bh2[1][1], bd);
                #pragma unroll
                for (int mt = 0; mt < 2; mt++)
                    #pragma unroll
                    for (int j = 0; j < 2; j++)
                        mma_f16(acc[mt][2*ng + j], ah[mt], bh2[j]);
            }
        }
        bufc = (bufc + 1 == 3) ? 0 : bufc + 1;
        bufn = (bufn + 1 == 3) ? 0 : bufn + 1;
    }

    int rbase = rowBase + m0 + (lane >> 2);
    int cbase = colBase + n0 + (lane & 3) * 2;
    #pragma unroll
    for (int mt = 0; mt < 2; mt++) {
        #pragma unroll
        for (int half = 0; half < 2; half++) {
            int row = rbase + mt * 16 + half * 8;
            if (EPI == 0) {
                float* crow = Cf + (size_t)row * N;
                const float* rrow = res + (size_t)row * N;
                #pragma unroll
                for (int nt = 0; nt < 8; nt++) {
                    int col = cbase + nt * 8;
                    float2 o;
                    o.x = acc[mt][nt][half*2+0] + bias[col]   + rrow[col];
                    o.y = acc[mt][nt][half*2+1] + bias[col+1] + rrow[col+1];
                    *(float2*)(crow + col) = o;
                }
            } else {
                __half* hrow = Chi + (size_t)row * N;
                #pragma unroll
                for (int nt = 0; nt < 8; nt++) {
                    int col = cbase + nt * 8;
                    float v0 = acc[mt][nt][half*2+0] + bias[col];
                    float v1 = acc[mt][nt][half*2+1] + bias[col+1];
                    v0 = 0.5f * v0 * (1.0f + erff(v0 * 0.70710678118654752f));
                    v1 = 0.5f * v1 * (1.0f + erff(v1 * 0.70710678118654752f));
                    __half hh[2] = {__float2half(v0), __float2half(v1)};
                    *(uint32_t*)(hrow + col) = *(uint32_t*)hh;
                }
            }
        }
    }
}

// ---------------- launch ----------------
extern "C" void kernel_launch(void* const* d_in, const int* in_sizes, int n_in,
                              void* d_out, int out_size) {
    const float* x      = (const float*)d_in[0];
    const float* wrf    = (const float*)d_in[1];
    const float* kqv_w  = (const float*)d_in[2];
    const float* kqv_b  = (const float*)d_in[3];
    const float* proj_w = (const float*)d_in[4];
    const float* proj_b = (const float*)d_in[5];
    const float* ln1_g  = (const float*)d_in[6];
    const float* ln1_b  = (const float*)d_in[7];
    const float* ln2_g  = (const float*)d_in[8];
    const float* ln2_b  = (const float*)d_in[9];
    const float* mlp_w1 = (const float*)d_in[10];
    const float* mlp_b1 = (const float*)d_in[11];
    const float* mlp_w2 = (const float*)d_in[12];
    const float* mlp_b2 = (const float*)d_in[13];
    float* out = (float*)d_out;

    float *p_qp, *p_kp, *p_pk, *p_ps, *p_kptv, *p_ksum, *p_x1;
    __half *p_vh, *p_h2h, *p_yh, *p_hidh, *p_pwh, *p_w1h, *p_w2h, *p_kwh;
    cudaGetSymbolAddress((void**)&p_vh,   g_vh);
    cudaGetSymbolAddress((void**)&p_qp,   g_qp);
    cudaGetSymbolAddress((void**)&p_kp,   g_kp);
    cudaGetSymbolAddress((void**)&p_pk,   g_kptv_part);
    cudaGetSymbolAddress((void**)&p_ps,   g_ksum_part);
    cudaGetSymbolAddress((void**)&p_kptv, g_kptv);
    cudaGetSymbolAddress((void**)&p_ksum, g_ksum);
    cudaGetSymbolAddress((void**)&p_x1,   g_x1);
    cudaGetSymbolAddress((void**)&p_h2h,  g_h2h);
    cudaGetSymbolAddress((void**)&p_yh,   g_yh);
    cudaGetSymbolAddress((void**)&p_hidh, g_hidh);
    cudaGetSymbolAddress((void**)&p_pwh,  g_pwh);
    cudaGetSymbolAddress((void**)&p_w1h,  g_w1h);
    cudaGetSymbolAddress((void**)&p_w2h,  g_w2h);
    cudaGetSymbolAddress((void**)&p_kwh,  g_kwh);

    const size_t k1_smem = (size_t)K1_SMEM_FLOATS * sizeof(float);   // 83968B
    cudaFuncSetAttribute(kqv_prm_kernel, cudaFuncAttributeMaxDynamicSharedMemorySize,
                         (int)k1_smem);
    cudaFuncSetAttribute(gemm_mma<0>, cudaFuncAttributeMaxDynamicSharedMemorySize, GEMM_SMEM);
    cudaFuncSetAttribute(gemm_mma<1>, cudaFuncAttributeMaxDynamicSharedMemorySize, GEMM_SMEM);

    // 0. all weight fp16 rounds (one launch)
    cvt_all_kernel<<<(CVT_N4 + 255)/256, 256>>>(proj_w, mlp_w1, mlp_w2, kqv_w,
                                                p_pwh, p_w1h, p_w2h, p_kwh);
    // 1. fused LN1 + tensor kqv + prm_exp (v -> fp16)
    kqv_prm_kernel<<<NTOK/8, 256, k1_smem>>>(x, ln1_g, ln1_b, p_kwh, kqv_b, wrf,
                                             p_vh, p_kp, p_qp);
    // 2-3. kptv/ksum reduction over T (cp.async double-buffered)
    kpt_kernel<<<dim3(16, 64), 256>>>(p_vh, p_kp, p_pk, p_ps);
    reduce_kernel<<<513, 256>>>(p_pk, p_ps, p_kptv, p_ksum);
    // 4. y (smem qp + 1/D precompute)
    y_kernel<<<dim3(TQ/256, 64), 256>>>(p_qp, p_kptv, p_ksum, p_yh);
    // 5. attn proj + residual -> x1 (fp32)
    gemm_mma<0><<<dim3(EMB/128, NTOK/128), 256, GEMM_SMEM>>>(
        p_yh, p_pwh, proj_b, x, p_x1, nullptr, EMB, EMB);
    // 6. LN2 -> fp16
    ln2_kernel<<<NTOK/8, 256>>>(p_x1, ln2_g, ln2_b, p_h2h);
    // 7. mlp1 + gelu -> hid (fp16)
    gemm_mma<1><<<dim3(HID/128, NTOK/128), 256, GEMM_SMEM>>>(
        p_h2h, p_w1h, mlp_b1, nullptr, nullptr, p_hidh, HID, EMB);
    // 8. mlp2 + residual -> out (fp32)
    gemm_mma<0><<<dim3(EMB/128, NTOK/128), 256, GEMM_SMEM>>>(
        p_hidh, p_w2h, mlp_b2, p_x1, out, nullptr, EMB, HID);
}

// round 13
// speedup vs baseline: 1.2321x; 1.0122x over previous
#include <cuda_runtime.h>
#include <cuda_fp16.h>
#include <math.h>
#include <stdint.h>

// Problem constants
#define BQ 8
#define TQ 4096
#define NTOK (BQ*TQ)          // 32768 tokens
#define EMB 512
#define HEADS 8
#define ES 64
#define MF 32                 // random features
#define HID (4*EMB)           // 2048
#define LN_EPS 1e-5f

__device__ __forceinline__ uint32_t smem_to_u32(const void* smem_ptr) {
    uint32_t addr;
    asm("{ .reg .u64 tmp; cvta.to.shared.u64 tmp, %1; cvt.u32.u64 %0, tmp; }"
        : "=r"(addr) : "l"(smem_ptr));
    return addr;
}

__device__ __forceinline__ void cp_async16(uint32_t saddr, const void* gaddr) {
    asm volatile("cp.async.cg.shared.global [%0], [%1], 16;" :: "r"(saddr), "l"(gaddr));
}
#define CP_COMMIT() asm volatile("cp.async.commit_group;" ::: "memory")
#define CP_WAIT0()  asm volatile("cp.async.wait_group 0;" ::: "memory")
#define CP_WAIT1()  asm volatile("cp.async.wait_group 1;" ::: "memory")

__device__ __forceinline__ void ldsm_x4(uint32_t& r0, uint32_t& r1, uint32_t& r2, uint32_t& r3,
                                        uint32_t addr) {
    asm volatile("ldmatrix.sync.aligned.m8n8.x4.shared.b16 {%0,%1,%2,%3}, [%4];"
        : "=r"(r0), "=r"(r1), "=r"(r2), "=r"(r3) : "r"(addr));
}

__device__ __forceinline__ void mma_f16(float* c, const uint32_t* a, const uint32_t* b) {
    asm volatile(
        "mma.sync.aligned.m16n8k16.row.col.f32.f16.f16.f32 "
        "{%0,%1,%2,%3}, {%4,%5,%6,%7}, {%8,%9}, {%0,%1,%2,%3};"
        : "+f"(c[0]), "+f"(c[1]), "+f"(c[2]), "+f"(c[3])
        : "r"(a[0]), "r"(a[1]), "r"(a[2]), "r"(a[3]), "r"(b[0]), "r"(b[1]));
}

// -------- scratch (device globals; no runtime allocation) --------
__device__ __align__(16) __half g_vh[(size_t)NTOK*HEADS*ES];   // v fp16
__device__ float g_qp[(size_t)NTOK*HEADS*MF];
__device__ float g_kp[(size_t)NTOK*HEADS*MF];
__device__ float g_kptv_part[16*64*ES*MF];
__device__ float g_ksum_part[16*64*MF];
__device__ float g_kptv[64*ES*MF];
__device__ float g_ksum[64*MF];
__device__ float g_x1[(size_t)NTOK*EMB];
__device__ __align__(16) __half g_h2h[(size_t)NTOK*EMB];
__device__ __align__(16) __half g_yh[(size_t)NTOK*EMB];
__device__ __align__(16) __half g_hidh[(size_t)NTOK*HID];
__device__ __align__(16) __half g_pwh[EMB*EMB];
__device__ __align__(16) __half g_w1h[HID*EMB];
__device__ __align__(16) __half g_w2h[EMB*HID];
__device__ __align__(16) __half g_kwh[192*64];   // kqv_w fp16

// ---------------- fused weight fp16 conversion (all 4 weights) ----------------
#define CVT_N4 (65536 + 262144 + 262144 + 3072)
__global__ void cvt_all_kernel(const float* __restrict__ pw, const float* __restrict__ w1,
                               const float* __restrict__ w2, const float* __restrict__ kw,
                               __half* __restrict__ pwh, __half* __restrict__ w1h,
                               __half* __restrict__ w2h, __half* __restrict__ kwh) {
    int i = blockIdx.x * 256 + threadIdx.x;
    if (i >= CVT_N4) return;
    const float* src;
    __half* dst;
    int j;
    if (i < 65536)       { src = pw; dst = pwh; j = i; }
    else if (i < 327680) { src = w1; dst = w1h; j = i - 65536; }
    else if (i < 589824) { src = w2; dst = w2h; j = i - 327680; }
    else                 { src = kw; dst = kwh; j = i - 589824; }
    float4 v = ((const float4*)src)[j];
    __half h[4];
    h[0] = __float2half(v.x); h[1] = __float2half(v.y);
    h[2] = __float2half(v.z); h[3] = __float2half(v.w);
    *(uint2*)(dst + (size_t)j*4) = *(uint2*)h;
}

// ---------------- LayerNorm (LN2): warp per token, fp16 out ----------------
__global__ void ln2_kernel(const float* __restrict__ x, const float* __restrict__ g,
                           const float* __restrict__ b, __half* __restrict__ ohi) {
    int tok  = blockIdx.x * 8 + (threadIdx.x >> 5);
    int lane = threadIdx.x & 31;
    const float4* xr = (const float4*)(x + (size_t)tok * EMB);
    float4 v[4];
    float s = 0.f, sq = 0.f;
    #pragma unroll
    for (int i = 0; i < 4; i++) {
        v[i] = xr[lane + 32*i];
        s  += v[i].x + v[i].y + v[i].z + v[i].w;
        sq += v[i].x*v[i].x + v[i].y*v[i].y + v[i].z*v[i].z + v[i].w*v[i].w;
    }
    #pragma unroll
    for (int o = 16; o; o >>= 1) {
        s  += __shfl_xor_sync(0xffffffffu, s,  o);
        sq += __shfl_xor_sync(0xffffffffu, sq, o);
    }
    float mean = s * (1.0f/EMB);
    float var  = sq * (1.0f/EMB) - mean*mean;
    float rstd = rsqrtf(var + LN_EPS);
    const float4* g4 = (const float4*)g;
    const float4* b4 = (const float4*)b;
    #pragma unroll
    for (int i = 0; i < 4; i++) {
        float4 gg = g4[lane + 32*i], bb = b4[lane + 32*i];
        size_t idx = (size_t)tok * EMB + (size_t)(lane + 32*i) * 4;
        __half h[4];
        h[0] = __float2half((v[i].x - mean) * rstd * gg.x + bb.x);
        h[1] = __float2half((v[i].y - mean) * rstd * gg.y + bb.y);
        h[2] = __float2half((v[i].z - mean) * rstd * gg.z + bb.z);
        h[3] = __float2half((v[i].w - mean) * rstd * gg.w + bb.w);
        *(uint2*)(ohi + idx) = *(uint2*)h;
    }
}

// ======== fused LN1 + tensor-core kqv + prm_exp (8 tok/block, 4 heads/pass) ========
#define SKQ_STRIDE 200
#define W16_OFF 16384
#define AHI_OFF 40960
#define ALO_OFF 45056
#define K1_SMEM_FLOATS 20992
__global__ void kqv_prm_kernel(const float* __restrict__ xg, const float* __restrict__ ln1_g,
                               const float* __restrict__ ln1_b,
                               const __half* __restrict__ kwh,
                               const float* __restrict__ kqv_b, const float* __restrict__ wrf,
                               __half* __restrict__ gvh, float* __restrict__ gkp,
                               float* __restrict__ gqp) {
    extern __shared__ float sm[];
    char* smc = (char*)sm;
    uint32_t sb = smem_to_u32(sm);
    float* sh_h  = sm;                    // [8 tok][512]
    float* wr_t  = sm + 12288;            // [64 e][32 m]
    float* sbias = wr_t + 2048;           // [192]
    float* skqv4 = sbias + 192;           // [4 hd][8 tok][SKQ_STRIDE]
    float* sxd4  = skqv4 + 6400;          // [4 hd][16]
    int tid = threadIdx.x, lane = tid & 31, wid = tid >> 5;
    size_t t0 = (size_t)blockIdx.x * 8;

    // ---- kqv_w fp16 -> smem via cp.async (192 rows x 128B, swizzled) ----
    #pragma unroll
    for (int i = 0; i < 6; i++) {
        int idx = tid + 256*i;
        int row = idx >> 3, c = idx & 7;
        cp_async16(sb + W16_OFF + (uint32_t)row*128 + (uint32_t)((c ^ (row & 7)) << 4),
                   kwh + row*64 + c*8);
    }
    CP_COMMIT();

    // ---- fused LN1: warp per token -> sh_h (fp32) ----
    {
        int tok = tid >> 5;
        const float4* xr = (const float4*)(xg + (t0 + tok) * EMB);
        float4 v[4];
        float s = 0.f, sq = 0.f;
        #pragma unroll
        for (int i = 0; i < 4; i++) {
            v[i] = xr[lane + 32*i];
            s  += v[i].x + v[i].y + v[i].z + v[i].w;
            sq += v[i].x*v[i].x + v[i].y*v[i].y + v[i].z*v[i].z + v[i].w*v[i].w;
        }
        #pragma unroll
        for (int o = 16; o; o >>= 1) {
            s  += __shfl_xor_sync(0xffffffffu, s,  o);
            sq += __shfl_xor_sync(0xffffffffu, sq, o);
        }
        float mean = s * (1.0f/EMB);
        float var  = sq * (1.0f/EMB) - mean*mean;
        float rstd = rsqrtf(var + LN_EPS);
        const float4* g4 = (const float4*)ln1_g;
        const float4* b4 = (const float4*)ln1_b;
        float4* hrow = (float4*)(sh_h + tok * 512);
        #pragma unroll
        for (int i = 0; i < 4; i++) {
            float4 gg = g4[lane + 32*i], bb = b4[lane + 32*i];
            float4 o;
            o.x = (v[i].x - mean) * rstd * gg.x + bb.x;
            o.y = (v[i].y - mean) * rstd * gg.y + bb.y;
            o.z = (v[i].z - mean) * rstd * gg.z + bb.z;
            o.w = (v[i].w - mean) * rstd * gg.w + bb.w;
            hrow[lane + 32*i] = o;
        }
    }
    // ---- wr_t [64 e][32 m] + bias ----
    #pragma unroll
    for (int i = 0; i < 2; i++) {
        int j = tid + 256*i;
        int m = j >> 4, e0 = (j & 15) << 2;
        float4 w4 = ((const float4*)wrf)[j];
        wr_t[(e0+0)*32 + m] = w4.x;
        wr_t[(e0+1)*32 + m] = w4.y;
        wr_t[(e0+2)*32 + m] = w4.z;
        wr_t[(e0+3)*32 + m] = w4.w;
    }
    if (tid < 192) sbias[tid] = kqv_b[tid];
    CP_WAIT0();
    __syncthreads();

    int wm = wid & 1, wn = wid >> 1;
    int m0 = wm * 16, n0 = wn * 48;
    int arow = m0 + (lane & 15), acb = lane >> 4;
    int brow_l = (lane & 7) + ((lane >> 4) << 3), bcb = (lane >> 3) & 1;

    for (int hg = 0; hg < 2; hg++) {
        // ---- convert A (32 rows x 64 e) to hi/lo fp16, swizzled ----
        {
            int r = tid >> 3, c = tid & 7;
            int hd4 = r >> 3, tok = r & 7;
            const float* hp = sh_h + tok*512 + (hg*4 + hd4)*64 + c*8;
            float4 f0 = *(const float4*)hp;
            float4 f1 = *(const float4*)(hp + 4);
            float vv[8] = {f0.x,f0.y,f0.z,f0.w,f1.x,f1.y,f1.z,f1.w};
            __half hi[8], lo[8];
            #pragma unroll
            for (int q = 0; q < 8; q++) {
                hi[q] = __float2half(vv[q]);
                lo[q] = __float2half(vv[q] - __half2float(hi[q]));
            }
            uint32_t off = (uint32_t)r*128 + (uint32_t)((c ^ (r & 7)) << 4);
            *(uint4*)(smc + AHI_OFF + off) = *(uint4*)hi;
            *(uint4*)(smc + ALO_OFF + off) = *(uint4*)lo;
        }
        __syncthreads();

        // ---- MMA: 2-term (hi+lo) x W16 ----
        float acc[6][4];
        #pragma unroll
        for (int nf = 0; nf < 6; nf++)
            #pragma unroll
            for (int q = 0; q < 4; q++) acc[nf][q] = 0.f;
        #pragma unroll
        for (int ks = 0; ks < 4; ks++) {
            uint32_t aoff = (uint32_t)arow*128 +
                            (uint32_t)((((ks*2 + acb)) ^ (arow & 7)) << 4);
            uint32_t ah[4], al[4];
            ldsm_x4(ah[0], ah[1], ah[2], ah[3], sb + AHI_OFF + aoff);
            ldsm_x4(al[0], al[1], al[2], al[3], sb + ALO_OFF + aoff);
            #pragma unroll
            for (int ng = 0; ng < 3; ng++) {
                int br = n0 + ng*16 + brow_l;
                uint32_t boff = (uint32_t)br*128 +
                                (uint32_t)(((ks*2 + bcb) ^ (br & 7)) << 4);
                uint32_t b2[2][2];
                ldsm_x4(b2[0][0], b2[0][1], b2[1][0], b2[1][1], sb + W16_OFF + boff);
                #pragma unroll
                for (int j = 0; j < 2; j++) {
                    mma_f16(acc[2*ng + j], ah, b2[j]);
                    mma_f16(acc[2*ng + j], al, b2[j]);
                }
            }
        }
        // ---- epilogue: acc + bias -> skqv4 ----
        {
            int rb = m0 + (lane >> 2);
            int cb = n0 + (lane & 3) * 2;
            #pragma unroll
            for (int half = 0; half < 2; half++) {
                int r = rb + half*8;
                int hd4 = r >> 3, tok = r & 7;
                float* row = skqv4 + hd4*8*SKQ_STRIDE + tok*SKQ_STRIDE;
                #pragma unroll
                for (int nf = 0; nf < 6; nf++) {
                    int col = cb + nf*8;
                    row[col]   = acc[nf][half*2+0] + sbias[col];
                    row[col+1] = acc[nf][half*2+1] + sbias[col+1];
                }
            }
        }
        __syncthreads();

        // ---- v write: 1024 half2 pairs ----
        #pragma unroll
        for (int i = 0; i < 4; i++) {
            int idx = tid + 256*i;
            int hd4 = idx >> 8, tok = (idx >> 5) & 7, e2 = idx & 31;
            const float* src = &skqv4[hd4*8*SKQ_STRIDE + tok*SKQ_STRIDE + 128 + e2*2];
            __half2 hv = __floats2half2_rn(src[0], src[1]);
            *(__half2*)&gvh[(((t0 + tok) * HEADS) + hg*4 + hd4) * ES + e2*2] = hv;
        }
        // ---- xd ----
        if (tid < 64) {
            int hd4 = tid >> 4, r = tid & 15, tok = r >> 1, which = r & 1;
            const float* z = skqv4 + hd4*8*SKQ_STRIDE + tok*SKQ_STRIDE + which*64;
            float s = 0.f;
            #pragma unroll 8
            for (int e = 0; e < 64; e++) { float zz = z[e]; s += zz*zz; }
            sxd4[hd4*16 + r] = 0.5f * s;
        }
        __syncthreads();

        // ---- wtx + exp ----
        #pragma unroll
        for (int i = 0; i < 2; i++) {
            int sidx = tid + 256*i;
            int mg = sidx & 7, which = (sidx >> 3) & 1, tok = (sidx >> 4) & 7, hd4 = sidx >> 7;
            int mq = mg * 4;
            const float* z = skqv4 + hd4*8*SKQ_STRIDE + tok*SKQ_STRIDE + which*64;
            float a0 = 0.f, a1 = 0.f, a2 = 0.f, a3 = 0.f;
            #pragma unroll 8
            for (int e = 0; e < 64; e++) {
                float zv = z[e];
                float4 w4 = *(const float4*)&wr_t[e*32 + mq];
                a0 += zv*w4.x; a1 += zv*w4.y; a2 += zv*w4.z; a3 += zv*w4.w;
            }
            float xdv = sxd4[hd4*16 + tok*2 + which];
            float4 o;
            o.x = expf(a0 - xdv) * 0.17677669529663689f;
            o.y = expf(a1 - xdv) * 0.17677669529663689f;
            o.z = expf(a2 - xdv) * 0.17677669529663689f;
            o.w = expf(a3 - xdv) * 0.17677669529663689f;
            float* dst = which ? gqp : gkp;
            *(float4*)&dst[(((t0 + tok) * HEADS) + hg*4 + hd4) * MF + mq] = o;
        }
        __syncthreads();
    }
}

// ------- kptv / ksum partial reduction over T: cp.async double-buffered -------
__global__ void kpt_kernel(const __half* __restrict__ gvh, const float* __restrict__ gkp,
                           float* __restrict__ part_kptv, float* __restrict__ part_ksum) {
    int chunk = blockIdx.x;
    int bh = blockIdx.y;
    int b = bh >> 3, h = bh & 7;
    __shared__ __half sv[2][16][64];
    __shared__ float skp[2][16][32];
    uint32_t sv_b = smem_to_u32(sv), skp_b = smem_to_u32(skp);
    int tid = threadIdx.x, lane = tid & 31, wid = tid >> 5;
    float acc[8] = {0,0,0,0,0,0,0,0};
    float ks = 0.f;
    int t0 = chunk * 256;

    auto load_stage = [&](int buf, int s0) {
        if (tid < 128) {
            int s = tid >> 3, c = tid & 7;
            cp_async16(sv_b + buf*2048 + s*128 + c*16,
                       gvh + (((size_t)b*TQ + s0 + s) * HEADS + h) * ES + c*8);
        } else {
            int r = tid - 128;
            int s = r >> 3, c = r & 7;
            cp_async16(skp_b + buf*2048 + s*128 + c*16,
                       gkp + (((size_t)b*TQ + s0 + s) * HEADS + h) * MF + c*4);
        }
    };

    load_stage(0, t0);
    CP_COMMIT();
    for (int st = 0; st < 16; st++) {
        CP_WAIT0();
        __syncthreads();
        if (st + 1 < 16) {
            load_stage((st + 1) & 1, t0 + (st + 1) * 16);
            CP_COMMIT();
        }
        int buf = st & 1;
        #pragma unroll
        for (int s = 0; s < 16; s++) {
            float kv = skp[buf][s][lane];
            uint4 vr = *(const uint4*)&sv[buf][s][wid*8];
            __half2* hp = (__half2*)&vr;
            float2 c0 = __half22float2(hp[0]);
            float2 c1 = __half22float2(hp[1]);
            float2 c2 = __half22float2(hp[2]);
            float2 c3 = __half22float2(hp[3]);
            acc[0] += c0.x*kv; acc[1] += c0.y*kv; acc[2] += c1.x*kv; acc[3] += c1.y*kv;
            acc[4] += c2.x*kv; acc[5] += c2.y*kv; acc[6] += c3.x*kv; acc[7] += c3.y*kv;
            if (wid == 0) ks += kv;
        }
    }
    size_t base = ((size_t)(chunk*64 + bh)) * (ES*MF);
    #pragma unroll
    for (int j = 0; j < 8; j++)
        part_kptv[base + (wid*8 + j)*MF + lane] = acc[j];
    if (wid == 0) part_ksum[(chunk*64 + bh)*MF + lane] = ks;
}

__global__ void reduce_kernel(const float* __restrict__ pk, const float* __restrict__ ps,
                              float* __restrict__ kptv, float* __restrict__ ksum) {
    int bid = blockIdx.x;
    if (bid < 512) {
        int idx = bid * 256 + threadIdx.x;
        int bh = idx >> 11;
        float s = 0.f;
        #pragma unroll
        for (int c = 0; c < 16; c++) s += pk[((size_t)(c*64 + bh)) * 2048 + (idx & 2047)];
        kptv[idx] = s;
    } else {
        #pragma unroll
        for (int j = 0; j < 8; j++) {
            int idx = threadIdx.x * 8 + j;
            int bh = idx >> 5, m = idx & 31;
            float s = 0.f;
            #pragma unroll
            for (int c = 0; c < 16; c++) s += ps[(c*64 + bh)*MF + m];
            ksum[idx] = s;
        }
    }
}

// ------- y = (qp . kptv) / D -> fp16: smem qp tile + precomputed 1/D, no shfl -------
__global__ void y_kernel(const float* __restrict__ gqp, const float* __restrict__ kptv,
                         const float* __restrict__ ksum, __half* __restrict__ yh) {
    int bh = blockIdx.y, b = bh >> 3, h = bh & 7;
    __shared__ float sk[64*33];
    __shared__ float sks[32];
    __shared__ float sqp[256*33];
    __shared__ float sdinv[256];
    int tid = threadIdx.x, lane = tid & 31, wid = tid >> 5;
    int tbase = blockIdx.x * 256;
    #pragma unroll
    for (int i = 0; i < 8; i++) {
        int idx = tid + 256*i;
        sk[(idx >> 5)*33 + (idx & 31)] = kptv[(size_t)bh*2048 + idx];
    }
    if (tid < 32) sks[tid] = ksum[bh*32 + tid];
    #pragma unroll
    for (int i = 0; i < 8; i++) {
        int idx = tid + 256*i;
        int t = idx >> 3, mq = (idx & 7) * 4;
        float4 q4 = *(const float4*)&gqp[(((size_t)b*TQ + tbase + t) * HEADS + h) * MF + mq];
        float* row = sqp + t*33 + mq;
        row[0] = q4.x; row[1] = q4.y; row[2] = q4.z; row[3] = q4.w;
    }
    __syncthreads();
    {
        float d = 0.f;
        const float* qrow = sqp + tid*33;
        #pragma unroll 8
        for (int m = 0; m < 32; m++) d += qrow[m] * sks[m];
        sdinv[tid] = 1.0f / d;
    }
    __syncthreads();
    for (int it = 0; it < 32; it++) {
        int tl = wid * 32 + it;
        const float* qrow = sqp + tl*33;
        float a0 = 0.f, a1 = 0.f;
        #pragma unroll 8
        for (int m = 0; m < 32; m++) {
            float qm = qrow[m];
            a0 += qm * sk[lane*33 + m];
            a1 += qm * sk[(lane+32)*33 + m];
        }
        float inv = sdinv[tl];
        size_t off = ((size_t)b*TQ + tbase + tl) * EMB + h * ES;
        yh[off + lane]      = __float2half(a0 * inv);
        yh[off + lane + 32] = __float2half(a1 * inv);
    }
}

// ===== mma.sync fp16 GEMM (fp32 accum), 3-stage smem + register-fragment double buffer =====
#define PLANE_BYTES 16384
#define BUF_BYTES (2*PLANE_BYTES)
#define GEMM_SMEM (3*BUF_BYTES)

#define SWZ_ADDR(base, row, chunk) \
    ((base) + (uint32_t)(row)*128u + (uint32_t)(((chunk) ^ ((row)&7)) << 4))

template<int EPI>
__global__ __launch_bounds__(256, 2)
void gemm_mma(const __half* __restrict__ Ah, const __half* __restrict__ Bh,
              const float* __restrict__ bias, const float* __restrict__ res,
              float* __restrict__ Cf, __half* __restrict__ Chi, int N, int K) {
    extern __shared__ char gsm[];
    uint32_t sb = smem_to_u32(gsm);
    int tid = threadIdx.x, lane = tid & 31, wid = tid >> 5;
    int rowBase = blockIdx.y * 128, colBase = blockIdx.x * 128;

    int wm = wid & 3, wn = wid >> 2;
    int m0 = wm * 32, n0 = wn * 64;

    float acc[2][8][4];
    #pragma unroll
    for (int i = 0; i < 2; i++)
        #pragma unroll
        for (int j = 0; j < 8; j++)
            #pragma unroll
            for (int q = 0; q < 4; q++) acc[i][j][q] = 0.f;

    int arow_l = (lane & 15);
    int acb    = (lane >> 4);
    int brow_l = (lane & 7) + ((lane >> 4) << 3);
    int bcb    = (lane >> 3) & 1;

    auto load_chunk = [&](int buf, int k0) {
        uint32_t sbase = sb + buf * BUF_BYTES;
        int row = tid >> 1, c0 = (tid & 1) * 4;
        size_t goA = (size_t)(rowBase + row) * K + k0 + c0 * 8;
        size_t goB = (size_t)(colBase + row) * K + k0 + c0 * 8;
        #pragma unroll
        for (int j = 0; j < 4; j++) {
            uint32_t so = SWZ_ADDR(sbase, row, c0 + j);
            cp_async16(so,               Ah + goA + j * 8);
            cp_async16(PLANE_BYTES + so, Bh + goB + j * 8);
        }
    };

    int NC = K >> 6;
    load_chunk(0, 0);
    CP_COMMIT();
    load_chunk(1, 64);
    CP_COMMIT();

    // register fragment double buffers
    uint32_t ahf[2][2][4];        // [buf][mt][4]
    uint32_t bhf[2][4][2][2];     // [buf][ng][j][2]

    int bufc = 0, bufn = 2;
    for (int c = 0; c < NC; c++) {
        if (c + 1 < NC) { CP_WAIT1(); } else { CP_WAIT0(); }
        __syncthreads();
        if (c + 2 < NC) {
            load_chunk(bufn, (c + 2) << 6);
            CP_COMMIT();
        }

        uint32_t pA = sb + bufc * BUF_BYTES;

        // prologue: fragments for ks=0 into buffer 0
        #pragma unroll
        for (int mt = 0; mt < 2; mt++) {
            int ar = m0 + mt * 16 + arow_l;
            ldsm_x4(ahf[0][mt][0], ahf[0][mt][1], ahf[0][mt][2], ahf[0][mt][3],
                    SWZ_ADDR(pA, ar, acb));
        }
        #pragma unroll
        for (int ng = 0; ng < 4; ng++) {
            int br = n0 + ng * 16 + brow_l;
            ldsm_x4(bhf[0][ng][0][0], bhf[0][ng][0][1], bhf[0][ng][1][0], bhf[0][ng][1][1],
                    SWZ_ADDR(pA + PLANE_BYTES, br, bcb));
        }

        #pragma unroll
        for (int ks = 0; ks < 4; ks++) {
            int cur = ks & 1;
            if (ks < 3) {
                int nxt = cur ^ 1;
                #pragma unroll
                for (int mt = 0; mt < 2; mt++) {
                    int ar = m0 + mt * 16 + arow_l;
                    ldsm_x4(ahf[nxt][mt][0], ahf[nxt][mt][1], ahf[nxt][mt][2], ahf[nxt][mt][3],
                            SWZ_ADDR(pA, ar, (ks + 1) * 2 + acb));
                }
                #pragma unroll
                for (int ng = 0; ng < 4; ng++) {
                    int br = n0 + ng * 16 + brow_l;
                    ldsm_x4(bhf[nxt][ng][0][0], bhf[nxt][ng][0][1],
                            bhf[nxt][ng][1][0], bhf[nxt][ng][1][1],
                            SWZ_ADDR(pA + PLANE_BYTES, br, (ks + 1) * 2 + bcb));
                }
            }
            #pragma unroll
            for (int ng = 0; ng < 4; ng++)
                #pragma unroll
                for (int mt = 0; mt < 2; mt++)
                    #pragma unroll
                    for (int j = 0; j < 2; j++)
                        mma_f16(acc[mt][2*ng + j], ahf[cur][mt], bhf[cur][ng][j]);
        }
        bufc = (bufc + 1 == 3) ? 0 : bufc + 1;
        bufn = (bufn + 1 == 3) ? 0 : bufn + 1;
    }

    int rbase = rowBase + m0 + (lane >> 2);
    int cbase = colBase + n0 + (lane & 3) * 2;
    #pragma unroll
    for (int mt = 0; mt < 2; mt++) {
        #pragma unroll
        for (int half = 0; half < 2; half++) {
            int row = rbase + mt * 16 + half * 8;
            if (EPI == 0) {
                float* crow = Cf + (size_t)row * N;
                const float* rrow = res + (size_t)row * N;
                #pragma unroll
                for (int nt = 0; nt < 8; nt++) {
                    int col = cbase + nt * 8;
                    float2 o;
                    o.x = acc[mt][nt][half*2+0] + bias[col]   + rrow[col];
                    o.y = acc[mt][nt][half*2+1] + bias[col+1] + rrow[col+1];
                    *(float2*)(crow + col) = o;
                }
            } else {
                __half* hrow = Chi + (size_t)row * N;
                #pragma unroll
                for (int nt = 0; nt < 8; nt++) {
                    int col = cbase + nt * 8;
                    float v0 = acc[mt][nt][half*2+0] + bias[col];
                    float v1 = acc[mt][nt][half*2+1] + bias[col+1];
                    v0 = 0.5f * v0 * (1.0f + erff(v0 * 0.70710678118654752f));
                    v1 = 0.5f * v1 * (1.0f + erff(v1 * 0.70710678118654752f));
                    __half hh[2] = {__float2half(v0), __float2half(v1)};
                    *(uint32_t*)(hrow + col) = *(uint32_t*)hh;
                }
            }
        }
    }
}

// ---------------- launch ----------------
extern "C" void kernel_launch(void* const* d_in, const int* in_sizes, int n_in,
                              void* d_out, int out_size) {
    const float* x      = (const float*)d_in[0];
    const float* wrf    = (const float*)d_in[1];
    const float* kqv_w  = (const float*)d_in[2];
    const float* kqv_b  = (const float*)d_in[3];
    const float* proj_w = (const float*)d_in[4];
    const float* proj_b = (const float*)d_in[5];
    const float* ln1_g  = (const float*)d_in[6];
    const float* ln1_b  = (const float*)d_in[7];
    const float* ln2_g  = (const float*)d_in[8];
    const float* ln2_b  = (const float*)d_in[9];
    const float* mlp_w1 = (const float*)d_in[10];
    const float* mlp_b1 = (const float*)d_in[11];
    const float* mlp_w2 = (const float*)d_in[12];
    const float* mlp_b2 = (const float*)d_in[13];
    float* out = (float*)d_out;

    float *p_qp, *p_kp, *p_pk, *p_ps, *p_kptv, *p_ksum, *p_x1;
    __half *p_vh, *p_h2h, *p_yh, *p_hidh, *p_pwh, *p_w1h, *p_w2h, *p_kwh;
    cudaGetSymbolAddress((void**)&p_vh,   g_vh);
    cudaGetSymbolAddress((void**)&p_qp,   g_qp);
    cudaGetSymbolAddress((void**)&p_kp,   g_kp);
    cudaGetSymbolAddress((void**)&p_pk,   g_kptv_part);
    cudaGetSymbolAddress((void**)&p_ps,   g_ksum_part);
    cudaGetSymbolAddress((void**)&p_kptv, g_kptv);
    cudaGetSymbolAddress((void**)&p_ksum, g_ksum);
    cudaGetSymbolAddress((void**)&p_x1,   g_x1);
    cudaGetSymbolAddress((void**)&p_h2h,  g_h2h);
    cudaGetSymbolAddress((void**)&p_yh,   g_yh);
    cudaGetSymbolAddress((void**)&p_hidh, g_hidh);
    cudaGetSymbolAddress((void**)&p_pwh,  g_pwh);
    cudaGetSymbolAddress((void**)&p_w1h,  g_w1h);
    cudaGetSymbolAddress((void**)&p_w2h,  g_w2h);
    cudaGetSymbolAddress((void**)&p_kwh,  g_kwh);

    const size_t k1_smem = (size_t)K1_SMEM_FLOATS * sizeof(float);   // 83968B
    cudaFuncSetAttribute(kqv_prm_kernel, cudaFuncAttributeMaxDynamicSharedMemorySize,
                         (int)k1_smem);
    cudaFuncSetAttribute(gemm_mma<0>, cudaFuncAttributeMaxDynamicSharedMemorySize, GEMM_SMEM);
    cudaFuncSetAttribute(gemm_mma<1>, cudaFuncAttributeMaxDynamicSharedMemorySize, GEMM_SMEM);

    // 0. all weight fp16 rounds (one launch)
    cvt_all_kernel<<<(CVT_N4 + 255)/256, 256>>>(proj_w, mlp_w1, mlp_w2, kqv_w,
                                                p_pwh, p_w1h, p_w2h, p_kwh);
    // 1. fused LN1 + tensor kqv + prm_exp (v -> fp16)
    kqv_prm_kernel<<<NTOK/8, 256, k1_smem>>>(x, ln1_g, ln1_b, p_kwh, kqv_b, wrf,
                                             p_vh, p_kp, p_qp);
    // 2-3. kptv/ksum reduction over T
    kpt_kernel<<<dim3(16, 64), 256>>>(p_vh, p_kp, p_pk, p_ps);
    reduce_kernel<<<513, 256>>>(p_pk, p_ps, p_kptv, p_ksum);
    // 4. y
    y_kernel<<<dim3(TQ/256, 64), 256>>>(p_qp, p_kptv, p_ksum, p_yh);
    // 5. attn proj + residual -> x1 (fp32)
    gemm_mma<0><<<dim3(EMB/128, NTOK/128), 256, GEMM_SMEM>>>(
        p_yh, p_pwh, proj_b, x, p_x1, nullptr, EMB, EMB);
    // 6. LN2 -> fp16
    ln2_kernel<<<NTOK/8, 256>>>(p_x1, ln2_g, ln2_b, p_h2h);
    // 7. mlp1 + gelu -> hid (fp16)
    gemm_mma<1><<<dim3(HID/128, NTOK/128), 256, GEMM_SMEM>>>(
        p_h2h, p_w1h, mlp_b1, nullptr, nullptr, p_hidh, HID, EMB);
    // 8. mlp2 + residual -> out (fp32)
    gemm_mma<0><<<dim3(EMB/128, NTOK/128), 256, GEMM_SMEM>>>(
        p_hidh, p_w2h, mlp_b2, p_x1, out, nullptr, EMB, HID);
}

// round 14
// speedup vs baseline: 1.3014x; 1.0563x over previous
#include <cuda_runtime.h>
#include <cuda_fp16.h>
#include <math.h>
#include <stdint.h>

// Problem constants
#define BQ 8
#define TQ 4096
#define NTOK (BQ*TQ)          // 32768 tokens
#define EMB 512
#define HEADS 8
#define ES 64
#define MF 32                 // random features
#define HID (4*EMB)           // 2048
#define LN_EPS 1e-5f

__device__ __forceinline__ uint32_t smem_to_u32(const void* smem_ptr) {
    uint32_t addr;
    asm("{ .reg .u64 tmp; cvta.to.shared.u64 tmp, %1; cvt.u32.u64 %0, tmp; }"
        : "=r"(addr) : "l"(smem_ptr));
    return addr;
}

__device__ __forceinline__ void cp_async16(uint32_t saddr, const void* gaddr) {
    asm volatile("cp.async.cg.shared.global [%0], [%1], 16;" :: "r"(saddr), "l"(gaddr));
}
#define CP_COMMIT() asm volatile("cp.async.commit_group;" ::: "memory")
#define CP_WAIT0()  asm volatile("cp.async.wait_group 0;" ::: "memory")
#define CP_WAIT1()  asm volatile("cp.async.wait_group 1;" ::: "memory")

__device__ __forceinline__ void ldsm_x4(uint32_t& r0, uint32_t& r1, uint32_t& r2, uint32_t& r3,
                                        uint32_t addr) {
    asm volatile("ldmatrix.sync.aligned.m8n8.x4.shared.b16 {%0,%1,%2,%3}, [%4];"
        : "=r"(r0), "=r"(r1), "=r"(r2), "=r"(r3) : "r"(addr));
}

__device__ __forceinline__ void mma_f16(float* c, const uint32_t* a, const uint32_t* b) {
    asm volatile(
        "mma.sync.aligned.m16n8k16.row.col.f32.f16.f16.f32 "
        "{%0,%1,%2,%3}, {%4,%5,%6,%7}, {%8,%9}, {%0,%1,%2,%3};"
        : "+f"(c[0]), "+f"(c[1]), "+f"(c[2]), "+f"(c[3])
        : "r"(a[0]), "r"(a[1]), "r"(a[2]), "r"(a[3]), "r"(b[0]), "r"(b[1]));
}

// -------- scratch (device globals; no runtime allocation) --------
__device__ __align__(16) __half g_vh[(size_t)NTOK*HEADS*ES];   // v fp16
__device__ float g_qp[(size_t)NTOK*HEADS*MF];
__device__ float g_kp[(size_t)NTOK*HEADS*MF];
__device__ float g_kptv_part[16*64*ES*MF];
__device__ float g_ksum_part[16*64*MF];
__device__ float g_kptv[64*ES*MF];
__device__ float g_ksum[64*MF];
__device__ float g_x1[(size_t)NTOK*EMB];
__device__ __align__(16) __half g_h2h[(size_t)NTOK*EMB];
__device__ __align__(16) __half g_yh[(size_t)NTOK*EMB];
__device__ __align__(16) __half g_hidh[(size_t)NTOK*HID];
__device__ __align__(16) __half g_pwh[EMB*EMB];
__device__ __align__(16) __half g_w1h[HID*EMB];
__device__ __align__(16) __half g_w2h[EMB*HID];
__device__ __align__(16) __half g_kwh[192*64];   // kqv_w fp16

// ---------------- fused weight fp16 conversion (all 4 weights) ----------------
#define CVT_N4 (65536 + 262144 + 262144 + 3072)
__global__ void cvt_all_kernel(const float* __restrict__ pw, const float* __restrict__ w1,
                               const float* __restrict__ w2, const float* __restrict__ kw,
                               __half* __restrict__ pwh, __half* __restrict__ w1h,
                               __half* __restrict__ w2h, __half* __restrict__ kwh) {
    int i = blockIdx.x * 256 + threadIdx.x;
    if (i >= CVT_N4) return;
    const float* src;
    __half* dst;
    int j;
    if (i < 65536)       { src = pw; dst = pwh; j = i; }
    else if (i < 327680) { src = w1; dst = w1h; j = i - 65536; }
    else if (i < 589824) { src = w2; dst = w2h; j = i - 327680; }
    else                 { src = kw; dst = kwh; j = i - 589824; }
    float4 v = ((const float4*)src)[j];
    __half h[4];
    h[0] = __float2half(v.x); h[1] = __float2half(v.y);
    h[2] = __float2half(v.z); h[3] = __float2half(v.w);
    *(uint2*)(dst + (size_t)j*4) = *(uint2*)h;
}

// ---------------- LayerNorm (LN2): warp per token, fp16 out ----------------
__global__ void ln2_kernel(const float* __restrict__ x, const float* __restrict__ g,
                           const float* __restrict__ b, __half* __restrict__ ohi) {
    int tok  = blockIdx.x * 8 + (threadIdx.x >> 5);
    int lane = threadIdx.x & 31;
    const float4* xr = (const float4*)(x + (size_t)tok * EMB);
    float4 v[4];
    float s = 0.f, sq = 0.f;
    #pragma unroll
    for (int i = 0; i < 4; i++) {
        v[i] = xr[lane + 32*i];
        s  += v[i].x + v[i].y + v[i].z + v[i].w;
        sq += v[i].x*v[i].x + v[i].y*v[i].y + v[i].z*v[i].z + v[i].w*v[i].w;
    }
    #pragma unroll
    for (int o = 16; o; o >>= 1) {
        s  += __shfl_xor_sync(0xffffffffu, s,  o);
        sq += __shfl_xor_sync(0xffffffffu, sq, o);
    }
    float mean = s * (1.0f/EMB);
    float var  = sq * (1.0f/EMB) - mean*mean;
    float rstd = rsqrtf(var + LN_EPS);
    const float4* g4 = (const float4*)g;
    const float4* b4 = (const float4*)b;
    #pragma unroll
    for (int i = 0; i < 4; i++) {
        float4 gg = g4[lane + 32*i], bb = b4[lane + 32*i];
        size_t idx = (size_t)tok * EMB + (size_t)(lane + 32*i) * 4;
        __half h[4];
        h[0] = __float2half((v[i].x - mean) * rstd * gg.x + bb.x);
        h[1] = __float2half((v[i].y - mean) * rstd * gg.y + bb.y);
        h[2] = __float2half((v[i].z - mean) * rstd * gg.z + bb.z);
        h[3] = __float2half((v[i].w - mean) * rstd * gg.w + bb.w);
        *(uint2*)(ohi + idx) = *(uint2*)h;
    }
}

// ======== fused LN1 + tensor-core kqv + prm_exp (8 tok/block, 4 heads/pass) ========
#define SKQ_STRIDE 200
#define W16_OFF 16384
#define AHI_OFF 40960
#define ALO_OFF 45056
#define K1_SMEM_FLOATS 20992
__global__ void kqv_prm_kernel(const float* __restrict__ xg, const float* __restrict__ ln1_g,
                               const float* __restrict__ ln1_b,
                               const __half* __restrict__ kwh,
                               const float* __restrict__ kqv_b, const float* __restrict__ wrf,
                               __half* __restrict__ gvh, float* __restrict__ gkp,
                               float* __restrict__ gqp) {
    extern __shared__ float sm[];
    char* smc = (char*)sm;
    uint32_t sb = smem_to_u32(sm);
    float* sh_h  = sm;                    // [8 tok][512]
    float* wr_t  = sm + 12288;            // [64 e][32 m]
    float* sbias = wr_t + 2048;           // [192]
    float* skqv4 = sbias + 192;           // [4 hd][8 tok][SKQ_STRIDE]
    float* sxd4  = skqv4 + 6400;          // [4 hd][16]
    int tid = threadIdx.x, lane = tid & 31, wid = tid >> 5;
    size_t t0 = (size_t)blockIdx.x * 8;

    // ---- kqv_w fp16 -> smem via cp.async (192 rows x 128B, swizzled) ----
    #pragma unroll
    for (int i = 0; i < 6; i++) {
        int idx = tid + 256*i;
        int row = idx >> 3, c = idx & 7;
        cp_async16(sb + W16_OFF + (uint32_t)row*128 + (uint32_t)((c ^ (row & 7)) << 4),
                   kwh + row*64 + c*8);
    }
    CP_COMMIT();

    // ---- fused LN1: warp per token -> sh_h (fp32) ----
    {
        int tok = tid >> 5;
        const float4* xr = (const float4*)(xg + (t0 + tok) * EMB);
        float4 v[4];
        float s = 0.f, sq = 0.f;
        #pragma unroll
        for (int i = 0; i < 4; i++) {
            v[i] = xr[lane + 32*i];
            s  += v[i].x + v[i].y + v[i].z + v[i].w;
            sq += v[i].x*v[i].x + v[i].y*v[i].y + v[i].z*v[i].z + v[i].w*v[i].w;
        }
        #pragma unroll
        for (int o = 16; o; o >>= 1) {
            s  += __shfl_xor_sync(0xffffffffu, s,  o);
            sq += __shfl_xor_sync(0xffffffffu, sq, o);
        }
        float mean = s * (1.0f/EMB);
        float var  = sq * (1.0f/EMB) - mean*mean;
        float rstd = rsqrtf(var + LN_EPS);
        const float4* g4 = (const float4*)ln1_g;
        const float4* b4 = (const float4*)ln1_b;
        float4* hrow = (float4*)(sh_h + tok * 512);
        #pragma unroll
        for (int i = 0; i < 4; i++) {
            float4 gg = g4[lane + 32*i], bb = b4[lane + 32*i];
            float4 o;
            o.x = (v[i].x - mean) * rstd * gg.x + bb.x;
            o.y = (v[i].y - mean) * rstd * gg.y + bb.y;
            o.z = (v[i].z - mean) * rstd * gg.z + bb.z;
            o.w = (v[i].w - mean) * rstd * gg.w + bb.w;
            hrow[lane + 32*i] = o;
        }
    }
    // ---- wr_t [64 e][32 m] + bias ----
    #pragma unroll
    for (int i = 0; i < 2; i++) {
        int j = tid + 256*i;
        int m = j >> 4, e0 = (j & 15) << 2;
        float4 w4 = ((const float4*)wrf)[j];
        wr_t[(e0+0)*32 + m] = w4.x;
        wr_t[(e0+1)*32 + m] = w4.y;
        wr_t[(e0+2)*32 + m] = w4.z;
        wr_t[(e0+3)*32 + m] = w4.w;
    }
    if (tid < 192) sbias[tid] = kqv_b[tid];
    CP_WAIT0();
    __syncthreads();

    int wm = wid & 1, wn = wid >> 1;
    int m0 = wm * 16, n0 = wn * 48;
    int arow = m0 + (lane & 15), acb = lane >> 4;
    int brow_l = (lane & 7) + ((lane >> 4) << 3), bcb = (lane >> 3) & 1;

    for (int hg = 0; hg < 2; hg++) {
        // ---- convert A (32 rows x 64 e) to hi/lo fp16, swizzled ----
        {
            int r = tid >> 3, c = tid & 7;
            int hd4 = r >> 3, tok = r & 7;
            const float* hp = sh_h + tok*512 + (hg*4 + hd4)*64 + c*8;
            float4 f0 = *(const float4*)hp;
            float4 f1 = *(const float4*)(hp + 4);
            float vv[8] = {f0.x,f0.y,f0.z,f0.w,f1.x,f1.y,f1.z,f1.w};
            __half hi[8], lo[8];
            #pragma unroll
            for (int q = 0; q < 8; q++) {
                hi[q] = __float2half(vv[q]);
                lo[q] = __float2half(vv[q] - __half2float(hi[q]));
            }
            uint32_t off = (uint32_t)r*128 + (uint32_t)((c ^ (r & 7)) << 4);
            *(uint4*)(smc + AHI_OFF + off) = *(uint4*)hi;
            *(uint4*)(smc + ALO_OFF + off) = *(uint4*)lo;
        }
        __syncthreads();

        // ---- MMA: 2-term (hi+lo) x W16 ----
        float acc[6][4];
        #pragma unroll
        for (int nf = 0; nf < 6; nf++)
            #pragma unroll
            for (int q = 0; q < 4; q++) acc[nf][q] = 0.f;
        #pragma unroll
        for (int ks = 0; ks < 4; ks++) {
            uint32_t aoff = (uint32_t)arow*128 +
                            (uint32_t)((((ks*2 + acb)) ^ (arow & 7)) << 4);
            uint32_t ah[4], al[4];
            ldsm_x4(ah[0], ah[1], ah[2], ah[3], sb + AHI_OFF + aoff);
            ldsm_x4(al[0], al[1], al[2], al[3], sb + ALO_OFF + aoff);
            #pragma unroll
            for (int ng = 0; ng < 3; ng++) {
                int br = n0 + ng*16 + brow_l;
                uint32_t boff = (uint32_t)br*128 +
                                (uint32_t)(((ks*2 + bcb) ^ (br & 7)) << 4);
                uint32_t b2[2][2];
                ldsm_x4(b2[0][0], b2[0][1], b2[1][0], b2[1][1], sb + W16_OFF + boff);
                #pragma unroll
                for (int j = 0; j < 2; j++) {
                    mma_f16(acc[2*ng + j], ah, b2[j]);
                    mma_f16(acc[2*ng + j], al, b2[j]);
                }
            }
        }
        // ---- epilogue: acc + bias -> skqv4 ----
        {
            int rb = m0 + (lane >> 2);
            int cb = n0 + (lane & 3) * 2;
            #pragma unroll
            for (int half = 0; half < 2; half++) {
                int r = rb + half*8;
                int hd4 = r >> 3, tok = r & 7;
                float* row = skqv4 + hd4*8*SKQ_STRIDE + tok*SKQ_STRIDE;
                #pragma unroll
                for (int nf = 0; nf < 6; nf++) {
                    int col = cb + nf*8;
                    row[col]   = acc[nf][half*2+0] + sbias[col];
                    row[col+1] = acc[nf][half*2+1] + sbias[col+1];
                }
            }
        }
        __syncthreads();

        // ---- v write: 1024 half2 pairs ----
        #pragma unroll
        for (int i = 0; i < 4; i++) {
            int idx = tid + 256*i;
            int hd4 = idx >> 8, tok = (idx >> 5) & 7, e2 = idx & 31;
            const float* src = &skqv4[hd4*8*SKQ_STRIDE + tok*SKQ_STRIDE + 128 + e2*2];
            __half2 hv = __floats2half2_rn(src[0], src[1]);
            *(__half2*)&gvh[(((t0 + tok) * HEADS) + hg*4 + hd4) * ES + e2*2] = hv;
        }
        // ---- xd ----
        if (tid < 64) {
            int hd4 = tid >> 4, r = tid & 15, tok = r >> 1, which = r & 1;
            const float* z = skqv4 + hd4*8*SKQ_STRIDE + tok*SKQ_STRIDE + which*64;
            float s = 0.f;
            #pragma unroll 8
            for (int e = 0; e < 64; e++) { float zz = z[e]; s += zz*zz; }
            sxd4[hd4*16 + r] = 0.5f * s;
        }
        __syncthreads();

        // ---- wtx + exp ----
        #pragma unroll
        for (int i = 0; i < 2; i++) {
            int sidx = tid + 256*i;
            int mg = sidx & 7, which = (sidx >> 3) & 1, tok = (sidx >> 4) & 7, hd4 = sidx >> 7;
            int mq = mg * 4;
            const float* z = skqv4 + hd4*8*SKQ_STRIDE + tok*SKQ_STRIDE + which*64;
            float a0 = 0.f, a1 = 0.f, a2 = 0.f, a3 = 0.f;
            #pragma unroll 8
            for (int e = 0; e < 64; e++) {
                float zv = z[e];
                float4 w4 = *(const float4*)&wr_t[e*32 + mq];
                a0 += zv*w4.x; a1 += zv*w4.y; a2 += zv*w4.z; a3 += zv*w4.w;
            }
            float xdv = sxd4[hd4*16 + tok*2 + which];
            float4 o;
            o.x = expf(a0 - xdv) * 0.17677669529663689f;
            o.y = expf(a1 - xdv) * 0.17677669529663689f;
            o.z = expf(a2 - xdv) * 0.17677669529663689f;
            o.w = expf(a3 - xdv) * 0.17677669529663689f;
            float* dst = which ? gqp : gkp;
            *(float4*)&dst[(((t0 + tok) * HEADS) + hg*4 + hd4) * MF + mq] = o;
        }
        __syncthreads();
    }
}

// ------- kptv / ksum partial reduction over T: cp.async double-buffered -------
__global__ void kpt_kernel(const __half* __restrict__ gvh, const float* __restrict__ gkp,
                           float* __restrict__ part_kptv, float* __restrict__ part_ksum) {
    int chunk = blockIdx.x;
    int bh = blockIdx.y;
    int b = bh >> 3, h = bh & 7;
    __shared__ __half sv[2][16][64];
    __shared__ float skp[2][16][32];
    uint32_t sv_b = smem_to_u32(sv), skp_b = smem_to_u32(skp);
    int tid = threadIdx.x, lane = tid & 31, wid = tid >> 5;
    float acc[8] = {0,0,0,0,0,0,0,0};
    float ks = 0.f;
    int t0 = chunk * 256;

    auto load_stage = [&](int buf, int s0) {
        if (tid < 128) {
            int s = tid >> 3, c = tid & 7;
            cp_async16(sv_b + buf*2048 + s*128 + c*16,
                       gvh + (((size_t)b*TQ + s0 + s) * HEADS + h) * ES + c*8);
        } else {
            int r = tid - 128;
            int s = r >> 3, c = r & 7;
            cp_async16(skp_b + buf*2048 + s*128 + c*16,
                       gkp + (((size_t)b*TQ + s0 + s) * HEADS + h) * MF + c*4);
        }
    };

    load_stage(0, t0);
    CP_COMMIT();
    for (int st = 0; st < 16; st++) {
        CP_WAIT0();
        __syncthreads();
        if (st + 1 < 16) {
            load_stage((st + 1) & 1, t0 + (st + 1) * 16);
            CP_COMMIT();
        }
        int buf = st & 1;
        #pragma unroll
        for (int s = 0; s < 16; s++) {
            float kv = skp[buf][s][lane];
            uint4 vr = *(const uint4*)&sv[buf][s][wid*8];
            __half2* hp = (__half2*)&vr;
            float2 c0 = __half22float2(hp[0]);
            float2 c1 = __half22float2(hp[1]);
            float2 c2 = __half22float2(hp[2]);
            float2 c3 = __half22float2(hp[3]);
            acc[0] += c0.x*kv; acc[1] += c0.y*kv; acc[2] += c1.x*kv; acc[3] += c1.y*kv;
            acc[4] += c2.x*kv; acc[5] += c2.y*kv; acc[6] += c3.x*kv; acc[7] += c3.y*kv;
            if (wid == 0) ks += kv;
        }
    }
    size_t base = ((size_t)(chunk*64 + bh)) * (ES*MF);
    #pragma unroll
    for (int j = 0; j < 8; j++)
        part_kptv[base + (wid*8 + j)*MF + lane] = acc[j];
    if (wid == 0) part_ksum[(chunk*64 + bh)*MF + lane] = ks;
}

__global__ void reduce_kernel(const float* __restrict__ pk, const float* __restrict__ ps,
                              float* __restrict__ kptv, float* __restrict__ ksum) {
    int bid = blockIdx.x;
    if (bid < 512) {
        int idx = bid * 256 + threadIdx.x;
        int bh = idx >> 11;
        float s = 0.f;
        #pragma unroll
        for (int c = 0; c < 16; c++) s += pk[((size_t)(c*64 + bh)) * 2048 + (idx & 2047)];
        kptv[idx] = s;
    } else {
        #pragma unroll
        for (int j = 0; j < 8; j++) {
            int idx = threadIdx.x * 8 + j;
            int bh = idx >> 5, m = idx & 31;
            float s = 0.f;
            #pragma unroll
            for (int c = 0; c < 16; c++) s += ps[(c*64 + bh)*MF + m];
            ksum[idx] = s;
        }
    }
}

// ------- y = (qp . kptv) / D -> fp16: smem qp tile + precomputed 1/D -------
__global__ void y_kernel(const float* __restrict__ gqp, const float* __restrict__ kptv,
                         const float* __restrict__ ksum, __half* __restrict__ yh) {
    int bh = blockIdx.y, b = bh >> 3, h = bh & 7;
    __shared__ float sk[64*33];
    __shared__ float sks[32];
    __shared__ float sqp[256*33];
    __shared__ float sdinv[256];
    int tid = threadIdx.x, lane = tid & 31, wid = tid >> 5;
    int tbase = blockIdx.x * 256;
    #pragma unroll
    for (int i = 0; i < 8; i++) {
        int idx = tid + 256*i;
        sk[(idx >> 5)*33 + (idx & 31)] = kptv[(size_t)bh*2048 + idx];
    }
    if (tid < 32) sks[tid] = ksum[bh*32 + tid];
    #pragma unroll
    for (int i = 0; i < 8; i++) {
        int idx = tid + 256*i;
        int t = idx >> 3, mq = (idx & 7) * 4;
        float4 q4 = *(const float4*)&gqp[(((size_t)b*TQ + tbase + t) * HEADS + h) * MF + mq];
        float* row = sqp + t*33 + mq;
        row[0] = q4.x; row[1] = q4.y; row[2] = q4.z; row[3] = q4.w;
    }
    __syncthreads();
    {
        float d = 0.f;
        const float* qrow = sqp + tid*33;
        #pragma unroll 8
        for (int m = 0; m < 32; m++) d += qrow[m] * sks[m];
        sdinv[tid] = 1.0f / d;
    }
    __syncthreads();
    for (int it = 0; it < 32; it++) {
        int tl = wid * 32 + it;
        const float* qrow = sqp + tl*33;
        float a0 = 0.f, a1 = 0.f;
        #pragma unroll 8
        for (int m = 0; m < 32; m++) {
            float qm = qrow[m];
            a0 += qm * sk[lane*33 + m];
            a1 += qm * sk[(lane+32)*33 + m];
        }
        float inv = sdinv[tl];
        size_t off = ((size_t)b*TQ + tbase + tl) * EMB + h * ES;
        yh[off + lane]      = __float2half(a0 * inv);
        yh[off + lane + 32] = __float2half(a1 * inv);
    }
}

// ===== mma.sync fp16 GEMM: 256x128 CTA tile, 512 threads, 3-stage, one sync/chunk =====
// Warp grid 4m x 4n; warp tile 64x32. A plane 32KB, B plane 16KB; buffer 48KB x 3.
#define A_PL 32768
#define BUF_BYTES 49152
#define GEMM_SMEM (3*BUF_BYTES)            // 147456

#define SWZ_ADDR(base, row, chunk) \
    ((base) + (uint32_t)(row)*128u + (uint32_t)(((chunk) ^ ((row)&7)) << 4))

template<int EPI>
__global__ __launch_bounds__(512, 1)
void gemm_mma(const __half* __restrict__ Ah, const __half* __restrict__ Bh,
              const float* __restrict__ bias, const float* __restrict__ res,
              float* __restrict__ Cf, __half* __restrict__ Chi, int N, int K) {
    extern __shared__ char gsm[];
    uint32_t sb = smem_to_u32(gsm);
    int tid = threadIdx.x, lane = tid & 31, wid = tid >> 5;
    int rowBase = blockIdx.y * 256, colBase = blockIdx.x * 128;

    int wm = wid & 3, wn = wid >> 2;       // 4x4 warp grid
    int m0 = wm * 64, n0 = wn * 32;

    float acc[4][4][4];                    // [mt 16-row][nt 8-col][frag]
    #pragma unroll
    for (int i = 0; i < 4; i++)
        #pragma unroll
        for (int j = 0; j < 4; j++)
            #pragma unroll
            for (int q = 0; q < 4; q++) acc[i][j][q] = 0.f;

    int arow_l = (lane & 15);
    int acb    = (lane >> 4);
    int brow_l = (lane & 7) + ((lane >> 4) << 3);
    int bcb    = (lane >> 3) & 1;

    auto load_chunk = [&](int buf, int k0) {
        uint32_t sbase = sb + buf * BUF_BYTES;
        // A: 2048 x 16B
        #pragma unroll
        for (int j = 0; j < 4; j++) {
            int idx = tid + 512*j;
            int row = idx >> 3, c = idx & 7;
            cp_async16(SWZ_ADDR(sbase, row, c),
                       Ah + (size_t)(rowBase + row) * K + k0 + c * 8);
        }
        // B: 1024 x 16B
        #pragma unroll
        for (int j = 0; j < 2; j++) {
            int idx = tid + 512*j;
            int row = idx >> 3, c = idx & 7;
            cp_async16(SWZ_ADDR(sbase + A_PL, row, c),
                       Bh + (size_t)(colBase + row) * K + k0 + c * 8);
        }
    };

    int NC = K >> 6;
    load_chunk(0, 0);
    CP_COMMIT();
    load_chunk(1, 64);
    CP_COMMIT();

    int bufc = 0, bufn = 2;
    for (int c = 0; c < NC; c++) {
        if (c + 1 < NC) { CP_WAIT1(); } else { CP_WAIT0(); }
        __syncthreads();
        if (c + 2 < NC) {
            load_chunk(bufn, (c + 2) << 6);
            CP_COMMIT();
        }

        uint32_t pA = sb + bufc * BUF_BYTES;
        #pragma unroll
        for (int ks = 0; ks < 4; ks++) {
            uint32_t ah[4][4];
            #pragma unroll
            for (int mt = 0; mt < 4; mt++) {
                int ar = m0 + mt * 16 + arow_l;
                ldsm_x4(ah[mt][0], ah[mt][1], ah[mt][2], ah[mt][3],
                        SWZ_ADDR(pA, ar, ks * 2 + acb));
            }
            uint32_t bh2[4][2];            // 2 n16-groups -> 4 n8 frags
            #pragma unroll
            for (int ng = 0; ng < 2; ng++) {
                int br = n0 + ng * 16 + brow_l;
                ldsm_x4(bh2[2*ng][0], bh2[2*ng][1], bh2[2*ng+1][0], bh2[2*ng+1][1],
                        SWZ_ADDR(pA + A_PL, br, ks * 2 + bcb));
            }
            #pragma unroll
            for (int mt = 0; mt < 4; mt++)
                #pragma unroll
                for (int nt = 0; nt < 4; nt++)
                    mma_f16(acc[mt][nt], ah[mt], bh2[nt]);
        }
        bufc = (bufc + 1 == 3) ? 0 : bufc + 1;
        bufn = (bufn + 1 == 3) ? 0 : bufn + 1;
    }

    int rbase = rowBase + m0 + (lane >> 2);
    int cbase = colBase + n0 + (lane & 3) * 2;
    #pragma unroll
    for (int mt = 0; mt < 4; mt++) {
        #pragma unroll
        for (int half = 0; half < 2; half++) {
            int row = rbase + mt * 16 + half * 8;
            if (EPI == 0) {
                float* crow = Cf + (size_t)row * N;
                const float* rrow = res + (size_t)row * N;
                #pragma unroll
                for (int nt = 0; nt < 4; nt++) {
                    int col = cbase + nt * 8;
                    float2 o;
                    o.x = acc[mt][nt][half*2+0] + bias[col]   + rrow[col];
                    o.y = acc[mt][nt][half*2+1] + bias[col+1] + rrow[col+1];
                    *(float2*)(crow + col) = o;
                }
            } else {
                __half* hrow = Chi + (size_t)row * N;
                #pragma unroll
                for (int nt = 0; nt < 4; nt++) {
                    int col = cbase + nt * 8;
                    float v0 = acc[mt][nt][half*2+0] + bias[col];
                    float v1 = acc[mt][nt][half*2+1] + bias[col+1];
                    v0 = 0.5f * v0 * (1.0f + erff(v0 * 0.70710678118654752f));
                    v1 = 0.5f * v1 * (1.0f + erff(v1 * 0.70710678118654752f));
                    __half hh[2] = {__float2half(v0), __float2half(v1)};
                    *(uint32_t*)(hrow + col) = *(uint32_t*)hh;
                }
            }
        }
    }
}

// ---------------- launch ----------------
extern "C" void kernel_launch(void* const* d_in, const int* in_sizes, int n_in,
                              void* d_out, int out_size) {
    const float* x      = (const float*)d_in[0];
    const float* wrf    = (const float*)d_in[1];
    const float* kqv_w  = (const float*)d_in[2];
    const float* kqv_b  = (const float*)d_in[3];
    const float* proj_w = (const float*)d_in[4];
    const float* proj_b = (const float*)d_in[5];
    const float* ln1_g  = (const float*)d_in[6];
    const float* ln1_b  = (const float*)d_in[7];
    const float* ln2_g  = (const float*)d_in[8];
    const float* ln2_b  = (const float*)d_in[9];
    const float* mlp_w1 = (const float*)d_in[10];
    const float* mlp_b1 = (const float*)d_in[11];
    const float* mlp_w2 = (const float*)d_in[12];
    const float* mlp_b2 = (const float*)d_in[13];
    float* out = (float*)d_out;

    float *p_qp, *p_kp, *p_pk, *p_ps, *p_kptv, *p_ksum, *p_x1;
    __half *p_vh, *p_h2h, *p_yh, *p_hidh, *p_pwh, *p_w1h, *p_w2h, *p_kwh;
    cudaGetSymbolAddress((void**)&p_vh,   g_vh);
    cudaGetSymbolAddress((void**)&p_qp,   g_qp);
    cudaGetSymbolAddress((void**)&p_kp,   g_kp);
    cudaGetSymbolAddress((void**)&p_pk,   g_kptv_part);
    cudaGetSymbolAddress((void**)&p_ps,   g_ksum_part);
    cudaGetSymbolAddress((void**)&p_kptv, g_kptv);
    cudaGetSymbolAddress((void**)&p_ksum, g_ksum);
    cudaGetSymbolAddress((void**)&p_x1,   g_x1);
    cudaGetSymbolAddress((void**)&p_h2h,  g_h2h);
    cudaGetSymbolAddress((void**)&p_yh,   g_yh);
    cudaGetSymbolAddress((void**)&p_hidh, g_hidh);
    cudaGetSymbolAddress((void**)&p_pwh,  g_pwh);
    cudaGetSymbolAddress((void**)&p_w1h,  g_w1h);
    cudaGetSymbolAddress((void**)&p_w2h,  g_w2h);
    cudaGetSymbolAddress((void**)&p_kwh,  g_kwh);

    const size_t k1_smem = (size_t)K1_SMEM_FLOATS * sizeof(float);   // 83968B
    cudaFuncSetAttribute(kqv_prm_kernel, cudaFuncAttributeMaxDynamicSharedMemorySize,
                         (int)k1_smem);
    cudaFuncSetAttribute(gemm_mma<0>, cudaFuncAttributeMaxDynamicSharedMemorySize, GEMM_SMEM);
    cudaFuncSetAttribute(gemm_mma<1>, cudaFuncAttributeMaxDynamicSharedMemorySize, GEMM_SMEM);

    // 0. all weight fp16 rounds (one launch)
    cvt_all_kernel<<<(CVT_N4 + 255)/256, 256>>>(proj_w, mlp_w1, mlp_w2, kqv_w,
                                                p_pwh, p_w1h, p_w2h, p_kwh);
    // 1. fused LN1 + tensor kqv + prm_exp (v -> fp16)
    kqv_prm_kernel<<<NTOK/8, 256, k1_smem>>>(x, ln1_g, ln1_b, p_kwh, kqv_b, wrf,
                                             p_vh, p_kp, p_qp);
    // 2-3. kptv/ksum reduction over T
    kpt_kernel<<<dim3(16, 64), 256>>>(p_vh, p_kp, p_pk, p_ps);
    reduce_kernel<<<513, 256>>>(p_pk, p_ps, p_kptv, p_ksum);
    // 4. y
    y_kernel<<<dim3(TQ/256, 64), 256>>>(p_qp, p_kptv, p_ksum, p_yh);
    // 5. attn proj + residual -> x1 (fp32)
    gemm_mma<0><<<dim3(EMB/128, NTOK/256), 512, GEMM_SMEM>>>(
        p_yh, p_pwh, proj_b, x, p_x1, nullptr, EMB, EMB);
    // 6. LN2 -> fp16
    ln2_kernel<<<NTOK/8, 256>>>(p_x1, ln2_g, ln2_b, p_h2h);
    // 7. mlp1 + gelu -> hid (fp16)
    gemm_mma<1><<<dim3(HID/128, NTOK/256), 512, GEMM_SMEM>>>(
        p_h2h, p_w1h, mlp_b1, nullptr, nullptr, p_hidh, HID, EMB);
    // 8. mlp2 + residual -> out (fp32)
    gemm_mma<0><<<dim3(EMB/128, NTOK/256), 512, GEMM_SMEM>>>(
        p_hidh, p_w2h, mlp_b2, p_x1, out, nullptr, EMB, HID);
}

// round 15
// speedup vs baseline: 1.3057x; 1.0033x over previous
#include <cuda_runtime.h>
#include <cuda_fp16.h>
#include <math.h>
#include <stdint.h>

// Problem constants
#define BQ 8
#define TQ 4096
#define NTOK (BQ*TQ)          // 32768 tokens
#define EMB 512
#define HEADS 8
#define ES 64
#define MF 32                 // random features
#define HID (4*EMB)           // 2048
#define LN_EPS 1e-5f

__device__ __forceinline__ uint32_t smem_to_u32(const void* smem_ptr) {
    uint32_t addr;
    asm("{ .reg .u64 tmp; cvta.to.shared.u64 tmp, %1; cvt.u32.u64 %0, tmp; }"
        : "=r"(addr) : "l"(smem_ptr));
    return addr;
}

__device__ __forceinline__ void cp_async16(uint32_t saddr, const void* gaddr) {
    asm volatile("cp.async.cg.shared.global [%0], [%1], 16;" :: "r"(saddr), "l"(gaddr));
}
#define CP_COMMIT() asm volatile("cp.async.commit_group;" ::: "memory")
#define CP_WAIT0()  asm volatile("cp.async.wait_group 0;" ::: "memory")
#define CP_WAIT1()  asm volatile("cp.async.wait_group 1;" ::: "memory")

__device__ __forceinline__ void ldsm_x4(uint32_t& r0, uint32_t& r1, uint32_t& r2, uint32_t& r3,
                                        uint32_t addr) {
    asm volatile("ldmatrix.sync.aligned.m8n8.x4.shared.b16 {%0,%1,%2,%3}, [%4];"
        : "=r"(r0), "=r"(r1), "=r"(r2), "=r"(r3) : "r"(addr));
}

__device__ __forceinline__ void mma_f16(float* c, const uint32_t* a, const uint32_t* b) {
    asm volatile(
        "mma.sync.aligned.m16n8k16.row.col.f32.f16.f16.f32 "
        "{%0,%1,%2,%3}, {%4,%5,%6,%7}, {%8,%9}, {%0,%1,%2,%3};"
        : "+f"(c[0]), "+f"(c[1]), "+f"(c[2]), "+f"(c[3])
        : "r"(a[0]), "r"(a[1]), "r"(a[2]), "r"(a[3]), "r"(b[0]), "r"(b[1]));
}

// -------- scratch (device globals; no runtime allocation) --------
__device__ __align__(16) __half g_vh[(size_t)NTOK*HEADS*ES];   // v fp16
__device__ float g_qp[(size_t)NTOK*HEADS*MF];
__device__ float g_kp[(size_t)NTOK*HEADS*MF];
__device__ float g_kptv_part[16*64*ES*MF];
__device__ float g_ksum_part[16*64*MF];
__device__ float g_kptv[64*ES*MF];
__device__ float g_ksum[64*MF];
__device__ float g_x1[(size_t)NTOK*EMB];
__device__ __align__(16) __half g_h2h[(size_t)NTOK*EMB];
__device__ __align__(16) __half g_yh[(size_t)NTOK*EMB];
__device__ __align__(16) __half g_hidh[(size_t)NTOK*HID];
__device__ __align__(16) __half g_pwh[EMB*EMB];
__device__ __align__(16) __half g_w1h[HID*EMB];
__device__ __align__(16) __half g_w2h[EMB*HID];
__device__ __align__(16) __half g_kwh[192*64];   // kqv_w fp16

// ---------------- fused weight fp16 conversion (all 4 weights) ----------------
#define CVT_N4 (65536 + 262144 + 262144 + 3072)
__global__ void cvt_all_kernel(const float* __restrict__ pw, const float* __restrict__ w1,
                               const float* __restrict__ w2, const float* __restrict__ kw,
                               __half* __restrict__ pwh, __half* __restrict__ w1h,
                               __half* __restrict__ w2h, __half* __restrict__ kwh) {
    int i = blockIdx.x * 256 + threadIdx.x;
    if (i >= CVT_N4) return;
    const float* src;
    __half* dst;
    int j;
    if (i < 65536)       { src = pw; dst = pwh; j = i; }
    else if (i < 327680) { src = w1; dst = w1h; j = i - 65536; }
    else if (i < 589824) { src = w2; dst = w2h; j = i - 327680; }
    else                 { src = kw; dst = kwh; j = i - 589824; }
    float4 v = ((const float4*)src)[j];
    __half h[4];
    h[0] = __float2half(v.x); h[1] = __float2half(v.y);
    h[2] = __float2half(v.z); h[3] = __float2half(v.w);
    *(uint2*)(dst + (size_t)j*4) = *(uint2*)h;
}

// ---------------- LayerNorm (LN2): warp per token, fp16 out ----------------
__global__ void ln2_kernel(const float* __restrict__ x, const float* __restrict__ g,
                           const float* __restrict__ b, __half* __restrict__ ohi) {
    int tok  = blockIdx.x * 8 + (threadIdx.x >> 5);
    int lane = threadIdx.x & 31;
    const float4* xr = (const float4*)(x + (size_t)tok * EMB);
    float4 v[4];
    float s = 0.f, sq = 0.f;
    #pragma unroll
    for (int i = 0; i < 4; i++) {
        v[i] = xr[lane + 32*i];
        s  += v[i].x + v[i].y + v[i].z + v[i].w;
        sq += v[i].x*v[i].x + v[i].y*v[i].y + v[i].z*v[i].z + v[i].w*v[i].w;
    }
    #pragma unroll
    for (int o = 16; o; o >>= 1) {
        s  += __shfl_xor_sync(0xffffffffu, s,  o);
        sq += __shfl_xor_sync(0xffffffffu, sq, o);
    }
    float mean = s * (1.0f/EMB);
    float var  = sq * (1.0f/EMB) - mean*mean;
    float rstd = rsqrtf(var + LN_EPS);
    const float4* g4 = (const float4*)g;
    const float4* b4 = (const float4*)b;
    #pragma unroll
    for (int i = 0; i < 4; i++) {
        float4 gg = g4[lane + 32*i], bb = b4[lane + 32*i];
        size_t idx = (size_t)tok * EMB + (size_t)(lane + 32*i) * 4;
        __half h[4];
        h[0] = __float2half((v[i].x - mean) * rstd * gg.x + bb.x);
        h[1] = __float2half((v[i].y - mean) * rstd * gg.y + bb.y);
        h[2] = __float2half((v[i].z - mean) * rstd * gg.z + bb.z);
        h[3] = __float2half((v[i].w - mean) * rstd * gg.w + bb.w);
        *(uint2*)(ohi + idx) = *(uint2*)h;
    }
}

// ======== fused LN1 + tensor-core kqv + prm_exp (8 tok/block, 4 heads/pass) ========
#define SKQ_STRIDE 200
#define W16_OFF 16384
#define AHI_OFF 40960
#define ALO_OFF 45056
#define K1_SMEM_FLOATS 20992
__global__ void kqv_prm_kernel(const float* __restrict__ xg, const float* __restrict__ ln1_g,
                               const float* __restrict__ ln1_b,
                               const __half* __restrict__ kwh,
                               const float* __restrict__ kqv_b, const float* __restrict__ wrf,
                               __half* __restrict__ gvh, float* __restrict__ gkp,
                               float* __restrict__ gqp) {
    extern __shared__ float sm[];
    char* smc = (char*)sm;
    uint32_t sb = smem_to_u32(sm);
    float* sh_h  = sm;                    // [8 tok][512]
    float* wr_t  = sm + 12288;            // [64 e][32 m]
    float* sbias = wr_t + 2048;           // [192]
    float* skqv4 = sbias + 192;           // [4 hd][8 tok][SKQ_STRIDE]
    float* sxd4  = skqv4 + 6400;          // [4 hd][16]
    int tid = threadIdx.x, lane = tid & 31, wid = tid >> 5;
    size_t t0 = (size_t)blockIdx.x * 8;

    // ---- kqv_w fp16 -> smem via cp.async (192 rows x 128B, swizzled) ----
    #pragma unroll
    for (int i = 0; i < 6; i++) {
        int idx = tid + 256*i;
        int row = idx >> 3, c = idx & 7;
        cp_async16(sb + W16_OFF + (uint32_t)row*128 + (uint32_t)((c ^ (row & 7)) << 4),
                   kwh + row*64 + c*8);
    }
    CP_COMMIT();

    // ---- fused LN1: warp per token -> sh_h (fp32) ----
    {
        int tok = tid >> 5;
        const float4* xr = (const float4*)(xg + (t0 + tok) * EMB);
        float4 v[4];
        float s = 0.f, sq = 0.f;
        #pragma unroll
        for (int i = 0; i < 4; i++) {
            v[i] = xr[lane + 32*i];
            s  += v[i].x + v[i].y + v[i].z + v[i].w;
            sq += v[i].x*v[i].x + v[i].y*v[i].y + v[i].z*v[i].z + v[i].w*v[i].w;
        }
        #pragma unroll
        for (int o = 16; o; o >>= 1) {
            s  += __shfl_xor_sync(0xffffffffu, s,  o);
            sq += __shfl_xor_sync(0xffffffffu, sq, o);
        }
        float mean = s * (1.0f/EMB);
        float var  = sq * (1.0f/EMB) - mean*mean;
        float rstd = rsqrtf(var + LN_EPS);
        const float4* g4 = (const float4*)ln1_g;
        const float4* b4 = (const float4*)ln1_b;
        float4* hrow = (float4*)(sh_h + tok * 512);
        #pragma unroll
        for (int i = 0; i < 4; i++) {
            float4 gg = g4[lane + 32*i], bb = b4[lane + 32*i];
            float4 o;
            o.x = (v[i].x - mean) * rstd * gg.x + bb.x;
            o.y = (v[i].y - mean) * rstd * gg.y + bb.y;
            o.z = (v[i].z - mean) * rstd * gg.z + bb.z;
            o.w = (v[i].w - mean) * rstd * gg.w + bb.w;
            hrow[lane + 32*i] = o;
        }
    }
    // ---- wr_t [64 e][32 m] + bias ----
    #pragma unroll
    for (int i = 0; i < 2; i++) {
        int j = tid + 256*i;
        int m = j >> 4, e0 = (j & 15) << 2;
        float4 w4 = ((const float4*)wrf)[j];
        wr_t[(e0+0)*32 + m] = w4.x;
        wr_t[(e0+1)*32 + m] = w4.y;
        wr_t[(e0+2)*32 + m] = w4.z;
        wr_t[(e0+3)*32 + m] = w4.w;
    }
    if (tid < 192) sbias[tid] = kqv_b[tid];
    CP_WAIT0();
    __syncthreads();

    int wm = wid & 1, wn = wid >> 1;
    int m0 = wm * 16, n0 = wn * 48;
    int arow = m0 + (lane & 15), acb = lane >> 4;
    int brow_l = (lane & 7) + ((lane >> 4) << 3), bcb = (lane >> 3) & 1;

    for (int hg = 0; hg < 2; hg++) {
        // ---- convert A (32 rows x 64 e) to hi/lo fp16, swizzled ----
        {
            int r = tid >> 3, c = tid & 7;
            int hd4 = r >> 3, tok = r & 7;
            const float* hp = sh_h + tok*512 + (hg*4 + hd4)*64 + c*8;
            float4 f0 = *(const float4*)hp;
            float4 f1 = *(const float4*)(hp + 4);
            float vv[8] = {f0.x,f0.y,f0.z,f0.w,f1.x,f1.y,f1.z,f1.w};
            __half hi[8], lo[8];
            #pragma unroll
            for (int q = 0; q < 8; q++) {
                hi[q] = __float2half(vv[q]);
                lo[q] = __float2half(vv[q] - __half2float(hi[q]));
            }
            uint32_t off = (uint32_t)r*128 + (uint32_t)((c ^ (r & 7)) << 4);
            *(uint4*)(smc + AHI_OFF + off) = *(uint4*)hi;
            *(uint4*)(smc + ALO_OFF + off) = *(uint4*)lo;
        }
        __syncthreads();

        // ---- MMA: 2-term (hi+lo) x W16 ----
        float acc[6][4];
        #pragma unroll
        for (int nf = 0; nf < 6; nf++)
            #pragma unroll
            for (int q = 0; q < 4; q++) acc[nf][q] = 0.f;
        #pragma unroll
        for (int ks = 0; ks < 4; ks++) {
            uint32_t aoff = (uint32_t)arow*128 +
                            (uint32_t)((((ks*2 + acb)) ^ (arow & 7)) << 4);
            uint32_t ah[4], al[4];
            ldsm_x4(ah[0], ah[1], ah[2], ah[3], sb + AHI_OFF + aoff);
            ldsm_x4(al[0], al[1], al[2], al[3], sb + ALO_OFF + aoff);
            #pragma unroll
            for (int ng = 0; ng < 3; ng++) {
                int br = n0 + ng*16 + brow_l;
                uint32_t boff = (uint32_t)br*128 +
                                (uint32_t)(((ks*2 + bcb) ^ (br & 7)) << 4);
                uint32_t b2[2][2];
                ldsm_x4(b2[0][0], b2[0][1], b2[1][0], b2[1][1], sb + W16_OFF + boff);
                #pragma unroll
                for (int j = 0; j < 2; j++) {
                    mma_f16(acc[2*ng + j], ah, b2[j]);
                    mma_f16(acc[2*ng + j], al, b2[j]);
                }
            }
        }
        // ---- epilogue: acc + bias -> skqv4 ----
        {
            int rb = m0 + (lane >> 2);
            int cb = n0 + (lane & 3) * 2;
            #pragma unroll
            for (int half = 0; half < 2; half++) {
                int r = rb + half*8;
                int hd4 = r >> 3, tok = r & 7;
                float* row = skqv4 + hd4*8*SKQ_STRIDE + tok*SKQ_STRIDE;
                #pragma unroll
                for (int nf = 0; nf < 6; nf++) {
                    int col = cb + nf*8;
                    row[col]   = acc[nf][half*2+0] + sbias[col];
                    row[col+1] = acc[nf][half*2+1] + sbias[col+1];
                }
            }
        }
        __syncthreads();

        // ---- v write: 1024 half2 pairs ----
        #pragma unroll
        for (int i = 0; i < 4; i++) {
            int idx = tid + 256*i;
            int hd4 = idx >> 8, tok = (idx >> 5) & 7, e2 = idx & 31;
            const float* src = &skqv4[hd4*8*SKQ_STRIDE + tok*SKQ_STRIDE + 128 + e2*2];
            __half2 hv = __floats2half2_rn(src[0], src[1]);
            *(__half2*)&gvh[(((t0 + tok) * HEADS) + hg*4 + hd4) * ES + e2*2] = hv;
        }
        // ---- xd ----
        if (tid < 64) {
            int hd4 = tid >> 4, r = tid & 15, tok = r >> 1, which = r & 1;
            const float* z = skqv4 + hd4*8*SKQ_STRIDE + tok*SKQ_STRIDE + which*64;
            float s = 0.f;
            #pragma unroll 8
            for (int e = 0; e < 64; e++) { float zz = z[e]; s += zz*zz; }
            sxd4[hd4*16 + r] = 0.5f * s;
        }
        __syncthreads();

        // ---- wtx + exp ----
        #pragma unroll
        for (int i = 0; i < 2; i++) {
            int sidx = tid + 256*i;
            int mg = sidx & 7, which = (sidx >> 3) & 1, tok = (sidx >> 4) & 7, hd4 = sidx >> 7;
            int mq = mg * 4;
            const float* z = skqv4 + hd4*8*SKQ_STRIDE + tok*SKQ_STRIDE + which*64;
            float a0 = 0.f, a1 = 0.f, a2 = 0.f, a3 = 0.f;
            #pragma unroll 8
            for (int e = 0; e < 64; e++) {
                float zv = z[e];
                float4 w4 = *(const float4*)&wr_t[e*32 + mq];
                a0 += zv*w4.x; a1 += zv*w4.y; a2 += zv*w4.z; a3 += zv*w4.w;
            }
            float xdv = sxd4[hd4*16 + tok*2 + which];
            float4 o;
            o.x = expf(a0 - xdv) * 0.17677669529663689f;
            o.y = expf(a1 - xdv) * 0.17677669529663689f;
            o.z = expf(a2 - xdv) * 0.17677669529663689f;
            o.w = expf(a3 - xdv) * 0.17677669529663689f;
            float* dst = which ? gqp : gkp;
            *(float4*)&dst[(((t0 + tok) * HEADS) + hg*4 + hd4) * MF + mq] = o;
        }
        __syncthreads();
    }
}

// ------- kptv / ksum partial reduction over T: cp.async double-buffered -------
__global__ void kpt_kernel(const __half* __restrict__ gvh, const float* __restrict__ gkp,
                           float* __restrict__ part_kptv, float* __restrict__ part_ksum) {
    int chunk = blockIdx.x;
    int bh = blockIdx.y;
    int b = bh >> 3, h = bh & 7;
    __shared__ __half sv[2][16][64];
    __shared__ float skp[2][16][32];
    uint32_t sv_b = smem_to_u32(sv), skp_b = smem_to_u32(skp);
    int tid = threadIdx.x, lane = tid & 31, wid = tid >> 5;
    float acc[8] = {0,0,0,0,0,0,0,0};
    float ks = 0.f;
    int t0 = chunk * 256;

    auto load_stage = [&](int buf, int s0) {
        if (tid < 128) {
            int s = tid >> 3, c = tid & 7;
            cp_async16(sv_b + buf*2048 + s*128 + c*16,
                       gvh + (((size_t)b*TQ + s0 + s) * HEADS + h) * ES + c*8);
        } else {
            int r = tid - 128;
            int s = r >> 3, c = r & 7;
            cp_async16(skp_b + buf*2048 + s*128 + c*16,
                       gkp + (((size_t)b*TQ + s0 + s) * HEADS + h) * MF + c*4);
        }
    };

    load_stage(0, t0);
    CP_COMMIT();
    for (int st = 0; st < 16; st++) {
        CP_WAIT0();
        __syncthreads();
        if (st + 1 < 16) {
            load_stage((st + 1) & 1, t0 + (st + 1) * 16);
            CP_COMMIT();
        }
        int buf = st & 1;
        #pragma unroll
        for (int s = 0; s < 16; s++) {
            float kv = skp[buf][s][lane];
            uint4 vr = *(const uint4*)&sv[buf][s][wid*8];
            __half2* hp = (__half2*)&vr;
            float2 c0 = __half22float2(hp[0]);
            float2 c1 = __half22float2(hp[1]);
            float2 c2 = __half22float2(hp[2]);
            float2 c3 = __half22float2(hp[3]);
            acc[0] += c0.x*kv; acc[1] += c0.y*kv; acc[2] += c1.x*kv; acc[3] += c1.y*kv;
            acc[4] += c2.x*kv; acc[5] += c2.y*kv; acc[6] += c3.x*kv; acc[7] += c3.y*kv;
            if (wid == 0) ks += kv;
        }
    }
    size_t base = ((size_t)(chunk*64 + bh)) * (ES*MF);
    #pragma unroll
    for (int j = 0; j < 8; j++)
        part_kptv[base + (wid*8 + j)*MF + lane] = acc[j];
    if (wid == 0) part_ksum[(chunk*64 + bh)*MF + lane] = ks;
}

__global__ void reduce_kernel(const float* __restrict__ pk, const float* __restrict__ ps,
                              float* __restrict__ kptv, float* __restrict__ ksum) {
    int bid = blockIdx.x;
    if (bid < 512) {
        int idx = bid * 256 + threadIdx.x;
        int bh = idx >> 11;
        float s = 0.f;
        #pragma unroll
        for (int c = 0; c < 16; c++) s += pk[((size_t)(c*64 + bh)) * 2048 + (idx & 2047)];
        kptv[idx] = s;
    } else {
        #pragma unroll
        for (int j = 0; j < 8; j++) {
            int idx = threadIdx.x * 8 + j;
            int bh = idx >> 5, m = idx & 31;
            float s = 0.f;
            #pragma unroll
            for (int c = 0; c < 16; c++) s += ps[(c*64 + bh)*MF + m];
            ksum[idx] = s;
        }
    }
}

// ------- y = (qp . kptv) / D -> fp16: smem qp tile + precomputed 1/D -------
__global__ void y_kernel(const float* __restrict__ gqp, const float* __restrict__ kptv,
                         const float* __restrict__ ksum, __half* __restrict__ yh) {
    int bh = blockIdx.y, b = bh >> 3, h = bh & 7;
    __shared__ float sk[64*33];
    __shared__ float sks[32];
    __shared__ float sqp[256*33];
    __shared__ float sdinv[256];
    int tid = threadIdx.x, lane = tid & 31, wid = tid >> 5;
    int tbase = blockIdx.x * 256;
    #pragma unroll
    for (int i = 0; i < 8; i++) {
        int idx = tid + 256*i;
        sk[(idx >> 5)*33 + (idx & 31)] = kptv[(size_t)bh*2048 + idx];
    }
    if (tid < 32) sks[tid] = ksum[bh*32 + tid];
    #pragma unroll
    for (int i = 0; i < 8; i++) {
        int idx = tid + 256*i;
        int t = idx >> 3, mq = (idx & 7) * 4;
        float4 q4 = *(const float4*)&gqp[(((size_t)b*TQ + tbase + t) * HEADS + h) * MF + mq];
        float* row = sqp + t*33 + mq;
        row[0] = q4.x; row[1] = q4.y; row[2] = q4.z; row[3] = q4.w;
    }
    __syncthreads();
    {
        float d = 0.f;
        const float* qrow = sqp + tid*33;
        #pragma unroll 8
        for (int m = 0; m < 32; m++) d += qrow[m] * sks[m];
        sdinv[tid] = 1.0f / d;
    }
    __syncthreads();
    for (int it = 0; it < 32; it++) {
        int tl = wid * 32 + it;
        const float* qrow = sqp + tl*33;
        float a0 = 0.f, a1 = 0.f;
        #pragma unroll 8
        for (int m = 0; m < 32; m++) {
            float qm = qrow[m];
            a0 += qm * sk[lane*33 + m];
            a1 += qm * sk[(lane+32)*33 + m];
        }
        float inv = sdinv[tl];
        size_t off = ((size_t)b*TQ + tbase + tl) * EMB + h * ES;
        yh[off + lane]      = __float2half(a0 * inv);
        yh[off + lane + 32] = __float2half(a1 * inv);
    }
}

// ===== mma.sync fp16 GEMM: 256x128 CTA, 512 thr, K-super-chunk 128, ONE sync per 128k =====
// Per stage: two 48KB sub-chunks (A 32KB + B 16KB each) = 96KB; 2 stages = 192KB, 1 CTA/SM.
#define A_PL 32768
#define SUB_BYTES 49152
#define STAGE_BYTES (2*SUB_BYTES)          // 98304
#define GEMM_SMEM (2*STAGE_BYTES)          // 196608

#define SWZ_ADDR(base, row, chunk) \
    ((base) + (uint32_t)(row)*128u + (uint32_t)(((chunk) ^ ((row)&7)) << 4))

template<int EPI>
__global__ __launch_bounds__(512, 1)
void gemm_mma(const __half* __restrict__ Ah, const __half* __restrict__ Bh,
              const float* __restrict__ bias, const float* __restrict__ res,
              float* __restrict__ Cf, __half* __restrict__ Chi, int N, int K) {
    extern __shared__ char gsm[];
    uint32_t sb = smem_to_u32(gsm);
    int tid = threadIdx.x, lane = tid & 31, wid = tid >> 5;
    int rowBase = blockIdx.y * 256, colBase = blockIdx.x * 128;

    int wm = wid & 3, wn = wid >> 2;       // 4x4 warp grid
    int m0 = wm * 64, n0 = wn * 32;

    float acc[4][4][4];
    #pragma unroll
    for (int i = 0; i < 4; i++)
        #pragma unroll
        for (int j = 0; j < 4; j++)
            #pragma unroll
            for (int q = 0; q < 4; q++) acc[i][j][q] = 0.f;

    int arow_l = (lane & 15);
    int acb    = (lane >> 4);
    int brow_l = (lane & 7) + ((lane >> 4) << 3);
    int bcb    = (lane >> 3) & 1;

    // load a 128-k super-chunk (two 64-k sub-chunks) into stage buffer
    auto load_super = [&](int stg, int k0) {
        uint32_t sbase = sb + stg * STAGE_BYTES;
        // A: 256 rows x 256B = 4096 x 16B
        #pragma unroll
        for (int j = 0; j < 8; j++) {
            int idx = tid + 512*j;
            int row = idx >> 4, c = idx & 15;
            int sub = c >> 3, c128 = c & 7;
            cp_async16(SWZ_ADDR(sbase + sub*SUB_BYTES, row, c128),
                       Ah + (size_t)(rowBase + row) * K + k0 + sub*64 + c128*8);
        }
        // B: 128 rows x 256B = 2048 x 16B
        #pragma unroll
        for (int j = 0; j < 4; j++) {
            int idx = tid + 512*j;
            int row = idx >> 4, c = idx & 15;
            int sub = c >> 3, c128 = c & 7;
            cp_async16(SWZ_ADDR(sbase + sub*SUB_BYTES + A_PL, row, c128),
                       Bh + (size_t)(colBase + row) * K + k0 + sub*64 + c128*8);
        }
    };

    int NC = K >> 7;                       // 128-k chunks
    load_super(0, 0);
    CP_COMMIT();

    for (int c = 0; c < NC; c++) {
        CP_WAIT0();
        __syncthreads();
        if (c + 1 < NC) {
            load_super((c + 1) & 1, (c + 1) << 7);
            CP_COMMIT();
        }

        uint32_t pS = sb + (c & 1) * STAGE_BYTES;
        #pragma unroll
        for (int ks = 0; ks < 8; ks++) {
            uint32_t pA = pS + (ks >> 2) * SUB_BYTES;
            int kss = ks & 3;
            uint32_t ah[4][4];
            #pragma unroll
            for (int mt = 0; mt < 4; mt++) {
                int ar = m0 + mt * 16 + arow_l;
                ldsm_x4(ah[mt][0], ah[mt][1], ah[mt][2], ah[mt][3],
                        SWZ_ADDR(pA, ar, kss * 2 + acb));
            }
            uint32_t bh2[4][2];
            #pragma unroll
            for (int ng = 0; ng < 2; ng++) {
                int br = n0 + ng * 16 + brow_l;
                ldsm_x4(bh2[2*ng][0], bh2[2*ng][1], bh2[2*ng+1][0], bh2[2*ng+1][1],
                        SWZ_ADDR(pA + A_PL, br, kss * 2 + bcb));
            }
            #pragma unroll
            for (int mt = 0; mt < 4; mt++)
                #pragma unroll
                for (int nt = 0; nt < 4; nt++)
                    mma_f16(acc[mt][nt], ah[mt], bh2[nt]);
        }
    }

    int rbase = rowBase + m0 + (lane >> 2);
    int cbase = colBase + n0 + (lane & 3) * 2;
    #pragma unroll
    for (int mt = 0; mt < 4; mt++) {
        #pragma unroll
        for (int half = 0; half < 2; half++) {
            int row = rbase + mt * 16 + half * 8;
            if (EPI == 0) {
                float* crow = Cf + (size_t)row * N;
                const float* rrow = res + (size_t)row * N;
                #pragma unroll
                for (int nt = 0; nt < 4; nt++) {
                    int col = cbase + nt * 8;
                    float2 o;
                    o.x = acc[mt][nt][half*2+0] + bias[col]   + rrow[col];
                    o.y = acc[mt][nt][half*2+1] + bias[col+1] + rrow[col+1];
                    *(float2*)(crow + col) = o;
                }
            } else {
                __half* hrow = Chi + (size_t)row * N;
                #pragma unroll
                for (int nt = 0; nt < 4; nt++) {
                    int col = cbase + nt * 8;
                    float v0 = acc[mt][nt][half*2+0] + bias[col];
                    float v1 = acc[mt][nt][half*2+1] + bias[col+1];
                    v0 = 0.5f * v0 * (1.0f + erff(v0 * 0.70710678118654752f));
                    v1 = 0.5f * v1 * (1.0f + erff(v1 * 0.70710678118654752f));
                    __half hh[2] = {__float2half(v0), __float2half(v1)};
                    *(uint32_t*)(hrow + col) = *(uint32_t*)hh;
                }
            }
        }
    }
}

// ---------------- launch ----------------
extern "C" void kernel_launch(void* const* d_in, const int* in_sizes, int n_in,
                              void* d_out, int out_size) {
    const float* x      = (const float*)d_in[0];
    const float* wrf    = (const float*)d_in[1];
    const float* kqv_w  = (const float*)d_in[2];
    const float* kqv_b  = (const float*)d_in[3];
    const float* proj_w = (const float*)d_in[4];
    const float* proj_b = (const float*)d_in[5];
    const float* ln1_g  = (const float*)d_in[6];
    const float* ln1_b  = (const float*)d_in[7];
    const float* ln2_g  = (const float*)d_in[8];
    const float* ln2_b  = (const float*)d_in[9];
    const float* mlp_w1 = (const float*)d_in[10];
    const float* mlp_b1 = (const float*)d_in[11];
    const float* mlp_w2 = (const float*)d_in[12];
    const float* mlp_b2 = (const float*)d_in[13];
    float* out = (float*)d_out;

    float *p_qp, *p_kp, *p_pk, *p_ps, *p_kptv, *p_ksum, *p_x1;
    __half *p_vh, *p_h2h, *p_yh, *p_hidh, *p_pwh, *p_w1h, *p_w2h, *p_kwh;
    cudaGetSymbolAddress((void**)&p_vh,   g_vh);
    cudaGetSymbolAddress((void**)&p_qp,   g_qp);
    cudaGetSymbolAddress((void**)&p_kp,   g_kp);
    cudaGetSymbolAddress((void**)&p_pk,   g_kptv_part);
    cudaGetSymbolAddress((void**)&p_ps,   g_ksum_part);
    cudaGetSymbolAddress((void**)&p_kptv, g_kptv);
    cudaGetSymbolAddress((void**)&p_ksum, g_ksum);
    cudaGetSymbolAddress((void**)&p_x1,   g_x1);
    cudaGetSymbolAddress((void**)&p_h2h,  g_h2h);
    cudaGetSymbolAddress((void**)&p_yh,   g_yh);
    cudaGetSymbolAddress((void**)&p_hidh, g_hidh);
    cudaGetSymbolAddress((void**)&p_pwh,  g_pwh);
    cudaGetSymbolAddress((void**)&p_w1h,  g_w1h);
    cudaGetSymbolAddress((void**)&p_w2h,  g_w2h);
    cudaGetSymbolAddress((void**)&p_kwh,  g_kwh);

    const size_t k1_smem = (size_t)K1_SMEM_FLOATS * sizeof(float);   // 83968B
    cudaFuncSetAttribute(kqv_prm_kernel, cudaFuncAttributeMaxDynamicSharedMemorySize,
                         (int)k1_smem);
    cudaFuncSetAttribute(gemm_mma<0>, cudaFuncAttributeMaxDynamicSharedMemorySize, GEMM_SMEM);
    cudaFuncSetAttribute(gemm_mma<1>, cudaFuncAttributeMaxDynamicSharedMemorySize, GEMM_SMEM);

    // 0. all weight fp16 rounds (one launch)
    cvt_all_kernel<<<(CVT_N4 + 255)/256, 256>>>(proj_w, mlp_w1, mlp_w2, kqv_w,
                                                p_pwh, p_w1h, p_w2h, p_kwh);
    // 1. fused LN1 + tensor kqv + prm_exp (v -> fp16)
    kqv_prm_kernel<<<NTOK/8, 256, k1_smem>>>(x, ln1_g, ln1_b, p_kwh, kqv_b, wrf,
                                             p_vh, p_kp, p_qp);
    // 2-3. kptv/ksum reduction over T
    kpt_kernel<<<dim3(16, 64), 256>>>(p_vh, p_kp, p_pk, p_ps);
    reduce_kernel<<<513, 256>>>(p_pk, p_ps, p_kptv, p_ksum);
    // 4. y
    y_kernel<<<dim3(TQ/256, 64), 256>>>(p_qp, p_kptv, p_ksum, p_yh);
    // 5. attn proj + residual -> x1 (fp32)
    gemm_mma<0><<<dim3(EMB/128, NTOK/256), 512, GEMM_SMEM>>>(
        p_yh, p_pwh, proj_b, x, p_x1, nullptr, EMB, EMB);
    // 6. LN2 -> fp16
    ln2_kernel<<<NTOK/8, 256>>>(p_x1, ln2_g, ln2_b, p_h2h);
    // 7. mlp1 + gelu -> hid (fp16)
    gemm_mma<1><<<dim3(HID/128, NTOK/256), 512, GEMM_SMEM>>>(
        p_h2h, p_w1h, mlp_b1, nullptr, nullptr, p_hidh, HID, EMB);
    // 8. mlp2 + residual -> out (fp32)
    gemm_mma<0><<<dim3(EMB/128, NTOK/256), 512, GEMM_SMEM>>>(
        p_hidh, p_w2h, mlp_b2, p_x1, out, nullptr, EMB, HID);
}

// round 16
// speedup vs baseline: 1.3206x; 1.0114x over previous
#include <cuda_runtime.h>
#include <cuda_fp16.h>
#include <math.h>
#include <stdint.h>

// Problem constants
#define BQ 8
#define TQ 4096
#define NTOK (BQ*TQ)          // 32768 tokens
#define EMB 512
#define HEADS 8
#define ES 64
#define MF 32                 // random features
#define HID (4*EMB)           // 2048
#define LN_EPS 1e-5f

__device__ __forceinline__ uint32_t smem_to_u32(const void* smem_ptr) {
    uint32_t addr;
    asm("{ .reg .u64 tmp; cvta.to.shared.u64 tmp, %1; cvt.u32.u64 %0, tmp; }"
        : "=r"(addr) : "l"(smem_ptr));
    return addr;
}

__device__ __forceinline__ void cp_async16(uint32_t saddr, const void* gaddr) {
    asm volatile("cp.async.cg.shared.global [%0], [%1], 16;" :: "r"(saddr), "l"(gaddr));
}
#define CP_COMMIT() asm volatile("cp.async.commit_group;" ::: "memory")
#define CP_WAIT0()  asm volatile("cp.async.wait_group 0;" ::: "memory")
#define CP_WAIT1()  asm volatile("cp.async.wait_group 1;" ::: "memory")

__device__ __forceinline__ void ldsm_x4(uint32_t& r0, uint32_t& r1, uint32_t& r2, uint32_t& r3,
                                        uint32_t addr) {
    asm volatile("ldmatrix.sync.aligned.m8n8.x4.shared.b16 {%0,%1,%2,%3}, [%4];"
        : "=r"(r0), "=r"(r1), "=r"(r2), "=r"(r3) : "r"(addr));
}

__device__ __forceinline__ void mma_f16(float* c, const uint32_t* a, const uint32_t* b) {
    asm volatile(
        "mma.sync.aligned.m16n8k16.row.col.f32.f16.f16.f32 "
        "{%0,%1,%2,%3}, {%4,%5,%6,%7}, {%8,%9}, {%0,%1,%2,%3};"
        : "+f"(c[0]), "+f"(c[1]), "+f"(c[2]), "+f"(c[3])
        : "r"(a[0]), "r"(a[1]), "r"(a[2]), "r"(a[3]), "r"(b[0]), "r"(b[1]));
}

// -------- scratch (device globals; no runtime allocation) --------
__device__ __align__(16) __half g_vh[(size_t)NTOK*HEADS*ES];   // v fp16
__device__ float g_qp[(size_t)NTOK*HEADS*MF];
__device__ float g_kp[(size_t)NTOK*HEADS*MF];
__device__ float g_kptv_part[8*64*ES*MF];
__device__ float g_ksum_part[8*64*MF];
__device__ float g_kptv[64*ES*MF];
__device__ float g_ksum[64*MF];
__device__ float g_x1[(size_t)NTOK*EMB];
__device__ __align__(16) __half g_h2h[(size_t)NTOK*EMB];
__device__ __align__(16) __half g_yh[(size_t)NTOK*EMB];
__device__ __align__(16) __half g_hidh[(size_t)NTOK*HID];
__device__ __align__(16) __half g_pwh[EMB*EMB];
__device__ __align__(16) __half g_w1h[HID*EMB];
__device__ __align__(16) __half g_w2h[EMB*HID];
__device__ __align__(16) __half g_kwh[192*64];   // kqv_w fp16

// ---------------- fused weight fp16 conversion (all 4 weights) ----------------
#define CVT_N4 (65536 + 262144 + 262144 + 3072)
__global__ void cvt_all_kernel(const float* __restrict__ pw, const float* __restrict__ w1,
                               const float* __restrict__ w2, const float* __restrict__ kw,
                               __half* __restrict__ pwh, __half* __restrict__ w1h,
                               __half* __restrict__ w2h, __half* __restrict__ kwh) {
    int i = blockIdx.x * 256 + threadIdx.x;
    if (i >= CVT_N4) return;
    const float* src;
    __half* dst;
    int j;
    if (i < 65536)       { src = pw; dst = pwh; j = i; }
    else if (i < 327680) { src = w1; dst = w1h; j = i - 65536; }
    else if (i < 589824) { src = w2; dst = w2h; j = i - 327680; }
    else                 { src = kw; dst = kwh; j = i - 589824; }
    float4 v = ((const float4*)src)[j];
    __half h[4];
    h[0] = __float2half(v.x); h[1] = __float2half(v.y);
    h[2] = __float2half(v.z); h[3] = __float2half(v.w);
    *(uint2*)(dst + (size_t)j*4) = *(uint2*)h;
}

// ---------------- LayerNorm (LN2): warp per token, fp16 out ----------------
__global__ void ln2_kernel(const float* __restrict__ x, const float* __restrict__ g,
                           const float* __restrict__ b, __half* __restrict__ ohi) {
    int tok  = blockIdx.x * 8 + (threadIdx.x >> 5);
    int lane = threadIdx.x & 31;
    const float4* xr = (const float4*)(x + (size_t)tok * EMB);
    float4 v[4];
    float s = 0.f, sq = 0.f;
    #pragma unroll
    for (int i = 0; i < 4; i++) {
        v[i] = xr[lane + 32*i];
        s  += v[i].x + v[i].y + v[i].z + v[i].w;
        sq += v[i].x*v[i].x + v[i].y*v[i].y + v[i].z*v[i].z + v[i].w*v[i].w;
    }
    #pragma unroll
    for (int o = 16; o; o >>= 1) {
        s  += __shfl_xor_sync(0xffffffffu, s,  o);
        sq += __shfl_xor_sync(0xffffffffu, sq, o);
    }
    float mean = s * (1.0f/EMB);
    float var  = sq * (1.0f/EMB) - mean*mean;
    float rstd = rsqrtf(var + LN_EPS);
    const float4* g4 = (const float4*)g;
    const float4* b4 = (const float4*)b;
    #pragma unroll
    for (int i = 0; i < 4; i++) {
        float4 gg = g4[lane + 32*i], bb = b4[lane + 32*i];
        size_t idx = (size_t)tok * EMB + (size_t)(lane + 32*i) * 4;
        __half h[4];
        h[0] = __float2half((v[i].x - mean) * rstd * gg.x + bb.x);
        h[1] = __float2half((v[i].y - mean) * rstd * gg.y + bb.y);
        h[2] = __float2half((v[i].z - mean) * rstd * gg.z + bb.z);
        h[3] = __float2half((v[i].w - mean) * rstd * gg.w + bb.w);
        *(uint2*)(ohi + idx) = *(uint2*)h;
    }
}

// ======== fused LN1 + tensor-core kqv + prm_exp (8 tok/block, 4 heads/pass) ========
#define SKQ_STRIDE 200
#define W16_OFF 16384
#define AHI_OFF 40960
#define ALO_OFF 45056
#define K1_SMEM_FLOATS 20992
__global__ void kqv_prm_kernel(const float* __restrict__ xg, const float* __restrict__ ln1_g,
                               const float* __restrict__ ln1_b,
                               const __half* __restrict__ kwh,
                               const float* __restrict__ kqv_b, const float* __restrict__ wrf,
                               __half* __restrict__ gvh, float* __restrict__ gkp,
                               float* __restrict__ gqp) {
    extern __shared__ float sm[];
    char* smc = (char*)sm;
    uint32_t sb = smem_to_u32(sm);
    float* sh_h  = sm;                    // [8 tok][512]
    float* wr_t  = sm + 12288;            // [64 e][32 m]
    float* sbias = wr_t + 2048;           // [192]
    float* skqv4 = sbias + 192;           // [4 hd][8 tok][SKQ_STRIDE]
    float* sxd4  = skqv4 + 6400;          // [4 hd][16]
    int tid = threadIdx.x, lane = tid & 31, wid = tid >> 5;
    size_t t0 = (size_t)blockIdx.x * 8;

    // ---- kqv_w fp16 -> smem via cp.async (192 rows x 128B, swizzled) ----
    #pragma unroll
    for (int i = 0; i < 6; i++) {
        int idx = tid + 256*i;
        int row = idx >> 3, c = idx & 7;
        cp_async16(sb + W16_OFF + (uint32_t)row*128 + (uint32_t)((c ^ (row & 7)) << 4),
                   kwh + row*64 + c*8);
    }
    CP_COMMIT();

    // ---- fused LN1: warp per token -> sh_h (fp32) ----
    {
        int tok = tid >> 5;
        const float4* xr = (const float4*)(xg + (t0 + tok) * EMB);
        float4 v[4];
        float s = 0.f, sq = 0.f;
        #pragma unroll
        for (int i = 0; i < 4; i++) {
            v[i] = xr[lane + 32*i];
            s  += v[i].x + v[i].y + v[i].z + v[i].w;
            sq += v[i].x*v[i].x + v[i].y*v[i].y + v[i].z*v[i].z + v[i].w*v[i].w;
        }
        #pragma unroll
        for (int o = 16; o; o >>= 1) {
            s  += __shfl_xor_sync(0xffffffffu, s,  o);
            sq += __shfl_xor_sync(0xffffffffu, sq, o);
        }
        float mean = s * (1.0f/EMB);
        float var  = sq * (1.0f/EMB) - mean*mean;
        float rstd = rsqrtf(var + LN_EPS);
        const float4* g4 = (const float4*)ln1_g;
        const float4* b4 = (const float4*)ln1_b;
        float4* hrow = (float4*)(sh_h + tok * 512);
        #pragma unroll
        for (int i = 0; i < 4; i++) {
            float4 gg = g4[lane + 32*i], bb = b4[lane + 32*i];
            float4 o;
            o.x = (v[i].x - mean) * rstd * gg.x + bb.x;
            o.y = (v[i].y - mean) * rstd * gg.y + bb.y;
            o.z = (v[i].z - mean) * rstd * gg.z + bb.z;
            o.w = (v[i].w - mean) * rstd * gg.w + bb.w;
            hrow[lane + 32*i] = o;
        }
    }
    // ---- wr_t [64 e][32 m] + bias ----
    #pragma unroll
    for (int i = 0; i < 2; i++) {
        int j = tid + 256*i;
        int m = j >> 4, e0 = (j & 15) << 2;
        float4 w4 = ((const float4*)wrf)[j];
        wr_t[(e0+0)*32 + m] = w4.x;
        wr_t[(e0+1)*32 + m] = w4.y;
        wr_t[(e0+2)*32 + m] = w4.z;
        wr_t[(e0+3)*32 + m] = w4.w;
    }
    if (tid < 192) sbias[tid] = kqv_b[tid];
    CP_WAIT0();
    __syncthreads();

    int wm = wid & 1, wn = wid >> 1;
    int m0 = wm * 16, n0 = wn * 48;
    int arow = m0 + (lane & 15), acb = lane >> 4;
    int brow_l = (lane & 7) + ((lane >> 4) << 3), bcb = (lane >> 3) & 1;

    for (int hg = 0; hg < 2; hg++) {
        // ---- convert A (32 rows x 64 e) to hi/lo fp16, swizzled ----
        {
            int r = tid >> 3, c = tid & 7;
            int hd4 = r >> 3, tok = r & 7;
            const float* hp = sh_h + tok*512 + (hg*4 + hd4)*64 + c*8;
            float4 f0 = *(const float4*)hp;
            float4 f1 = *(const float4*)(hp + 4);
            float vv[8] = {f0.x,f0.y,f0.z,f0.w,f1.x,f1.y,f1.z,f1.w};
            __half hi[8], lo[8];
            #pragma unroll
            for (int q = 0; q < 8; q++) {
                hi[q] = __float2half(vv[q]);
                lo[q] = __float2half(vv[q] - __half2float(hi[q]));
            }
            uint32_t off = (uint32_t)r*128 + (uint32_t)((c ^ (r & 7)) << 4);
            *(uint4*)(smc + AHI_OFF + off) = *(uint4*)hi;
            *(uint4*)(smc + ALO_OFF + off) = *(uint4*)lo;
        }
        __syncthreads();

        // ---- MMA: 2-term (hi+lo) x W16 ----
        float acc[6][4];
        #pragma unroll
        for (int nf = 0; nf < 6; nf++)
            #pragma unroll
            for (int q = 0; q < 4; q++) acc[nf][q] = 0.f;
        #pragma unroll
        for (int ks = 0; ks < 4; ks++) {
            uint32_t aoff = (uint32_t)arow*128 +
                            (uint32_t)((((ks*2 + acb)) ^ (arow & 7)) << 4);
            uint32_t ah[4], al[4];
            ldsm_x4(ah[0], ah[1], ah[2], ah[3], sb + AHI_OFF + aoff);
            ldsm_x4(al[0], al[1], al[2], al[3], sb + ALO_OFF + aoff);
            #pragma unroll
            for (int ng = 0; ng < 3; ng++) {
                int br = n0 + ng*16 + brow_l;
                uint32_t boff = (uint32_t)br*128 +
                                (uint32_t)(((ks*2 + bcb) ^ (br & 7)) << 4);
                uint32_t b2[2][2];
                ldsm_x4(b2[0][0], b2[0][1], b2[1][0], b2[1][1], sb + W16_OFF + boff);
                #pragma unroll
                for (int j = 0; j < 2; j++) {
                    mma_f16(acc[2*ng + j], ah, b2[j]);
                    mma_f16(acc[2*ng + j], al, b2[j]);
                }
            }
        }
        // ---- epilogue: acc + bias -> skqv4 ----
        {
            int rb = m0 + (lane >> 2);
            int cb = n0 + (lane & 3) * 2;
            #pragma unroll
            for (int half = 0; half < 2; half++) {
                int r = rb + half*8;
                int hd4 = r >> 3, tok = r & 7;
                float* row = skqv4 + hd4*8*SKQ_STRIDE + tok*SKQ_STRIDE;
                #pragma unroll
                for (int nf = 0; nf < 6; nf++) {
                    int col = cb + nf*8;
                    row[col]   = acc[nf][half*2+0] + sbias[col];
                    row[col+1] = acc[nf][half*2+1] + sbias[col+1];
                }
            }
        }
        __syncthreads();

        // ---- v write: 1024 half2 pairs ----
        #pragma unroll
        for (int i = 0; i < 4; i++) {
            int idx = tid + 256*i;
            int hd4 = idx >> 8, tok = (idx >> 5) & 7, e2 = idx & 31;
            const float* src = &skqv4[hd4*8*SKQ_STRIDE + tok*SKQ_STRIDE + 128 + e2*2];
            __half2 hv = __floats2half2_rn(src[0], src[1]);
            *(__half2*)&gvh[(((t0 + tok) * HEADS) + hg*4 + hd4) * ES + e2*2] = hv;
        }
        // ---- xd ----
        if (tid < 64) {
            int hd4 = tid >> 4, r = tid & 15, tok = r >> 1, which = r & 1;
            const float* z = skqv4 + hd4*8*SKQ_STRIDE + tok*SKQ_STRIDE + which*64;
            float s = 0.f;
            #pragma unroll 8
            for (int e = 0; e < 64; e++) { float zz = z[e]; s += zz*zz; }
            sxd4[hd4*16 + r] = 0.5f * s;
        }
        __syncthreads();

        // ---- wtx + exp ----
        #pragma unroll
        for (int i = 0; i < 2; i++) {
            int sidx = tid + 256*i;
            int mg = sidx & 7, which = (sidx >> 3) & 1, tok = (sidx >> 4) & 7, hd4 = sidx >> 7;
            int mq = mg * 4;
            const float* z = skqv4 + hd4*8*SKQ_STRIDE + tok*SKQ_STRIDE + which*64;
            float a0 = 0.f, a1 = 0.f, a2 = 0.f, a3 = 0.f;
            #pragma unroll 8
            for (int e = 0; e < 64; e++) {
                float zv = z[e];
                float4 w4 = *(const float4*)&wr_t[e*32 + mq];
                a0 += zv*w4.x; a1 += zv*w4.y; a2 += zv*w4.z; a3 += zv*w4.w;
            }
            float xdv = sxd4[hd4*16 + tok*2 + which];
            float4 o;
            o.x = expf(a0 - xdv) * 0.17677669529663689f;
            o.y = expf(a1 - xdv) * 0.17677669529663689f;
            o.z = expf(a2 - xdv) * 0.17677669529663689f;
            o.w = expf(a3 - xdv) * 0.17677669529663689f;
            float* dst = which ? gqp : gkp;
            *(float4*)&dst[(((t0 + tok) * HEADS) + hg*4 + hd4) * MF + mq] = o;
        }
        __syncthreads();
    }
}

// ------- kptv / ksum reduction over T: 8 chunks x 512 steps, 32-step stages -------
__global__ void kpt_kernel(const __half* __restrict__ gvh, const float* __restrict__ gkp,
                           float* __restrict__ part_kptv, float* __restrict__ part_ksum) {
    int chunk = blockIdx.x;            // 0..7
    int bh = blockIdx.y;
    int b = bh >> 3, h = bh & 7;
    __shared__ __half sv[2][32][64];   // 2 x 4096 B
    __shared__ float skp[2][32][32];   // 2 x 4096 B
    uint32_t sv_b = smem_to_u32(sv), skp_b = smem_to_u32(skp);
    int tid = threadIdx.x, lane = tid & 31, wid = tid >> 5;
    float acc[8] = {0,0,0,0,0,0,0,0};
    float ks = 0.f;
    int t0 = chunk * 512;

    auto load_stage = [&](int buf, int s0) {
        int s = tid >> 3, c = tid & 7;     // 32 rows x 8
        size_t gtok = (size_t)b*TQ + s0 + s;
        cp_async16(sv_b  + buf*4096 + s*128 + c*16, gvh + (gtok * HEADS + h) * ES + c*8);
        cp_async16(skp_b + buf*4096 + s*128 + c*16, gkp + (gtok * HEADS + h) * MF + c*4);
    };

    load_stage(0, t0);
    CP_COMMIT();
    for (int st = 0; st < 16; st++) {
        CP_WAIT0();
        __syncthreads();
        if (st + 1 < 16) {
            load_stage((st + 1) & 1, t0 + (st + 1) * 32);
            CP_COMMIT();
        }
        int buf = st & 1;
        #pragma unroll
        for (int s = 0; s < 32; s++) {
            float kv = skp[buf][s][lane];
            uint4 vr = *(const uint4*)&sv[buf][s][wid*8];
            __half2* hp = (__half2*)&vr;
            float2 c0 = __half22float2(hp[0]);
            float2 c1 = __half22float2(hp[1]);
            float2 c2 = __half22float2(hp[2]);
            float2 c3 = __half22float2(hp[3]);
            acc[0] += c0.x*kv; acc[1] += c0.y*kv; acc[2] += c1.x*kv; acc[3] += c1.y*kv;
            acc[4] += c2.x*kv; acc[5] += c2.y*kv; acc[6] += c3.x*kv; acc[7] += c3.y*kv;
            if (wid == 0) ks += kv;
        }
    }
    size_t base = ((size_t)(chunk*64 + bh)) * (ES*MF);
    #pragma unroll
    for (int j = 0; j < 8; j++)
        part_kptv[base + (wid*8 + j)*MF + lane] = acc[j];
    if (wid == 0) part_ksum[(chunk*64 + bh)*MF + lane] = ks;
}

__global__ void reduce_kernel(const float* __restrict__ pk, const float* __restrict__ ps,
                              float* __restrict__ kptv, float* __restrict__ ksum) {
    int bid = blockIdx.x;
    if (bid < 512) {
        int idx = bid * 256 + threadIdx.x;
        int bh = idx >> 11;
        float s = 0.f;
        #pragma unroll
        for (int c = 0; c < 8; c++) s += pk[((size_t)(c*64 + bh)) * 2048 + (idx & 2047)];
        kptv[idx] = s;
    } else {
        #pragma unroll
        for (int j = 0; j < 8; j++) {
            int idx = threadIdx.x * 8 + j;
            int bh = idx >> 5, m = idx & 31;
            float s = 0.f;
            #pragma unroll
            for (int c = 0; c < 8; c++) s += ps[(c*64 + bh)*MF + m];
            ksum[idx] = s;
        }
    }
}

// ------- y = (qp . kptv) / D -> fp16: smem qp tile + precomputed 1/D -------
__global__ void y_kernel(const float* __restrict__ gqp, const float* __restrict__ kptv,
                         const float* __restrict__ ksum, __half* __restrict__ yh) {
    int bh = blockIdx.y, b = bh >> 3, h = bh & 7;
    __shared__ float sk[64*33];
    __shared__ float sks[32];
    __shared__ float sqp[256*33];
    __shared__ float sdinv[256];
    int tid = threadIdx.x, lane = tid & 31, wid = tid >> 5;
    int tbase = blockIdx.x * 256;
    #pragma unroll
    for (int i = 0; i < 8; i++) {
        int idx = tid + 256*i;
        sk[(idx >> 5)*33 + (idx & 31)] = kptv[(size_t)bh*2048 + idx];
    }
    if (tid < 32) sks[tid] = ksum[bh*32 + tid];
    #pragma unroll
    for (int i = 0; i < 8; i++) {
        int idx = tid + 256*i;
        int t = idx >> 3, mq = (idx & 7) * 4;
        float4 q4 = *(const float4*)&gqp[(((size_t)b*TQ + tbase + t) * HEADS + h) * MF + mq];
        float* row = sqp + t*33 + mq;
        row[0] = q4.x; row[1] = q4.y; row[2] = q4.z; row[3] = q4.w;
    }
    __syncthreads();
    {
        float d = 0.f;
        const float* qrow = sqp + tid*33;
        #pragma unroll 8
        for (int m = 0; m < 32; m++) d += qrow[m] * sks[m];
        sdinv[tid] = 1.0f / d;
    }
    __syncthreads();
    for (int it = 0; it < 32; it++) {
        int tl = wid * 32 + it;
        const float* qrow = sqp + tl*33;
        float a0 = 0.f, a1 = 0.f;
        #pragma unroll 8
        for (int m = 0; m < 32; m++) {
            float qm = qrow[m];
            a0 += qm * sk[lane*33 + m];
            a1 += qm * sk[(lane+32)*33 + m];
        }
        float inv = sdinv[tl];
        size_t off = ((size_t)b*TQ + tbase + tl) * EMB + h * ES;
        yh[off + lane]      = __float2half(a0 * inv);
        yh[off + lane + 32] = __float2half(a1 * inv);
    }
}

// ===== mma.sync fp16 GEMM: 256x128 CTA, 512 thr, K-super-chunk 128, compile-time N/K =====
#define A_PL 32768
#define SUB_BYTES 49152
#define STAGE_BYTES (2*SUB_BYTES)          // 98304
#define GEMM_SMEM (2*STAGE_BYTES)          // 196608

#define SWZ_ADDR(base, row, chunk) \
    ((base) + (uint32_t)(row)*128u + (uint32_t)(((chunk) ^ ((row)&7)) << 4))

template<int EPI, int NN, int KK>
__global__ __launch_bounds__(512, 1)
void gemm_mma(const __half* __restrict__ Ah, const __half* __restrict__ Bh,
              const float* __restrict__ bias, const float* __restrict__ res,
              float* __restrict__ Cf, __half* __restrict__ Chi) {
    extern __shared__ char gsm[];
    uint32_t sb = smem_to_u32(gsm);
    int tid = threadIdx.x, lane = tid & 31, wid = tid >> 5;
    int rowBase = blockIdx.y * 256, colBase = blockIdx.x * 128;

    int wm = wid & 3, wn = wid >> 2;       // 4x4 warp grid
    int m0 = wm * 64, n0 = wn * 32;

    float acc[4][4][4];
    #pragma unroll
    for (int i = 0; i < 4; i++)
        #pragma unroll
        for (int j = 0; j < 4; j++)
            #pragma unroll
            for (int q = 0; q < 4; q++) acc[i][j][q] = 0.f;

    int arow_l = (lane & 15);
    int acb    = (lane >> 4);
    int brow_l = (lane & 7) + ((lane >> 4) << 3);
    int bcb    = (lane >> 3) & 1;

    auto load_super = [&](int stg, int k0) {
        uint32_t sbase = sb + stg * STAGE_BYTES;
        #pragma unroll
        for (int j = 0; j < 8; j++) {
            int idx = tid + 512*j;
            int row = idx >> 4, c = idx & 15;
            int sub = c >> 3, c128 = c & 7;
            cp_async16(SWZ_ADDR(sbase + sub*SUB_BYTES, row, c128),
                       Ah + (size_t)(rowBase + row) * KK + k0 + sub*64 + c128*8);
        }
        #pragma unroll
        for (int j = 0; j < 4; j++) {
            int idx = tid + 512*j;
            int row = idx >> 4, c = idx & 15;
            int sub = c >> 3, c128 = c & 7;
            cp_async16(SWZ_ADDR(sbase + sub*SUB_BYTES + A_PL, row, c128),
                       Bh + (size_t)(colBase + row) * KK + k0 + sub*64 + c128*8);
        }
    };

    constexpr int NC = KK >> 7;
    load_super(0, 0);
    CP_COMMIT();

    #pragma unroll 2
    for (int c = 0; c < NC; c++) {
        CP_WAIT0();
        __syncthreads();
        if (c + 1 < NC) {
            load_super((c + 1) & 1, (c + 1) << 7);
            CP_COMMIT();
        }

        uint32_t pS = sb + (c & 1) * STAGE_BYTES;
        #pragma unroll
        for (int ks = 0; ks < 8; ks++) {
            uint32_t pA = pS + (ks >> 2) * SUB_BYTES;
            int kss = ks & 3;
            uint32_t ah[4][4];
            #pragma unroll
            for (int mt = 0; mt < 4; mt++) {
                int ar = m0 + mt * 16 + arow_l;
                ldsm_x4(ah[mt][0], ah[mt][1], ah[mt][2], ah[mt][3],
                        SWZ_ADDR(pA, ar, kss * 2 + acb));
            }
            uint32_t bh2[4][2];
            #pragma unroll
            for (int ng = 0; ng < 2; ng++) {
                int br = n0 + ng * 16 + brow_l;
                ldsm_x4(bh2[2*ng][0], bh2[2*ng][1], bh2[2*ng+1][0], bh2[2*ng+1][1],
                        SWZ_ADDR(pA + A_PL, br, kss * 2 + bcb));
            }
            #pragma unroll
            for (int mt = 0; mt < 4; mt++)
                #pragma unroll
                for (int nt = 0; nt < 4; nt++)
                    mma_f16(acc[mt][nt], ah[mt], bh2[nt]);
        }
    }

    int rbase = rowBase + m0 + (lane >> 2);
    int cbase = colBase + n0 + (lane & 3) * 2;
    #pragma unroll
    for (int mt = 0; mt < 4; mt++) {
        #pragma unroll
        for (int half = 0; half < 2; half++) {
            int row = rbase + mt * 16 + half * 8;
            if (EPI == 0) {
                float* crow = Cf + (size_t)row * NN;
                const float* rrow = res + (size_t)row * NN;
                #pragma unroll
                for (int nt = 0; nt < 4; nt++) {
                    int col = cbase + nt * 8;
                    float2 o;
                    o.x = acc[mt][nt][half*2+0] + bias[col]   + rrow[col];
                    o.y = acc[mt][nt][half*2+1] + bias[col+1] + rrow[col+1];
                    *(float2*)(crow + col) = o;
                }
            } else {
                __half* hrow = Chi + (size_t)row * NN;
                #pragma unroll
                for (int nt = 0; nt < 4; nt++) {
                    int col = cbase + nt * 8;
                    float v0 = acc[mt][nt][half*2+0] + bias[col];
                    float v1 = acc[mt][nt][half*2+1] + bias[col+1];
                    v0 = 0.5f * v0 * (1.0f + erff(v0 * 0.70710678118654752f));
                    v1 = 0.5f * v1 * (1.0f + erff(v1 * 0.70710678118654752f));
                    __half hh[2] = {__float2half(v0), __float2half(v1)};
                    *(uint32_t*)(hrow + col) = *(uint32_t*)hh;
                }
            }
        }
    }
}

// ---------------- launch ----------------
extern "C" void kernel_launch(void* const* d_in, const int* in_sizes, int n_in,
                              void* d_out, int out_size) {
    const float* x      = (const float*)d_in[0];
    const float* wrf    = (const float*)d_in[1];
    const float* kqv_w  = (const float*)d_in[2];
    const float* kqv_b  = (const float*)d_in[3];
    const float* proj_w = (const float*)d_in[4];
    const float* proj_b = (const float*)d_in[5];
    const float* ln1_g  = (const float*)d_in[6];
    const float* ln1_b  = (const float*)d_in[7];
    const float* ln2_g  = (const float*)d_in[8];
    const float* ln2_b  = (const float*)d_in[9];
    const float* mlp_w1 = (const float*)d_in[10];
    const float* mlp_b1 = (const float*)d_in[11];
    const float* mlp_w2 = (const float*)d_in[12];
    const float* mlp_b2 = (const float*)d_in[13];
    float* out = (float*)d_out;

    float *p_qp, *p_kp, *p_pk, *p_ps, *p_kptv, *p_ksum, *p_x1;
    __half *p_vh, *p_h2h, *p_yh, *p_hidh, *p_pwh, *p_w1h, *p_w2h, *p_kwh;
    cudaGetSymbolAddress((void**)&p_vh,   g_vh);
    cudaGetSymbolAddress((void**)&p_qp,   g_qp);
    cudaGetSymbolAddress((void**)&p_kp,   g_kp);
    cudaGetSymbolAddress((void**)&p_pk,   g_kptv_part);
    cudaGetSymbolAddress((void**)&p_ps,   g_ksum_part);
    cudaGetSymbolAddress((void**)&p_kptv, g_kptv);
    cudaGetSymbolAddress((void**)&p_ksum, g_ksum);
    cudaGetSymbolAddress((void**)&p_x1,   g_x1);
    cudaGetSymbolAddress((void**)&p_h2h,  g_h2h);
    cudaGetSymbolAddress((void**)&p_yh,   g_yh);
    cudaGetSymbolAddress((void**)&p_hidh, g_hidh);
    cudaGetSymbolAddress((void**)&p_pwh,  g_pwh);
    cudaGetSymbolAddress((void**)&p_w1h,  g_w1h);
    cudaGetSymbolAddress((void**)&p_w2h,  g_w2h);
    cudaGetSymbolAddress((void**)&p_kwh,  g_kwh);

    const size_t k1_smem = (size_t)K1_SMEM_FLOATS * sizeof(float);   // 83968B
    cudaFuncSetAttribute(kqv_prm_kernel, cudaFuncAttributeMaxDynamicSharedMemorySize,
                         (int)k1_smem);
    cudaFuncSetAttribute((const void*)gemm_mma<0,EMB,EMB>,
                         cudaFuncAttributeMaxDynamicSharedMemorySize, GEMM_SMEM);
    cudaFuncSetAttribute((const void*)gemm_mma<1,HID,EMB>,
                         cudaFuncAttributeMaxDynamicSharedMemorySize, GEMM_SMEM);
    cudaFuncSetAttribute((const void*)gemm_mma<0,EMB,HID>,
                         cudaFuncAttributeMaxDynamicSharedMemorySize, GEMM_SMEM);

    // 0. all weight fp16 rounds (one launch)
    cvt_all_kernel<<<(CVT_N4 + 255)/256, 256>>>(proj_w, mlp_w1, mlp_w2, kqv_w,
                                                p_pwh, p_w1h, p_w2h, p_kwh);
    // 1. fused LN1 + tensor kqv + prm_exp (v -> fp16)
    kqv_prm_kernel<<<NTOK/8, 256, k1_smem>>>(x, ln1_g, ln1_b, p_kwh, kqv_b, wrf,
                                             p_vh, p_kp, p_qp);
    // 2-3. kptv/ksum reduction over T (8 chunks x 512 steps)
    kpt_kernel<<<dim3(8, 64), 256>>>(p_vh, p_kp, p_pk, p_ps);
    reduce_kernel<<<513, 256>>>(p_pk, p_ps, p_kptv, p_ksum);
    // 4. y
    y_kernel<<<dim3(TQ/256, 64), 256>>>(p_qp, p_kptv, p_ksum, p_yh);
    // 5. attn proj + residual -> x1 (fp32)
    gemm_mma<0,EMB,EMB><<<dim3(EMB/128, NTOK/256), 512, GEMM_SMEM>>>(
        p_yh, p_pwh, proj_b, x, p_x1, nullptr);
    // 6. LN2 -> fp16
    ln2_kernel<<<NTOK/8, 256>>>(p_x1, ln2_g, ln2_b, p_h2h);
    // 7. mlp1 + gelu -> hid (fp16)
    gemm_mma<1,HID,EMB><<<dim3(HID/128, NTOK/256), 512, GEMM_SMEM>>>(
        p_h2h, p_w1h, mlp_b1, nullptr, nullptr, p_hidh);
    // 8. mlp2 + residual -> out (fp32)
    gemm_mma<0,EMB,HID><<<dim3(EMB/128, NTOK/256), 512, GEMM_SMEM>>>(
        p_hidh, p_w2h, mlp_b2, p_x1, out, nullptr);
}

// round 17
// speedup vs baseline: 1.3213x; 1.0006x over previous
#include <cuda_runtime.h>
#include <cuda_fp16.h>
#include <math.h>
#include <stdint.h>

// Problem constants
#define BQ 8
#define TQ 4096
#define NTOK (BQ*TQ)          // 32768 tokens
#define EMB 512
#define HEADS 8
#define ES 64
#define MF 32                 // random features
#define HID (4*EMB)           // 2048
#define LN_EPS 1e-5f

__device__ __forceinline__ uint32_t smem_to_u32(const void* smem_ptr) {
    uint32_t addr;
    asm("{ .reg .u64 tmp; cvta.to.shared.u64 tmp, %1; cvt.u32.u64 %0, tmp; }"
        : "=r"(addr) : "l"(smem_ptr));
    return addr;
}

__device__ __forceinline__ void cp_async16(uint32_t saddr, const void* gaddr) {
    asm volatile("cp.async.cg.shared.global [%0], [%1], 16;" :: "r"(saddr), "l"(gaddr));
}
#define CP_COMMIT() asm volatile("cp.async.commit_group;" ::: "memory")
#define CP_WAIT0()  asm volatile("cp.async.wait_group 0;" ::: "memory")
#define CP_WAIT1()  asm volatile("cp.async.wait_group 1;" ::: "memory")

__device__ __forceinline__ void ldsm_x4(uint32_t& r0, uint32_t& r1, uint32_t& r2, uint32_t& r3,
                                        uint32_t addr) {
    asm volatile("ldmatrix.sync.aligned.m8n8.x4.shared.b16 {%0,%1,%2,%3}, [%4];"
        : "=r"(r0), "=r"(r1), "=r"(r2), "=r"(r3) : "r"(addr));
}

__device__ __forceinline__ void mma_f16(float* c, const uint32_t* a, const uint32_t* b) {
    asm volatile(
        "mma.sync.aligned.m16n8k16.row.col.f32.f16.f16.f32 "
        "{%0,%1,%2,%3}, {%4,%5,%6,%7}, {%8,%9}, {%0,%1,%2,%3};"
        : "+f"(c[0]), "+f"(c[1]), "+f"(c[2]), "+f"(c[3])
        : "r"(a[0]), "r"(a[1]), "r"(a[2]), "r"(a[3]), "r"(b[0]), "r"(b[1]));
}

// -------- scratch (device globals; no runtime allocation) --------
__device__ __align__(16) __half g_vh[(size_t)NTOK*HEADS*ES];   // v fp16
__device__ float g_qp[(size_t)NTOK*HEADS*MF];
__device__ float g_kp[(size_t)NTOK*HEADS*MF];
__device__ float g_kptv_part[8*64*ES*MF];
__device__ float g_ksum_part[8*64*MF];
__device__ float g_x1[(size_t)NTOK*EMB];
__device__ __align__(16) __half g_h2h[(size_t)NTOK*EMB];
__device__ __align__(16) __half g_yh[(size_t)NTOK*EMB];
__device__ __align__(16) __half g_hidh[(size_t)NTOK*HID];
__device__ __align__(16) __half g_pwh[EMB*EMB];
__device__ __align__(16) __half g_w1h[HID*EMB];
__device__ __align__(16) __half g_w2h[EMB*HID];
__device__ __align__(16) __half g_kwh[192*64];   // kqv_w fp16

// ---------------- fused weight fp16 conversion (all 4 weights) ----------------
#define CVT_N4 (65536 + 262144 + 262144 + 3072)
__global__ void cvt_all_kernel(const float* __restrict__ pw, const float* __restrict__ w1,
                               const float* __restrict__ w2, const float* __restrict__ kw,
                               __half* __restrict__ pwh, __half* __restrict__ w1h,
                               __half* __restrict__ w2h, __half* __restrict__ kwh) {
    int i = blockIdx.x * 256 + threadIdx.x;
    if (i >= CVT_N4) return;
    const float* src;
    __half* dst;
    int j;
    if (i < 65536)       { src = pw; dst = pwh; j = i; }
    else if (i < 327680) { src = w1; dst = w1h; j = i - 65536; }
    else if (i < 589824) { src = w2; dst = w2h; j = i - 327680; }
    else                 { src = kw; dst = kwh; j = i - 589824; }
    float4 v = ((const float4*)src)[j];
    __half h[4];
    h[0] = __float2half(v.x); h[1] = __float2half(v.y);
    h[2] = __float2half(v.z); h[3] = __float2half(v.w);
    *(uint2*)(dst + (size_t)j*4) = *(uint2*)h;
}

// ---------------- LayerNorm (LN2): warp per token, fp16 out ----------------
__global__ void ln2_kernel(const float* __restrict__ x, const float* __restrict__ g,
                           const float* __restrict__ b, __half* __restrict__ ohi) {
    int tok  = blockIdx.x * 8 + (threadIdx.x >> 5);
    int lane = threadIdx.x & 31;
    const float4* xr = (const float4*)(x + (size_t)tok * EMB);
    float4 v[4];
    float s = 0.f, sq = 0.f;
    #pragma unroll
    for (int i = 0; i < 4; i++) {
        v[i] = xr[lane + 32*i];
        s  += v[i].x + v[i].y + v[i].z + v[i].w;
        sq += v[i].x*v[i].x + v[i].y*v[i].y + v[i].z*v[i].z + v[i].w*v[i].w;
    }
    #pragma unroll
    for (int o = 16; o; o >>= 1) {
        s  += __shfl_xor_sync(0xffffffffu, s,  o);
        sq += __shfl_xor_sync(0xffffffffu, sq, o);
    }
    float mean = s * (1.0f/EMB);
    float var  = sq * (1.0f/EMB) - mean*mean;
    float rstd = rsqrtf(var + LN_EPS);
    const float4* g4 = (const float4*)g;
    const float4* b4 = (const float4*)b;
    #pragma unroll
    for (int i = 0; i < 4; i++) {
        float4 gg = g4[lane + 32*i], bb = b4[lane + 32*i];
        size_t idx = (size_t)tok * EMB + (size_t)(lane + 32*i) * 4;
        __half h[4];
        h[0] = __float2half((v[i].x - mean) * rstd * gg.x + bb.x);
        h[1] = __float2half((v[i].y - mean) * rstd * gg.y + bb.y);
        h[2] = __float2half((v[i].z - mean) * rstd * gg.z + bb.z);
        h[3] = __float2half((v[i].w - mean) * rstd * gg.w + bb.w);
        *(uint2*)(ohi + idx) = *(uint2*)h;
    }
}

// ======== fused LN1 + tensor-core kqv + prm_exp (16 tok/block, 4 passes) ========
// smem floats: sh_h 8192 | wr_t 2048 | sbias 192 | skqv4 6400 | sxd4 64  = 16896
// then bytes:  W16 @67584 (24576) | AHI @92160 (4096) | ALO @96256 (4096) => 100352 B
#define SKQ_STRIDE 200
#define W16_OFF 67584
#define AHI_OFF 92160
#define ALO_OFF 96256
#define K1_SMEM_BYTES 100352
__global__ void kqv_prm_kernel(const float* __restrict__ xg, const float* __restrict__ ln1_g,
                               const float* __restrict__ ln1_b,
                               const __half* __restrict__ kwh,
                               const float* __restrict__ kqv_b, const float* __restrict__ wrf,
                               __half* __restrict__ gvh, float* __restrict__ gkp,
                               float* __restrict__ gqp) {
    extern __shared__ float sm[];
    char* smc = (char*)sm;
    uint32_t sb = smem_to_u32(sm);
    float* sh_h  = sm;                    // [16 tok][512]
    float* wr_t  = sm + 8192;             // [64 e][32 m]
    float* sbias = wr_t + 2048;           // [192]
    float* skqv4 = sbias + 192;           // [4 hd][8 tok][SKQ_STRIDE]
    float* sxd4  = skqv4 + 6400;          // [4 hd][16]
    int tid = threadIdx.x, lane = tid & 31, wid = tid >> 5;
    size_t t0 = (size_t)blockIdx.x * 16;

    // ---- kqv_w fp16 -> smem via cp.async (192 rows x 128B, swizzled) ----
    #pragma unroll
    for (int i = 0; i < 6; i++) {
        int idx = tid + 256*i;
        int row = idx >> 3, c = idx & 7;
        cp_async16(sb + W16_OFF + (uint32_t)row*128 + (uint32_t)((c ^ (row & 7)) << 4),
                   kwh + row*64 + c*8);
    }
    CP_COMMIT();

    // ---- fused LN1: warp handles 2 tokens ----
    #pragma unroll
    for (int tt = 0; tt < 2; tt++) {
        int tok = (tid >> 5) * 2 + tt;
        const float4* xr = (const float4*)(xg + (t0 + tok) * EMB);
        float4 v[4];
        float s = 0.f, sq = 0.f;
        #pragma unroll
        for (int i = 0; i < 4; i++) {
            v[i] = xr[lane + 32*i];
            s  += v[i].x + v[i].y + v[i].z + v[i].w;
            sq += v[i].x*v[i].x + v[i].y*v[i].y + v[i].z*v[i].z + v[i].w*v[i].w;
        }
        #pragma unroll
        for (int o = 16; o; o >>= 1) {
            s  += __shfl_xor_sync(0xffffffffu, s,  o);
            sq += __shfl_xor_sync(0xffffffffu, sq, o);
        }
        float mean = s * (1.0f/EMB);
        float var  = sq * (1.0f/EMB) - mean*mean;
        float rstd = rsqrtf(var + LN_EPS);
        const float4* g4 = (const float4*)ln1_g;
        const float4* b4 = (const float4*)ln1_b;
        float4* hrow = (float4*)(sh_h + tok * 512);
        #pragma unroll
        for (int i = 0; i < 4; i++) {
            float4 gg = g4[lane + 32*i], bb = b4[lane + 32*i];
            float4 o;
            o.x = (v[i].x - mean) * rstd * gg.x + bb.x;
            o.y = (v[i].y - mean) * rstd * gg.y + bb.y;
            o.z = (v[i].z - mean) * rstd * gg.z + bb.z;
            o.w = (v[i].w - mean) * rstd * gg.w + bb.w;
            hrow[lane + 32*i] = o;
        }
    }
    // ---- wr_t [64 e][32 m] + bias ----
    #pragma unroll
    for (int i = 0; i < 2; i++) {
        int j = tid + 256*i;
        int m = j >> 4, e0 = (j & 15) << 2;
        float4 w4 = ((const float4*)wrf)[j];
        wr_t[(e0+0)*32 + m] = w4.x;
        wr_t[(e0+1)*32 + m] = w4.y;
        wr_t[(e0+2)*32 + m] = w4.z;
        wr_t[(e0+3)*32 + m] = w4.w;
    }
    if (tid < 192) sbias[tid] = kqv_b[tid];
    CP_WAIT0();
    __syncthreads();

    int wm = wid & 1, wn = wid >> 1;
    int m0 = wm * 16, n0 = wn * 48;
    int arow = m0 + (lane & 15), acb = lane >> 4;
    int brow_l = (lane & 7) + ((lane >> 4) << 3), bcb = (lane >> 3) & 1;

    for (int p = 0; p < 4; p++) {
        int hbase = (p & 1) * 4;          // heads hbase..hbase+3
        int tbase = (p >> 1) * 8;         // tokens tbase..tbase+7
        // ---- convert A (32 rows = 4hd x 8tok, 64 e) to hi/lo fp16, swizzled ----
        {
            int r = tid >> 3, c = tid & 7;
            int hd4 = r >> 3, tokl = r & 7;
            const float* hp = sh_h + (tbase + tokl)*512 + (hbase + hd4)*64 + c*8;
            float4 f0 = *(const float4*)hp;
            float4 f1 = *(const float4*)(hp + 4);
            float vv[8] = {f0.x,f0.y,f0.z,f0.w,f1.x,f1.y,f1.z,f1.w};
            __half hi[8], lo[8];
            #pragma unroll
            for (int q = 0; q < 8; q++) {
                hi[q] = __float2half(vv[q]);
                lo[q] = __float2half(vv[q] - __half2float(hi[q]));
            }
            uint32_t off = (uint32_t)r*128 + (uint32_t)((c ^ (r & 7)) << 4);
            *(uint4*)(smc + AHI_OFF + off) = *(uint4*)hi;
            *(uint4*)(smc + ALO_OFF + off) = *(uint4*)lo;
        }
        __syncthreads();

        // ---- MMA: 2-term (hi+lo) x W16 ----
        float acc[6][4];
        #pragma unroll
        for (int nf = 0; nf < 6; nf++)
            #pragma unroll
            for (int q = 0; q < 4; q++) acc[nf][q] = 0.f;
        #pragma unroll
        for (int ks = 0; ks < 4; ks++) {
            uint32_t aoff = (uint32_t)arow*128 +
                            (uint32_t)((((ks*2 + acb)) ^ (arow & 7)) << 4);
            uint32_t ah[4], al[4];
            ldsm_x4(ah[0], ah[1], ah[2], ah[3], sb + AHI_OFF + aoff);
            ldsm_x4(al[0], al[1], al[2], al[3], sb + ALO_OFF + aoff);
            #pragma unroll
            for (int ng = 0; ng < 3; ng++) {
                int br = n0 + ng*16 + brow_l;
                uint32_t boff = (uint32_t)br*128 +
                                (uint32_t)(((ks*2 + bcb) ^ (br & 7)) << 4);
                uint32_t b2[2][2];
                ldsm_x4(b2[0][0], b2[0][1], b2[1][0], b2[1][1], sb + W16_OFF + boff);
                #pragma unroll
                for (int j = 0; j < 2; j++) {
                    mma_f16(acc[2*ng + j], ah, b2[j]);
                    mma_f16(acc[2*ng + j], al, b2[j]);
                }
            }
        }
        // ---- epilogue: acc + bias -> skqv4 ----
        {
            int rb = m0 + (lane >> 2);
            int cb = n0 + (lane & 3) * 2;
            #pragma unroll
            for (int half = 0; half < 2; half++) {
                int r = rb + half*8;
                int hd4 = r >> 3, tokl = r & 7;
                float* row = skqv4 + hd4*8*SKQ_STRIDE + tokl*SKQ_STRIDE;
                #pragma unroll
                for (int nf = 0; nf < 6; nf++) {
                    int col = cb + nf*8;
                    row[col]   = acc[nf][half*2+0] + sbias[col];
                    row[col+1] = acc[nf][half*2+1] + sbias[col+1];
                }
            }
        }
        __syncthreads();

        // ---- v write: 1024 half2 pairs ----
        #pragma unroll
        for (int i = 0; i < 4; i++) {
            int idx = tid + 256*i;
            int hd4 = idx >> 8, tokl = (idx >> 5) & 7, e2 = idx & 31;
            const float* src = &skqv4[hd4*8*SKQ_STRIDE + tokl*SKQ_STRIDE + 128 + e2*2];
            __half2 hv = __floats2half2_rn(src[0], src[1]);
            *(__half2*)&gvh[(((t0 + tbase + tokl) * HEADS) + hbase + hd4) * ES + e2*2] = hv;
        }
        // ---- xd ----
        if (tid < 64) {
            int hd4 = tid >> 4, r = tid & 15, tokl = r >> 1, which = r & 1;
            const float* z = skqv4 + hd4*8*SKQ_STRIDE + tokl*SKQ_STRIDE + which*64;
            float s = 0.f;
            #pragma unroll 8
            for (int e = 0; e < 64; e++) { float zz = z[e]; s += zz*zz; }
            sxd4[hd4*16 + r] = 0.5f * s;
        }
        __syncthreads();

        // ---- wtx + exp ----
        #pragma unroll
        for (int i = 0; i < 2; i++) {
            int sidx = tid + 256*i;
            int mg = sidx & 7, which = (sidx >> 3) & 1, tokl = (sidx >> 4) & 7, hd4 = sidx >> 7;
            int mq = mg * 4;
            const float* z = skqv4 + hd4*8*SKQ_STRIDE + tokl*SKQ_STRIDE + which*64;
            float a0 = 0.f, a1 = 0.f, a2 = 0.f, a3 = 0.f;
            #pragma unroll 8
            for (int e = 0; e < 64; e++) {
                float zv = z[e];
                float4 w4 = *(const float4*)&wr_t[e*32 + mq];
                a0 += zv*w4.x; a1 += zv*w4.y; a2 += zv*w4.z; a3 += zv*w4.w;
            }
            float xdv = sxd4[hd4*16 + tokl*2 + which];
            float4 o;
            o.x = expf(a0 - xdv) * 0.17677669529663689f;
            o.y = expf(a1 - xdv) * 0.17677669529663689f;
            o.z = expf(a2 - xdv) * 0.17677669529663689f;
            o.w = expf(a3 - xdv) * 0.17677669529663689f;
            float* dst = which ? gqp : gkp;
            *(float4*)&dst[(((t0 + tbase + tokl) * HEADS) + hbase + hd4) * MF + mq] = o;
        }
        __syncthreads();
    }
}

// ------- kptv / ksum reduction over T: 8 chunks x 512 steps, 32-step stages -------
__global__ void kpt_kernel(const __half* __restrict__ gvh, const float* __restrict__ gkp,
                           float* __restrict__ part_kptv, float* __restrict__ part_ksum) {
    int chunk = blockIdx.x;            // 0..7
    int bh = blockIdx.y;
    int b = bh >> 3, h = bh & 7;
    __shared__ __half sv[2][32][64];
    __shared__ float skp[2][32][32];
    uint32_t sv_b = smem_to_u32(sv), skp_b = smem_to_u32(skp);
    int tid = threadIdx.x, lane = tid & 31, wid = tid >> 5;
    float acc[8] = {0,0,0,0,0,0,0,0};
    float ks = 0.f;
    int t0 = chunk * 512;

    auto load_stage = [&](int buf, int s0) {
        int s = tid >> 3, c = tid & 7;
        size_t gtok = (size_t)b*TQ + s0 + s;
        cp_async16(sv_b  + buf*4096 + s*128 + c*16, gvh + (gtok * HEADS + h) * ES + c*8);
        cp_async16(skp_b + buf*4096 + s*128 + c*16, gkp + (gtok * HEADS + h) * MF + c*4);
    };

    load_stage(0, t0);
    CP_COMMIT();
    for (int st = 0; st < 16; st++) {
        CP_WAIT0();
        __syncthreads();
        if (st + 1 < 16) {
            load_stage((st + 1) & 1, t0 + (st + 1) * 32);
            CP_COMMIT();
        }
        int buf = st & 1;
        #pragma unroll
        for (int s = 0; s < 32; s++) {
            float kv = skp[buf][s][lane];
            uint4 vr = *(const uint4*)&sv[buf][s][wid*8];
            __half2* hp = (__half2*)&vr;
            float2 c0 = __half22float2(hp[0]);
            float2 c1 = __half22float2(hp[1]);
            float2 c2 = __half22float2(hp[2]);
            float2 c3 = __half22float2(hp[3]);
            acc[0] += c0.x*kv; acc[1] += c0.y*kv; acc[2] += c1.x*kv; acc[3] += c1.y*kv;
            acc[4] += c2.x*kv; acc[5] += c2.y*kv; acc[6] += c3.x*kv; acc[7] += c3.y*kv;
            if (wid == 0) ks += kv;
        }
    }
    size_t base = ((size_t)(chunk*64 + bh)) * (ES*MF);
    #pragma unroll
    for (int j = 0; j < 8; j++)
        part_kptv[base + (wid*8 + j)*MF + lane] = acc[j];
    if (wid == 0) part_ksum[(chunk*64 + bh)*MF + lane] = ks;
}

// ------- y = (qp . kptv) / D -> fp16; inline 8-partial reduce; no shfl -------
__global__ void y_kernel(const float* __restrict__ gqp, const float* __restrict__ pk,
                         const float* __restrict__ ps, __half* __restrict__ yh) {
    int bh = blockIdx.y, b = bh >> 3, h = bh & 7;
    __shared__ float sk[64*33];
    __shared__ float sks[32];
    __shared__ float sqp[256*33];
    __shared__ float sdinv[256];
    int tid = threadIdx.x, lane = tid & 31, wid = tid >> 5;
    int tbase = blockIdx.x * 256;
    // inline reduce of kptv partials (same c-ascending order as old reduce_kernel)
    #pragma unroll
    for (int i = 0; i < 8; i++) {
        int idx = tid + 256*i;
        float s = 0.f;
        #pragma unroll
        for (int c = 0; c < 8; c++) s += pk[((size_t)(c*64 + bh)) * 2048 + idx];
        sk[(idx >> 5)*33 + (idx & 31)] = s;
    }
    if (tid < 32) {
        float s = 0.f;
        #pragma unroll
        for (int c = 0; c < 8; c++) s += ps[(c*64 + bh)*MF + tid];
        sks[tid] = s;
    }
    #pragma unroll
    for (int i = 0; i < 8; i++) {
        int idx = tid + 256*i;
        int t = idx >> 3, mq = (idx & 7) * 4;
        float4 q4 = *(const float4*)&gqp[(((size_t)b*TQ + tbase + t) * HEADS + h) * MF + mq];
        float* row = sqp + t*33 + mq;
        row[0] = q4.x; row[1] = q4.y; row[2] = q4.z; row[3] = q4.w;
    }
    __syncthreads();
    {
        float d = 0.f;
        const float* qrow = sqp + tid*33;
        #pragma unroll 8
        for (int m = 0; m < 32; m++) d += qrow[m] * sks[m];
        sdinv[tid] = 1.0f / d;
    }
    __syncthreads();
    for (int it = 0; it < 32; it++) {
        int tl = wid * 32 + it;
        const float* qrow = sqp + tl*33;
        float a0 = 0.f, a1 = 0.f;
        #pragma unroll 8
        for (int m = 0; m < 32; m++) {
            float qm = qrow[m];
            a0 += qm * sk[lane*33 + m];
            a1 += qm * sk[(lane+32)*33 + m];
        }
        float inv = sdinv[tl];
        size_t off = ((size_t)b*TQ + tbase + tl) * EMB + h * ES;
        yh[off + lane]      = __float2half(a0 * inv);
        yh[off + lane + 32] = __float2half(a1 * inv);
    }
}

// ===== mma.sync fp16 GEMM: 256x128 CTA, 512 thr, K-super-chunk 128, compile-time N/K =====
#define A_PL 32768
#define SUB_BYTES 49152
#define STAGE_BYTES (2*SUB_BYTES)          // 98304
#define GEMM_SMEM (2*STAGE_BYTES)          // 196608

#define SWZ_ADDR(base, row, chunk) \
    ((base) + (uint32_t)(row)*128u + (uint32_t)(((chunk) ^ ((row)&7)) << 4))

template<int EPI, int NN, int KK>
__global__ __launch_bounds__(512, 1)
void gemm_mma(const __half* __restrict__ Ah, const __half* __restrict__ Bh,
              const float* __restrict__ bias, const float* __restrict__ res,
              float* __restrict__ Cf, __half* __restrict__ Chi) {
    extern __shared__ char gsm[];
    uint32_t sb = smem_to_u32(gsm);
    int tid = threadIdx.x, lane = tid & 31, wid = tid >> 5;
    int rowBase = blockIdx.y * 256, colBase = blockIdx.x * 128;

    int wm = wid & 3, wn = wid >> 2;
    int m0 = wm * 64, n0 = wn * 32;

    float acc[4][4][4];
    #pragma unroll
    for (int i = 0; i < 4; i++)
        #pragma unroll
        for (int j = 0; j < 4; j++)
            #pragma unroll
            for (int q = 0; q < 4; q++) acc[i][j][q] = 0.f;

    int arow_l = (lane & 15);
    int acb    = (lane >> 4);
    int brow_l = (lane & 7) + ((lane >> 4) << 3);
    int bcb    = (lane >> 3) & 1;

    auto load_super = [&](int stg, int k0) {
        uint32_t sbase = sb + stg * STAGE_BYTES;
        #pragma unroll
        for (int j = 0; j < 8; j++) {
            int idx = tid + 512*j;
            int row = idx >> 4, c = idx & 15;
            int sub = c >> 3, c128 = c & 7;
            cp_async16(SWZ_ADDR(sbase + sub*SUB_BYTES, row, c128),
                       Ah + (size_t)(rowBase + row) * KK + k0 + sub*64 + c128*8);
        }
        #pragma unroll
        for (int j = 0; j < 4; j++) {
            int idx = tid + 512*j;
            int row = idx >> 4, c = idx & 15;
            int sub = c >> 3, c128 = c & 7;
            cp_async16(SWZ_ADDR(sbase + sub*SUB_BYTES + A_PL, row, c128),
                       Bh + (size_t)(colBase + row) * KK + k0 + sub*64 + c128*8);
        }
    };

    constexpr int NC = KK >> 7;
    load_super(0, 0);
    CP_COMMIT();

    #pragma unroll 2
    for (int c = 0; c < NC; c++) {
        CP_WAIT0();
        __syncthreads();
        if (c + 1 < NC) {
            load_super((c + 1) & 1, (c + 1) << 7);
            CP_COMMIT();
        }

        uint32_t pS = sb + (c & 1) * STAGE_BYTES;
        #pragma unroll
        for (int ks = 0; ks < 8; ks++) {
            uint32_t pA = pS + (ks >> 2) * SUB_BYTES;
            int kss = ks & 3;
            uint32_t ah[4][4];
            #pragma unroll
            for (int mt = 0; mt < 4; mt++) {
                int ar = m0 + mt * 16 + arow_l;
                ldsm_x4(ah[mt][0], ah[mt][1], ah[mt][2], ah[mt][3],
                        SWZ_ADDR(pA, ar, kss * 2 + acb));
            }
            uint32_t bh2[4][2];
            #pragma unroll
            for (int ng = 0; ng < 2; ng++) {
                int br = n0 + ng * 16 + brow_l;
                ldsm_x4(bh2[2*ng][0], bh2[2*ng][1], bh2[2*ng+1][0], bh2[2*ng+1][1],
                        SWZ_ADDR(pA + A_PL, br, kss * 2 + bcb));
            }
            #pragma unroll
            for (int mt = 0; mt < 4; mt++)
                #pragma unroll
                for (int nt = 0; nt < 4; nt++)
                    mma_f16(acc[mt][nt], ah[mt], bh2[nt]);
        }
    }

    int rbase = rowBase + m0 + (lane >> 2);
    int cbase = colBase + n0 + (lane & 3) * 2;
    #pragma unroll
    for (int mt = 0; mt < 4; mt++) {
        #pragma unroll
        for (int half = 0; half < 2; half++) {
            int row = rbase + mt * 16 + half * 8;
            if (EPI == 0) {
                float* crow = Cf + (size_t)row * NN;
                const float* rrow = res + (size_t)row * NN;
                #pragma unroll
                for (int nt = 0; nt < 4; nt++) {
                    int col = cbase + nt * 8;
                    float2 o;
                    o.x = acc[mt][nt][half*2+0] + bias[col]   + rrow[col];
                    o.y = acc[mt][nt][half*2+1] + bias[col+1] + rrow[col+1];
                    *(float2*)(crow + col) = o;
                }
            } else {
                __half* hrow = Chi + (size_t)row * NN;
                #pragma unroll
                for (int nt = 0; nt < 4; nt++) {
                    int col = cbase + nt * 8;
                    float v0 = acc[mt][nt][half*2+0] + bias[col];
                    float v1 = acc[mt][nt][half*2+1] + bias[col+1];
                    v0 = 0.5f * v0 * (1.0f + erff(v0 * 0.70710678118654752f));
                    v1 = 0.5f * v1 * (1.0f + erff(v1 * 0.70710678118654752f));
                    __half hh[2] = {__float2half(v0), __float2half(v1)};
                    *(uint32_t*)(hrow + col) = *(uint32_t*)hh;
                }
            }
        }
    }
}

// ---------------- launch ----------------
extern "C" void kernel_launch(void* const* d_in, const int* in_sizes, int n_in,
                              void* d_out, int out_size) {
    const float* x      = (const float*)d_in[0];
    const float* wrf    = (const float*)d_in[1];
    const float* kqv_w  = (const float*)d_in[2];
    const float* kqv_b  = (const float*)d_in[3];
    const float* proj_w = (const float*)d_in[4];
    const float* proj_b = (const float*)d_in[5];
    const float* ln1_g  = (const float*)d_in[6];
    const float* ln1_b  = (const float*)d_in[7];
    const float* ln2_g  = (const float*)d_in[8];
    const float* ln2_b  = (const float*)d_in[9];
    const float* mlp_w1 = (const float*)d_in[10];
    const float* mlp_b1 = (const float*)d_in[11];
    const float* mlp_w2 = (const float*)d_in[12];
    const float* mlp_b2 = (const float*)d_in[13];
    float* out = (float*)d_out;

    float *p_qp, *p_kp, *p_pk, *p_ps, *p_x1;
    __half *p_vh, *p_h2h, *p_yh, *p_hidh, *p_pwh, *p_w1h, *p_w2h, *p_kwh;
    cudaGetSymbolAddress((void**)&p_vh,   g_vh);
    cudaGetSymbolAddress((void**)&p_qp,   g_qp);
    cudaGetSymbolAddress((void**)&p_kp,   g_kp);
    cudaGetSymbolAddress((void**)&p_pk,   g_kptv_part);
    cudaGetSymbolAddress((void**)&p_ps,   g_ksum_part);
    cudaGetSymbolAddress((void**)&p_x1,   g_x1);
    cudaGetSymbolAddress((void**)&p_h2h,  g_h2h);
    cudaGetSymbolAddress((void**)&p_yh,   g_yh);
    cudaGetSymbolAddress((void**)&p_hidh, g_hidh);
    cudaGetSymbolAddress((void**)&p_pwh,  g_pwh);
    cudaGetSymbolAddress((void**)&p_w1h,  g_w1h);
    cudaGetSymbolAddress((void**)&p_w2h,  g_w2h);
    cudaGetSymbolAddress((void**)&p_kwh,  g_kwh);

    cudaFuncSetAttribute(kqv_prm_kernel, cudaFuncAttributeMaxDynamicSharedMemorySize,
                         K1_SMEM_BYTES);
    cudaFuncSetAttribute((const void*)gemm_mma<0,EMB,EMB>,
                         cudaFuncAttributeMaxDynamicSharedMemorySize, GEMM_SMEM);
    cudaFuncSetAttribute((const void*)gemm_mma<1,HID,EMB>,
                         cudaFuncAttributeMaxDynamicSharedMemorySize, GEMM_SMEM);
    cudaFuncSetAttribute((const void*)gemm_mma<0,EMB,HID>,
                         cudaFuncAttributeMaxDynamicSharedMemorySize, GEMM_SMEM);

    // 0. all weight fp16 rounds (one launch)
    cvt_all_kernel<<<(CVT_N4 + 255)/256, 256>>>(proj_w, mlp_w1, mlp_w2, kqv_w,
                                                p_pwh, p_w1h, p_w2h, p_kwh);
    // 1. fused LN1 + tensor kqv + prm_exp (16 tokens/block)
    kqv_prm_kernel<<<NTOK/16, 256, K1_SMEM_BYTES>>>(x, ln1_g, ln1_b, p_kwh, kqv_b, wrf,
                                                    p_vh, p_kp, p_qp);
    // 2. kptv/ksum partials over T (8 chunks x 512 steps)
    kpt_kernel<<<dim3(8, 64), 256>>>(p_vh, p_kp, p_pk, p_ps);
    // 3. y (inline partial reduce + qp smem + 1/D precompute)
    y_kernel<<<dim3(TQ/256, 64), 256>>>(p_qp, p_pk, p_ps, p_yh);
    // 4. attn proj + residual -> x1 (fp32)
    gemm_mma<0,EMB,EMB><<<dim3(EMB/128, NTOK/256), 512, GEMM_SMEM>>>(
        p_yh, p_pwh, proj_b, x, p_x1, nullptr);
    // 5. LN2 -> fp16
    ln2_kernel<<<NTOK/8, 256>>>(p_x1, ln2_g, ln2_b, p_h2h);
    // 6. mlp1 + gelu -> hid (fp16)
    gemm_mma<1,HID,EMB><<<dim3(HID/128, NTOK/256), 512, GEMM_SMEM>>>(
        p_h2h, p_w1h, mlp_b1, nullptr, nullptr, p_hidh);
    // 7. mlp2 + residual -> out (fp32)
    gemm_mma<0,EMB,HID><<<dim3(EMB/128, NTOK/256), 512, GEMM_SMEM>>>(
        p_hidh, p_w2h, mlp_b2, p_x1, out, nullptr);
}